// round 9
// baseline (speedup 1.0000x reference)
#include <cuda_runtime.h>
#include <cuda_bf16.h>
#include <cstdint>
#include <math.h>

#define NN 100000
#define DD 128
#define EE 250000
#define TT 3
#define ND (NN*DD)
#define ND4 (ND/4)

// -------- scratch --------
__device__ float g_feat[ND];
__device__ float g_t1[ND];
__device__ float g_t2[ND];
__device__ float g_key[3*ND];
__device__ float g_ska[3*ND];
__device__ float g_v[3*ND];
__device__ int   g_cnt[TT*NN];
__device__ float g_inv[TT*NN];
__device__ float g_gscale[NN];
__device__ float g_colsum[DD];
__device__ float g_colsq[DD];
__device__ float g_wqa[DD*DD];
__device__ float g_wka[DD*DD];

// -------- small kernels --------

__global__ void gather_feat_k(const float* __restrict__ n_emb, const int* __restrict__ ind,
                              float* __restrict__ feat) {
    int idx = blockIdx.x * blockDim.x + threadIdx.x;
    if (idx >= ND4) return;
    int n = idx >> 5;
    reinterpret_cast<float4*>(feat)[idx] =
        reinterpret_cast<const float4*>(n_emb)[(long)ind[n] * 32 + (idx & 31)];
}

__global__ void count_k(const int* __restrict__ dst, int* __restrict__ cnt) {
    int e = blockIdx.x * blockDim.x + threadIdx.x;
    if (e >= TT*EE) return;
    int t = e / EE;
    atomicAdd(&cnt[t * NN + dst[e]], 1);
}

__global__ void prep_k(const int* __restrict__ cnt, float* __restrict__ inv,
                       float* __restrict__ gscale) {
    int n = blockIdx.x * blockDim.x + threadIdx.x;
    if (n >= NN) return;
    int c0 = cnt[n], c1 = cnt[NN + n], c2 = cnt[2*NN + n];
    inv[n]        = 1.f / (float)max(c0, 1);
    inv[NN + n]   = 1.f / (float)max(c1, 1);
    inv[2*NN + n] = 1.f / (float)max(c2, 1);
    gscale[n] = (float)((c0 > 0) + (c1 > 0) + (c2 > 0));
}

__global__ void init_acc_k(const float* __restrict__ feat, const float* __restrict__ gscale,
                           float* __restrict__ acc) {
    int idx = blockIdx.x * blockDim.x + threadIdx.x;
    if (idx >= ND4) return;
    float s = gscale[idx >> 5];
    float4 f = reinterpret_cast<const float4*>(feat)[idx];
    reinterpret_cast<float4*>(acc)[idx] = make_float4(f.x*s, f.y*s, f.z*s, f.w*s);
}

__device__ __forceinline__ void red_add_v4(float* p, float4 v) {
    asm volatile("red.global.add.v4.f32 [%0], {%1,%2,%3,%4};"
                 :: "l"(p), "f"(v.x), "f"(v.y), "f"(v.z), "f"(v.w) : "memory");
}

__global__ void gcn_edge_k(const float* __restrict__ feat, const float* __restrict__ emb,
                           const int* __restrict__ src, const int* __restrict__ dst,
                           const float* __restrict__ inv, float* __restrict__ acc) {
    int gw = (blockIdx.x * blockDim.x + threadIdx.x) >> 5;
    int lane = threadIdx.x & 31;
    if (gw >= TT*EE) return;
    int t = gw / EE;
    int s = src[gw], d = dst[gw];
    float w = inv[t * NN + d];
    float4 f = reinterpret_cast<const float4*>(feat + (long)s * DD)[lane];
    float4 e = reinterpret_cast<const float4*>(emb + t * DD)[lane];
    float4 v = make_float4(-f.x*e.x*w, -f.y*e.y*w, -f.z*e.z*w, -f.w*e.w*w);
    red_add_v4(acc + (long)d * DD + lane*4, v);
}

__global__ void attn_edge_k(const float* __restrict__ feat, const float* __restrict__ emb,
                            const int* __restrict__ src, const int* __restrict__ dst,
                            const float* __restrict__ inv, float* __restrict__ key) {
    int gw = (blockIdx.x * blockDim.x + threadIdx.x) >> 5;
    int lane = threadIdx.x & 31;
    if (gw >= TT*EE) return;
    int t = gw / EE;
    int s = src[gw], d = dst[gw];
    float w = inv[t * NN + d];
    float4 f = reinterpret_cast<const float4*>(feat + (long)s * DD)[lane];
    float4 e = reinterpret_cast<const float4*>(emb + t * DD)[lane];
    float4 v = make_float4(f.x*e.x*w, f.y*e.y*w, f.z*e.z*w, f.w*e.w*w);
    red_add_v4(key + (long)t * ND + (long)d * DD + lane*4, v);
}

// -------- GEMM infrastructure --------

#define GSTAGE_A (128*36)
#define GSTAGE_B (32*136)
#define GSTAGE   (GSTAGE_A + GSTAGE_B)
#define GEMM_SMEM_BYTES (2*GSTAGE*4)

#define DSTAGE (GSTAGE_A + 2*GSTAGE_B)
#define DUAL_SMEM_BYTES (2*DSTAGE*4)

__device__ __forceinline__ void cp_async16(uint32_t saddr, const void* gptr, bool pred) {
    int sz = pred ? 16 : 0;
    asm volatile("cp.async.ca.shared.global [%0], [%1], 16, %2;"
                 :: "r"(saddr), "l"(gptr), "r"(sz));
}

__device__ __forceinline__ void mma_tf32(float* c, const uint32_t* a, const uint32_t* b) {
    asm volatile("mma.sync.aligned.m16n8k8.row.col.f32.tf32.tf32.f32 "
                 "{%0,%1,%2,%3}, {%4,%5,%6,%7}, {%8,%9}, {%0,%1,%2,%3};"
                 : "+f"(c[0]), "+f"(c[1]), "+f"(c[2]), "+f"(c[3])
                 : "r"(a[0]), "r"(a[1]), "r"(a[2]), "r"(a[3]), "r"(b[0]), "r"(b[1]));
}

// C[M,128] = A[M,128] @ B[128,128]
// EPI 0: store. EPI 1: C += acc + bias. EPI 3: softmax-combine acc(=qa) with ska/vv, store.
template<int EPI>
__global__ __launch_bounds__(256) void gemm_tc(const float* __restrict__ A,
                                               const float* __restrict__ B,
                                               float* __restrict__ C,
                                               const float* __restrict__ bias, int M,
                                               const float* __restrict__ ska,
                                               const float* __restrict__ vv) {
    extern __shared__ float smf[];
    int tid = threadIdx.x;
    int lane = tid & 31, wid = tid >> 5;
    int wm = wid & 3, wn = wid >> 2;
    int g = lane >> 2, q = lane & 3;
    long m0 = (long)blockIdx.x * 128;

    float acc[2][8][4];
    #pragma unroll
    for (int mt = 0; mt < 2; mt++)
        #pragma unroll
        for (int nt = 0; nt < 8; nt++)
            #pragma unroll
            for (int i = 0; i < 4; i++) acc[mt][nt][i] = 0.f;

    int ar[4], ac_[4], br[4], bc[4];
    #pragma unroll
    for (int i = 0; i < 4; i++) {
        int idx = (tid + 256 * i) * 4;
        ar[i] = idx >> 5; ac_[i] = idx & 31;
        br[i] = idx >> 7; bc[i] = idx & 127;
    }

    auto prefetch = [&](int kc, int s) {
        float* As = smf + s * GSTAGE;
        float* Bs = As + GSTAGE_A;
        #pragma unroll
        for (int i = 0; i < 4; i++) {
            long row = m0 + ar[i];
            uint32_t sa = (uint32_t)__cvta_generic_to_shared(&As[ar[i]*36 + ac_[i]]);
            cp_async16(sa, A + row * 128 + kc * 32 + ac_[i], row < M);
        }
        #pragma unroll
        for (int i = 0; i < 4; i++) {
            uint32_t sb = (uint32_t)__cvta_generic_to_shared(&Bs[br[i]*136 + bc[i]]);
            cp_async16(sb, B + (kc * 32 + br[i]) * 128 + bc[i], true);
        }
        asm volatile("cp.async.commit_group;");
    };

    prefetch(0, 0);

    for (int kc = 0; kc < 4; kc++) {
        if (kc < 3) {
            prefetch(kc + 1, (kc + 1) & 1);
            asm volatile("cp.async.wait_group 1;");
        } else {
            asm volatile("cp.async.wait_group 0;");
        }
        __syncthreads();

        const uint32_t* As = reinterpret_cast<const uint32_t*>(smf + (kc & 1) * GSTAGE);
        const uint32_t* Bs = As + GSTAGE_A;

        #pragma unroll
        for (int ks = 0; ks < 4; ks++) {
            int kc8 = ks * 8;
            uint32_t a[2][4], b[8][2];
            #pragma unroll
            for (int mt = 0; mt < 2; mt++) {
                int row = wm * 32 + mt * 16 + g;
                a[mt][0] = As[row*36 + kc8 + q];
                a[mt][1] = As[(row+8)*36 + kc8 + q];
                a[mt][2] = As[row*36 + kc8 + q + 4];
                a[mt][3] = As[(row+8)*36 + kc8 + q + 4];
            }
            #pragma unroll
            for (int nt = 0; nt < 8; nt++) {
                int col = wn * 64 + nt * 8 + g;
                b[nt][0] = Bs[(kc8 + q)*136 + col];
                b[nt][1] = Bs[(kc8 + q + 4)*136 + col];
            }
            #pragma unroll
            for (int mt = 0; mt < 2; mt++)
                #pragma unroll
                for (int nt = 0; nt < 8; nt++)
                    mma_tf32(acc[mt][nt], a[mt], b[nt]);
        }
        __syncthreads();
    }

    #pragma unroll
    for (int mt = 0; mt < 2; mt++) {
        #pragma unroll
        for (int h = 0; h < 2; h++) {
            long row = m0 + wm * 32 + mt * 16 + g + h * 8;
            if (row >= M) continue;
            #pragma unroll
            for (int nt = 0; nt < 8; nt++) {
                int col = wn * 64 + nt * 8 + q * 2;
                long base = row * 128 + col;
                float2* cp = reinterpret_cast<float2*>(&C[base]);
                float v0 = acc[mt][nt][h * 2], v1 = acc[mt][nt][h * 2 + 1];
                if (EPI == 0) {
                    *cp = make_float2(v0, v1);
                } else if (EPI == 1) {
                    float2 prev = *cp;
                    *cp = make_float2(prev.x + v0 + bias[col], prev.y + v1 + bias[col + 1]);
                } else { // EPI == 3: softmax combine (acc = qa)
                    float2 s0 = *reinterpret_cast<const float2*>(ska + base);
                    float2 s1 = *reinterpret_cast<const float2*>(ska + base + (long)ND);
                    float2 s2 = *reinterpret_cast<const float2*>(ska + base + 2L*ND);
                    float2 w0 = *reinterpret_cast<const float2*>(vv + base);
                    float2 w1 = *reinterpret_cast<const float2*>(vv + base + (long)ND);
                    float2 w2 = *reinterpret_cast<const float2*>(vv + base + 2L*ND);
                    float o0, o1;
                    {
                        float l0 = v0 - s0.x, l1 = v0 - s1.x, l2 = v0 - s2.x;
                        float mx = fmaxf(l0, fmaxf(l1, l2));
                        float e0 = __expf(l0-mx), e1 = __expf(l1-mx), e2 = __expf(l2-mx);
                        o0 = (e0*w0.x + e1*w1.x + e2*w2.x) / (e0 + e1 + e2);
                    }
                    {
                        float l0 = v1 - s0.y, l1 = v1 - s1.y, l2 = v1 - s2.y;
                        float mx = fmaxf(l0, fmaxf(l1, l2));
                        float e0 = __expf(l0-mx), e1 = __expf(l1-mx), e2 = __expf(l2-mx);
                        o1 = (e0*w0.y + e1*w1.y + e2*w2.y) / (e0 + e1 + e2);
                    }
                    *cp = make_float2(o0, o1);
                }
            }
        }
    }
}

// Dual-B GEMM, 512 threads: C1 = A@B1, C2 = A@B2. 8 warps per B → 64 acc regs/thread.
__global__ __launch_bounds__(512) void gemm_dual512(
    const float* __restrict__ A, const float* __restrict__ B1, const float* __restrict__ B2,
    float* __restrict__ C1, float* __restrict__ C2, int M) {
    extern __shared__ float smf[];
    int tid = threadIdx.x;
    int lane = tid & 31, wid = tid >> 5;   // 16 warps
    int wm = wid & 3;                      // M quadrant
    int wsel = (wid >> 2) & 1;             // 0 → B1, 1 → B2  (wid>>2 in 0..3)
    int wn = wid >> 3;                     // 0..1 → N half within selected B
    int g = lane >> 2, q = lane & 3;
    long m0 = (long)blockIdx.x * 128;

    float acc[2][8][4];
    #pragma unroll
    for (int mt = 0; mt < 2; mt++)
        #pragma unroll
        for (int nt = 0; nt < 8; nt++)
            #pragma unroll
            for (int i = 0; i < 4; i++) acc[mt][nt][i] = 0.f;

    int ar[2], ac_[2], br[2], bc[2];
    #pragma unroll
    for (int i = 0; i < 2; i++) {
        int idx = (tid + 512 * i) * 4;
        ar[i] = idx >> 5; ac_[i] = idx & 31;   // A 128x32
        br[i] = idx >> 7; bc[i] = idx & 127;   // B 32x128
    }

    auto prefetch = [&](int kc, int s) {
        float* As  = smf + s * DSTAGE;
        float* Bs1 = As + GSTAGE_A;
        float* Bs2 = Bs1 + GSTAGE_B;
        #pragma unroll
        for (int i = 0; i < 2; i++) {
            long row = m0 + ar[i];
            uint32_t sa = (uint32_t)__cvta_generic_to_shared(&As[ar[i]*36 + ac_[i]]);
            cp_async16(sa, A + row * 128 + kc * 32 + ac_[i], row < M);
        }
        #pragma unroll
        for (int i = 0; i < 2; i++) {
            uint32_t s1 = (uint32_t)__cvta_generic_to_shared(&Bs1[br[i]*136 + bc[i]]);
            cp_async16(s1, B1 + (kc * 32 + br[i]) * 128 + bc[i], true);
            uint32_t s2 = (uint32_t)__cvta_generic_to_shared(&Bs2[br[i]*136 + bc[i]]);
            cp_async16(s2, B2 + (kc * 32 + br[i]) * 128 + bc[i], true);
        }
        asm volatile("cp.async.commit_group;");
    };

    prefetch(0, 0);

    for (int kc = 0; kc < 4; kc++) {
        if (kc < 3) {
            prefetch(kc + 1, (kc + 1) & 1);
            asm volatile("cp.async.wait_group 1;");
        } else {
            asm volatile("cp.async.wait_group 0;");
        }
        __syncthreads();

        const uint32_t* As = reinterpret_cast<const uint32_t*>(smf + (kc & 1) * DSTAGE);
        const uint32_t* Bs = As + GSTAGE_A + wsel * GSTAGE_B;

        #pragma unroll
        for (int ks = 0; ks < 4; ks++) {
            int kc8 = ks * 8;
            uint32_t a[2][4], b[8][2];
            #pragma unroll
            for (int mt = 0; mt < 2; mt++) {
                int row = wm * 32 + mt * 16 + g;
                a[mt][0] = As[row*36 + kc8 + q];
                a[mt][1] = As[(row+8)*36 + kc8 + q];
                a[mt][2] = As[row*36 + kc8 + q + 4];
                a[mt][3] = As[(row+8)*36 + kc8 + q + 4];
            }
            #pragma unroll
            for (int nt = 0; nt < 8; nt++) {
                int col = wn * 64 + nt * 8 + g;
                b[nt][0] = Bs[(kc8 + q)*136 + col];
                b[nt][1] = Bs[(kc8 + q + 4)*136 + col];
            }
            #pragma unroll
            for (int mt = 0; mt < 2; mt++)
                #pragma unroll
                for (int nt = 0; nt < 8; nt++)
                    mma_tf32(acc[mt][nt], a[mt], b[nt]);
        }
        __syncthreads();
    }

    float* C = wsel ? C2 : C1;
    #pragma unroll
    for (int mt = 0; mt < 2; mt++) {
        #pragma unroll
        for (int h = 0; h < 2; h++) {
            long row = m0 + wm * 32 + mt * 16 + g + h * 8;
            if (row >= M) continue;
            #pragma unroll
            for (int nt = 0; nt < 8; nt++) {
                int col = wn * 64 + nt * 8 + q * 2;
                *reinterpret_cast<float2*>(&C[row * 128 + col]) =
                    make_float2(acc[mt][nt][h*2], acc[mt][nt][h*2+1]);
            }
        }
    }
}

// -------- BN kernels --------

__global__ void bn_stats_k(const float* __restrict__ h, float* __restrict__ colsum,
                           float* __restrict__ colsq) {
    __shared__ float ssum[128], ssq[128];
    int tid = threadIdx.x;
    if (tid < 128) { ssum[tid] = 0.f; ssq[tid] = 0.f; }
    __syncthreads();
    int c4 = tid & 31;
    int rstep = gridDim.x * 8;
    float4 s = make_float4(0,0,0,0), s2 = make_float4(0,0,0,0);
    for (int r = blockIdx.x * 8 + (tid >> 5); r < NN; r += rstep) {
        float4 x = reinterpret_cast<const float4*>(h)[(long)r * 32 + c4];
        s.x += x.x; s.y += x.y; s.z += x.z; s.w += x.w;
        s2.x += x.x*x.x; s2.y += x.y*x.y; s2.z += x.z*x.z; s2.w += x.w*x.w;
    }
    atomicAdd(&ssum[c4*4+0], s.x);  atomicAdd(&ssq[c4*4+0], s2.x);
    atomicAdd(&ssum[c4*4+1], s.y);  atomicAdd(&ssq[c4*4+1], s2.y);
    atomicAdd(&ssum[c4*4+2], s.z);  atomicAdd(&ssq[c4*4+2], s2.z);
    atomicAdd(&ssum[c4*4+3], s.w);  atomicAdd(&ssq[c4*4+3], s2.w);
    __syncthreads();
    if (tid < 128) {
        atomicAdd(&colsum[tid], ssum[tid]);
        atomicAdd(&colsq[tid], ssq[tid]);
    }
}

__global__ void bn_apply_relu_k(float* __restrict__ h, const float* __restrict__ gamma,
                                const float* __restrict__ beta,
                                const float* __restrict__ colsum,
                                const float* __restrict__ colsq) {
    __shared__ float sm_mean[128], sm_scale[128], sm_beta[128];
    int tid = threadIdx.x;
    if (tid < 128) {
        const float invN = 1.f / (float)NN;
        float mean = colsum[tid] * invN;
        float var  = colsq[tid] * invN - mean * mean;
        sm_mean[tid] = mean;
        sm_scale[tid] = rsqrtf(var + 1e-5f) * gamma[tid];
        sm_beta[tid] = beta[tid];
    }
    __syncthreads();
    int idx = blockIdx.x * blockDim.x + tid;
    if (idx >= ND4) return;
    int c = (idx & 31) * 4;
    float4 x = reinterpret_cast<float4*>(h)[idx];
    float4 o;
    o.x = fmaxf((x.x - sm_mean[c+0]) * sm_scale[c+0] + sm_beta[c+0], 0.f);
    o.y = fmaxf((x.y - sm_mean[c+1]) * sm_scale[c+1] + sm_beta[c+1], 0.f);
    o.z = fmaxf((x.z - sm_mean[c+2]) * sm_scale[c+2] + sm_beta[c+2], 0.f);
    o.w = fmaxf((x.w - sm_mean[c+3]) * sm_scale[c+3] + sm_beta[c+3], 0.f);
    reinterpret_cast<float4*>(h)[idx] = o;
}

// -------- host --------

extern "C" void kernel_launch(void* const* d_in, const int* in_sizes, int n_in,
                              void* d_out, int out_size) {
    const float* e_emb = (const float*)d_in[1];
    const int* node_ind = (const int*)d_in[26];
    const int* edge_src = (const int*)d_in[27];
    const int* edge_dst = (const int*)d_in[28];

    float *feat, *t1, *t2, *key, *ska, *vv, *inv, *gscale, *colsum, *colsq, *wqa, *wka;
    int* cnt;
    cudaGetSymbolAddress((void**)&feat, g_feat);
    cudaGetSymbolAddress((void**)&t1, g_t1);
    cudaGetSymbolAddress((void**)&t2, g_t2);
    cudaGetSymbolAddress((void**)&key, g_key);
    cudaGetSymbolAddress((void**)&ska, g_ska);
    cudaGetSymbolAddress((void**)&vv, g_v);
    cudaGetSymbolAddress((void**)&cnt, g_cnt);
    cudaGetSymbolAddress((void**)&inv, g_inv);
    cudaGetSymbolAddress((void**)&gscale, g_gscale);
    cudaGetSymbolAddress((void**)&colsum, g_colsum);
    cudaGetSymbolAddress((void**)&colsq, g_colsq);
    cudaGetSymbolAddress((void**)&wqa, g_wqa);
    cudaGetSymbolAddress((void**)&wka, g_wka);

    cudaFuncSetAttribute(gemm_tc<0>, cudaFuncAttributeMaxDynamicSharedMemorySize, GEMM_SMEM_BYTES);
    cudaFuncSetAttribute(gemm_tc<1>, cudaFuncAttributeMaxDynamicSharedMemorySize, GEMM_SMEM_BYTES);
    cudaFuncSetAttribute(gemm_tc<3>, cudaFuncAttributeMaxDynamicSharedMemorySize, GEMM_SMEM_BYTES);
    cudaFuncSetAttribute(gemm_dual512, cudaFuncAttributeMaxDynamicSharedMemorySize, DUAL_SMEM_BYTES);

    const int TPB = 256;
    const int ND4_BLK = (ND4 + TPB - 1) / TPB;
    const int EDGE_BLK = (TT*EE*32 + TPB - 1) / TPB;
    const int G1 = (NN + 127) / 128;
    const int G3 = (TT*NN + 127) / 128;

    cudaMemsetAsync(cnt, 0, TT*NN*sizeof(int), 0);
    count_k<<<(TT*EE + TPB - 1)/TPB, TPB>>>(edge_dst, cnt);
    prep_k<<<(NN + TPB - 1)/TPB, TPB>>>(cnt, inv, gscale);
    gather_feat_k<<<ND4_BLK, TPB>>>((const float*)d_in[0], node_ind, feat);

    const float* gcn_w1[2]    = {(const float*)d_in[2],  (const float*)d_in[14]};
    const float* gcn_gamma[2] = {(const float*)d_in[3],  (const float*)d_in[15]};
    const float* gcn_beta[2]  = {(const float*)d_in[4],  (const float*)d_in[16]};
    const float* gcn_w2[2]    = {(const float*)d_in[5],  (const float*)d_in[17]};
    const float* gcn_b2[2]    = {(const float*)d_in[6],  (const float*)d_in[18]};
    const float* at_wq[2]     = {(const float*)d_in[7],  (const float*)d_in[19]};
    const float* at_wk[2]     = {(const float*)d_in[8],  (const float*)d_in[20]};
    const float* at_wv[2]     = {(const float*)d_in[9],  (const float*)d_in[21]};
    const float* at_wa[2]     = {(const float*)d_in[10], (const float*)d_in[22]};
    const float* at_wp[2]     = {(const float*)d_in[12], (const float*)d_in[24]};
    const float* at_bp[2]     = {(const float*)d_in[13], (const float*)d_in[25]};

    for (int L = 0; L < 2; L++) {
        // ---- GCN layer ----
        init_acc_k<<<ND4_BLK, TPB>>>(feat, gscale, t1);
        gcn_edge_k<<<EDGE_BLK, TPB>>>(feat, e_emb, edge_src, edge_dst, inv, t1);
        gemm_tc<0><<<G1, 256, GEMM_SMEM_BYTES>>>(t1, gcn_w1[L], t2, nullptr, NN, nullptr, nullptr);
        cudaMemsetAsync(colsum, 0, DD*sizeof(float), 0);
        cudaMemsetAsync(colsq, 0, DD*sizeof(float), 0);
        bn_stats_k<<<1024, 256>>>(t2, colsum, colsq);
        bn_apply_relu_k<<<ND4_BLK, TPB>>>(t2, gcn_gamma[L], gcn_beta[L], colsum, colsq);
        gemm_tc<1><<<G1, 256, GEMM_SMEM_BYTES>>>(t2, gcn_w2[L], feat, gcn_b2[L], NN, nullptr, nullptr);

        // ---- Attention layer ----
        gemm_tc<0><<<1, 256, GEMM_SMEM_BYTES>>>(at_wq[L], at_wa[L], wqa, nullptr, 128, nullptr, nullptr);
        gemm_tc<0><<<1, 256, GEMM_SMEM_BYTES>>>(at_wk[L], at_wa[L], wka, nullptr, 128, nullptr, nullptr);
        cudaMemsetAsync(key, 0, (size_t)3*ND*sizeof(float), 0);
        attn_edge_k<<<EDGE_BLK, TPB>>>(feat, e_emb, edge_src, edge_dst, inv, key);
        gemm_dual512<<<G3, 512, DUAL_SMEM_BYTES>>>(key, wka, at_wv[L], ska, vv, TT*NN);
        // qa GEMM with softmax-combine epilogue → t2 (runs after dual; reads ska/vv)
        gemm_tc<3><<<G1, 256, GEMM_SMEM_BYTES>>>(feat, wqa, t2, nullptr, NN, ska, vv);
        gemm_tc<1><<<G1, 256, GEMM_SMEM_BYTES>>>(t2, at_wp[L], feat, at_bp[L], NN, nullptr, nullptr);
    }

    cudaMemcpyAsync(d_out, feat, (size_t)ND*sizeof(float), cudaMemcpyDeviceToDevice, 0);
    if (out_size >= ND + TT*DD) {
        cudaMemcpyAsync((float*)d_out + ND, e_emb, TT*DD*sizeof(float),
                        cudaMemcpyDeviceToDevice, 0);
    }
}

// round 10
// speedup vs baseline: 1.1256x; 1.1256x over previous
#include <cuda_runtime.h>
#include <cuda_bf16.h>
#include <cstdint>
#include <math.h>

#define NN 100000
#define DD 128
#define EE 250000
#define TT 3
#define ND (NN*DD)
#define ND4 (ND/4)
#define TNN (TT*NN)
#define NB_SCAN ((TNN + 255) / 256)   // 1172
#define SCHUNK ((NB_SCAN + 255) / 256) // 5

// -------- scratch --------
__device__ float g_feat[ND];
__device__ float g_t1[ND];
__device__ float g_t2[ND];
__device__ float g_key[3*ND];
__device__ float g_ska[3*ND];
__device__ float g_v[3*ND];
__device__ int   g_cnt[TNN];
__device__ int   g_offs[TNN];
__device__ int   g_fill[TNN];
__device__ int   g_partial[NB_SCAN];
__device__ int   g_ssrc[TT*EE];
__device__ float g_inv[TNN];
__device__ float g_gscale[NN];
__device__ float g_colsum[DD];
__device__ float g_colsq[DD];
__device__ float g_wqa[DD*DD];
__device__ float g_wka[DD*DD];

// -------- setup kernels --------

__global__ void gather_feat_k(const float* __restrict__ n_emb, const int* __restrict__ ind,
                              float* __restrict__ feat) {
    int idx = blockIdx.x * blockDim.x + threadIdx.x;
    if (idx >= ND4) return;
    int n = idx >> 5;
    reinterpret_cast<float4*>(feat)[idx] =
        reinterpret_cast<const float4*>(n_emb)[(long)ind[n] * 32 + (idx & 31)];
}

__global__ void count_k(const int* __restrict__ dst, int* __restrict__ cnt) {
    int e = blockIdx.x * blockDim.x + threadIdx.x;
    if (e >= TT*EE) return;
    int t = e / EE;
    atomicAdd(&cnt[t * NN + dst[e]], 1);
}

__global__ void prep_k(const int* __restrict__ cnt, float* __restrict__ inv,
                       float* __restrict__ gscale) {
    int n = blockIdx.x * blockDim.x + threadIdx.x;
    if (n >= NN) return;
    int c0 = cnt[n], c1 = cnt[NN + n], c2 = cnt[2*NN + n];
    inv[n]        = 1.f / (float)max(c0, 1);
    inv[NN + n]   = 1.f / (float)max(c1, 1);
    inv[2*NN + n] = 1.f / (float)max(c2, 1);
    gscale[n] = (float)((c0 > 0) + (c1 > 0) + (c2 > 0));
}

// ---- 3-kernel exclusive scan of cnt → offs ----
__global__ void scan_block_k(const int* __restrict__ cnt, int* __restrict__ offs,
                             int* __restrict__ partial) {
    __shared__ int sh[256];
    int tid = threadIdx.x;
    int i = blockIdx.x * 256 + tid;
    int v = (i < TNN) ? cnt[i] : 0;
    sh[tid] = v; __syncthreads();
    #pragma unroll
    for (int off = 1; off < 256; off <<= 1) {
        int x = (tid >= off) ? sh[tid - off] : 0;
        __syncthreads();
        sh[tid] += x;
        __syncthreads();
    }
    if (i < TNN) offs[i] = sh[tid] - v;
    if (tid == 255) partial[blockIdx.x] = sh[tid];
}

__global__ void scan_partial_k(int* __restrict__ partial) {
    __shared__ int sh[256];
    int tid = threadIdx.x;
    int base = tid * SCHUNK;
    int loc[SCHUNK];
    int s = 0;
    #pragma unroll
    for (int j = 0; j < SCHUNK; j++) {
        int idx = base + j;
        int v = (idx < NB_SCAN) ? partial[idx] : 0;
        loc[j] = s; s += v;
    }
    sh[tid] = s; __syncthreads();
    #pragma unroll
    for (int off = 1; off < 256; off <<= 1) {
        int x = (tid >= off) ? sh[tid - off] : 0;
        __syncthreads();
        sh[tid] += x;
        __syncthreads();
    }
    int excl = sh[tid] - s;
    #pragma unroll
    for (int j = 0; j < SCHUNK; j++) {
        int idx = base + j;
        if (idx < NB_SCAN) partial[idx] = excl + loc[j];
    }
}

__global__ void scan_add_k(int* __restrict__ offs, const int* __restrict__ partial) {
    int i = blockIdx.x * 256 + threadIdx.x;
    if (i < TNN) offs[i] += partial[blockIdx.x];
}

__global__ void scatter_k(const int* __restrict__ src, const int* __restrict__ dst,
                          const int* __restrict__ offs, int* __restrict__ fill,
                          int* __restrict__ ssrc) {
    int e = blockIdx.x * blockDim.x + threadIdx.x;
    if (e >= TT*EE) return;
    int t = e / EE;
    int td = t * NN + dst[e];
    int pos = offs[td] + atomicAdd(&fill[td], 1);
    ssrc[pos] = src[e];
}

// -------- sorted edge passes (no atomics, no memsets) --------

// warp per dst node: t1[n] = feat[n]*gscale[n] - Σ_t inv_t * Σ_{e∈seg(t,n)} feat[src_e]*emb_t
__global__ void gcn_edge_sorted(const float* __restrict__ feat, const float* __restrict__ emb,
                                const int* __restrict__ ssrc, const int* __restrict__ offs,
                                const int* __restrict__ cnt, const float* __restrict__ inv,
                                const float* __restrict__ gscale, float* __restrict__ out) {
    int gw = (blockIdx.x * blockDim.x + threadIdx.x) >> 5;
    int lane = threadIdx.x & 31;
    if (gw >= NN) return;
    float4 a = reinterpret_cast<const float4*>(feat)[gw * 32 + lane];
    float gs = gscale[gw];
    float4 acc = make_float4(a.x * gs, a.y * gs, a.z * gs, a.w * gs);
    #pragma unroll
    for (int t = 0; t < TT; t++) {
        int td = t * NN + gw;
        int len = cnt[td];
        if (len == 0) continue;
        int beg = offs[td];
        float4 s = make_float4(0.f, 0.f, 0.f, 0.f);
        for (int i = 0; i < len; i++) {
            int sn = ssrc[beg + i];
            float4 f = reinterpret_cast<const float4*>(feat)[sn * 32 + lane];
            s.x += f.x; s.y += f.y; s.z += f.z; s.w += f.w;
        }
        float4 e = reinterpret_cast<const float4*>(emb)[t * 32 + lane];
        float w = inv[td];
        acc.x -= s.x * e.x * w; acc.y -= s.y * e.y * w;
        acc.z -= s.z * e.z * w; acc.w -= s.w * e.w * w;
    }
    reinterpret_cast<float4*>(out)[gw * 32 + lane] = acc;
}

// warp per (t,dst): key[td] = inv_td * Σ feat[src]*emb_t   (zero when segment empty)
__global__ void attn_edge_sorted(const float* __restrict__ feat, const float* __restrict__ emb,
                                 const int* __restrict__ ssrc, const int* __restrict__ offs,
                                 const int* __restrict__ cnt, const float* __restrict__ inv,
                                 float* __restrict__ key) {
    int gw = (blockIdx.x * blockDim.x + threadIdx.x) >> 5;
    int lane = threadIdx.x & 31;
    if (gw >= TNN) return;
    int t = gw / NN;
    int len = cnt[gw];
    int beg = offs[gw];
    float4 s = make_float4(0.f, 0.f, 0.f, 0.f);
    for (int i = 0; i < len; i++) {
        int sn = ssrc[beg + i];
        float4 f = reinterpret_cast<const float4*>(feat)[sn * 32 + lane];
        s.x += f.x; s.y += f.y; s.z += f.z; s.w += f.w;
    }
    float4 e = reinterpret_cast<const float4*>(emb)[t * 32 + lane];
    float w = inv[gw];
    reinterpret_cast<float4*>(key)[(long)gw * 32 + lane] =
        make_float4(s.x * e.x * w, s.y * e.y * w, s.z * e.z * w, s.w * e.w * w);
}

// -------- tf32 GEMM with cp.async double buffering (R8, unchanged) --------

#define GSTAGE_A (128*36)
#define GSTAGE_B (32*136)
#define GSTAGE   (GSTAGE_A + GSTAGE_B)
#define GEMM_SMEM_BYTES (2*GSTAGE*4)

__device__ __forceinline__ void cp_async16(uint32_t saddr, const void* gptr, bool pred) {
    int sz = pred ? 16 : 0;
    asm volatile("cp.async.ca.shared.global [%0], [%1], 16, %2;"
                 :: "r"(saddr), "l"(gptr), "r"(sz));
}

__device__ __forceinline__ void mma_tf32(float* c, const uint32_t* a, const uint32_t* b) {
    asm volatile("mma.sync.aligned.m16n8k8.row.col.f32.tf32.tf32.f32 "
                 "{%0,%1,%2,%3}, {%4,%5,%6,%7}, {%8,%9}, {%0,%1,%2,%3};"
                 : "+f"(c[0]), "+f"(c[1]), "+f"(c[2]), "+f"(c[3])
                 : "r"(a[0]), "r"(a[1]), "r"(a[2]), "r"(a[3]), "r"(b[0]), "r"(b[1]));
}

template<int EPI>
__global__ __launch_bounds__(256) void gemm_tc(const float* __restrict__ A,
                                               const float* __restrict__ B,
                                               float* __restrict__ C,
                                               const float* __restrict__ bias, int M) {
    extern __shared__ float smf[];
    int tid = threadIdx.x;
    int lane = tid & 31, wid = tid >> 5;
    int wm = wid & 3, wn = wid >> 2;
    int g = lane >> 2, q = lane & 3;
    long m0 = (long)blockIdx.x * 128;

    float acc[2][8][4];
    #pragma unroll
    for (int mt = 0; mt < 2; mt++)
        #pragma unroll
        for (int nt = 0; nt < 8; nt++)
            #pragma unroll
            for (int i = 0; i < 4; i++) acc[mt][nt][i] = 0.f;

    int ar[4], ac_[4], br[4], bc[4];
    #pragma unroll
    for (int i = 0; i < 4; i++) {
        int idx = (tid + 256 * i) * 4;
        ar[i] = idx >> 5; ac_[i] = idx & 31;
        br[i] = idx >> 7; bc[i] = idx & 127;
    }

    auto prefetch = [&](int kc, int s) {
        float* As = smf + s * GSTAGE;
        float* Bs = As + GSTAGE_A;
        #pragma unroll
        for (int i = 0; i < 4; i++) {
            long row = m0 + ar[i];
            uint32_t sa = (uint32_t)__cvta_generic_to_shared(&As[ar[i]*36 + ac_[i]]);
            cp_async16(sa, A + row * 128 + kc * 32 + ac_[i], row < M);
        }
        #pragma unroll
        for (int i = 0; i < 4; i++) {
            uint32_t sb = (uint32_t)__cvta_generic_to_shared(&Bs[br[i]*136 + bc[i]]);
            cp_async16(sb, B + (kc * 32 + br[i]) * 128 + bc[i], true);
        }
        asm volatile("cp.async.commit_group;");
    };

    prefetch(0, 0);

    for (int kc = 0; kc < 4; kc++) {
        if (kc < 3) {
            prefetch(kc + 1, (kc + 1) & 1);
            asm volatile("cp.async.wait_group 1;");
        } else {
            asm volatile("cp.async.wait_group 0;");
        }
        __syncthreads();

        const uint32_t* As = reinterpret_cast<const uint32_t*>(smf + (kc & 1) * GSTAGE);
        const uint32_t* Bs = As + GSTAGE_A;

        #pragma unroll
        for (int ks = 0; ks < 4; ks++) {
            int kc8 = ks * 8;
            uint32_t a[2][4], b[8][2];
            #pragma unroll
            for (int mt = 0; mt < 2; mt++) {
                int row = wm * 32 + mt * 16 + g;
                a[mt][0] = As[row*36 + kc8 + q];
                a[mt][1] = As[(row+8)*36 + kc8 + q];
                a[mt][2] = As[row*36 + kc8 + q + 4];
                a[mt][3] = As[(row+8)*36 + kc8 + q + 4];
            }
            #pragma unroll
            for (int nt = 0; nt < 8; nt++) {
                int col = wn * 64 + nt * 8 + g;
                b[nt][0] = Bs[(kc8 + q)*136 + col];
                b[nt][1] = Bs[(kc8 + q + 4)*136 + col];
            }
            #pragma unroll
            for (int mt = 0; mt < 2; mt++)
                #pragma unroll
                for (int nt = 0; nt < 8; nt++)
                    mma_tf32(acc[mt][nt], a[mt], b[nt]);
        }
        __syncthreads();
    }

    #pragma unroll
    for (int mt = 0; mt < 2; mt++) {
        #pragma unroll
        for (int h = 0; h < 2; h++) {
            long row = m0 + wm * 32 + mt * 16 + g + h * 8;
            if (row >= M) continue;
            #pragma unroll
            for (int nt = 0; nt < 8; nt++) {
                int col = wn * 64 + nt * 8 + q * 2;
                float2* cp = reinterpret_cast<float2*>(&C[row * 128 + col]);
                float v0 = acc[mt][nt][h * 2], v1 = acc[mt][nt][h * 2 + 1];
                if (EPI == 0) {
                    *cp = make_float2(v0, v1);
                } else {
                    float2 prev = *cp;
                    *cp = make_float2(prev.x + v0 + bias[col], prev.y + v1 + bias[col + 1]);
                }
            }
        }
    }
}

// -------- BN / softmax kernels --------

__global__ void bn_stats_k(const float* __restrict__ h, float* __restrict__ colsum,
                           float* __restrict__ colsq) {
    __shared__ float ssum[128], ssq[128];
    int tid = threadIdx.x;
    if (tid < 128) { ssum[tid] = 0.f; ssq[tid] = 0.f; }
    __syncthreads();
    int c4 = tid & 31;
    int rstep = gridDim.x * 8;
    float4 s = make_float4(0,0,0,0), s2 = make_float4(0,0,0,0);
    for (int r = blockIdx.x * 8 + (tid >> 5); r < NN; r += rstep) {
        float4 x = reinterpret_cast<const float4*>(h)[(long)r * 32 + c4];
        s.x += x.x; s.y += x.y; s.z += x.z; s.w += x.w;
        s2.x += x.x*x.x; s2.y += x.y*x.y; s2.z += x.z*x.z; s2.w += x.w*x.w;
    }
    atomicAdd(&ssum[c4*4+0], s.x);  atomicAdd(&ssq[c4*4+0], s2.x);
    atomicAdd(&ssum[c4*4+1], s.y);  atomicAdd(&ssq[c4*4+1], s2.y);
    atomicAdd(&ssum[c4*4+2], s.z);  atomicAdd(&ssq[c4*4+2], s2.z);
    atomicAdd(&ssum[c4*4+3], s.w);  atomicAdd(&ssq[c4*4+3], s2.w);
    __syncthreads();
    if (tid < 128) {
        atomicAdd(&colsum[tid], ssum[tid]);
        atomicAdd(&colsq[tid], ssq[tid]);
    }
}

__global__ void bn_apply_relu_k(float* __restrict__ h, const float* __restrict__ gamma,
                                const float* __restrict__ beta,
                                const float* __restrict__ colsum,
                                const float* __restrict__ colsq) {
    __shared__ float sm_mean[128], sm_scale[128], sm_beta[128];
    int tid = threadIdx.x;
    if (tid < 128) {
        const float invN = 1.f / (float)NN;
        float mean = colsum[tid] * invN;
        float var  = colsq[tid] * invN - mean * mean;
        sm_mean[tid] = mean;
        sm_scale[tid] = rsqrtf(var + 1e-5f) * gamma[tid];
        sm_beta[tid] = beta[tid];
    }
    __syncthreads();
    int idx = blockIdx.x * blockDim.x + tid;
    if (idx >= ND4) return;
    int c = (idx & 31) * 4;
    float4 x = reinterpret_cast<float4*>(h)[idx];
    float4 o;
    o.x = fmaxf((x.x - sm_mean[c+0]) * sm_scale[c+0] + sm_beta[c+0], 0.f);
    o.y = fmaxf((x.y - sm_mean[c+1]) * sm_scale[c+1] + sm_beta[c+1], 0.f);
    o.z = fmaxf((x.z - sm_mean[c+2]) * sm_scale[c+2] + sm_beta[c+2], 0.f);
    o.w = fmaxf((x.w - sm_mean[c+3]) * sm_scale[c+3] + sm_beta[c+3], 0.f);
    reinterpret_cast<float4*>(h)[idx] = o;
}

__global__ void attn_combine_k(const float* __restrict__ qa, const float* __restrict__ ska,
                               const float* __restrict__ vv, float* __restrict__ o) {
    int idx = blockIdx.x * blockDim.x + threadIdx.x;
    if (idx >= ND4) return;
    float4 q  = reinterpret_cast<const float4*>(qa)[idx];
    float4 s0 = reinterpret_cast<const float4*>(ska)[idx];
    float4 s1 = reinterpret_cast<const float4*>(ska)[idx + ND4];
    float4 s2 = reinterpret_cast<const float4*>(ska)[idx + 2*ND4];
    float4 v0 = reinterpret_cast<const float4*>(vv)[idx];
    float4 v1 = reinterpret_cast<const float4*>(vv)[idx + ND4];
    float4 v2 = reinterpret_cast<const float4*>(vv)[idx + 2*ND4];
    float4 r;
    const float* pq = &q.x; const float* p0 = &s0.x; const float* p1 = &s1.x;
    const float* p2 = &s2.x; const float* w0 = &v0.x; const float* w1 = &v1.x;
    const float* w2 = &v2.x; float* pr = &r.x;
    #pragma unroll
    for (int j = 0; j < 4; j++) {
        float l0 = pq[j] - p0[j], l1 = pq[j] - p1[j], l2 = pq[j] - p2[j];
        float m = fmaxf(l0, fmaxf(l1, l2));
        float e0 = __expf(l0 - m), e1 = __expf(l1 - m), e2 = __expf(l2 - m);
        pr[j] = (e0 * w0[j] + e1 * w1[j] + e2 * w2[j]) / (e0 + e1 + e2);
    }
    reinterpret_cast<float4*>(o)[idx] = r;
}

// -------- host --------

extern "C" void kernel_launch(void* const* d_in, const int* in_sizes, int n_in,
                              void* d_out, int out_size) {
    const float* e_emb = (const float*)d_in[1];
    const int* node_ind = (const int*)d_in[26];
    const int* edge_src = (const int*)d_in[27];
    const int* edge_dst = (const int*)d_in[28];

    float *feat, *t1, *t2, *key, *ska, *vv, *inv, *gscale, *colsum, *colsq, *wqa, *wka;
    int *cnt, *offs, *fill, *partial, *ssrc;
    cudaGetSymbolAddress((void**)&feat, g_feat);
    cudaGetSymbolAddress((void**)&t1, g_t1);
    cudaGetSymbolAddress((void**)&t2, g_t2);
    cudaGetSymbolAddress((void**)&key, g_key);
    cudaGetSymbolAddress((void**)&ska, g_ska);
    cudaGetSymbolAddress((void**)&vv, g_v);
    cudaGetSymbolAddress((void**)&cnt, g_cnt);
    cudaGetSymbolAddress((void**)&offs, g_offs);
    cudaGetSymbolAddress((void**)&fill, g_fill);
    cudaGetSymbolAddress((void**)&partial, g_partial);
    cudaGetSymbolAddress((void**)&ssrc, g_ssrc);
    cudaGetSymbolAddress((void**)&inv, g_inv);
    cudaGetSymbolAddress((void**)&gscale, g_gscale);
    cudaGetSymbolAddress((void**)&colsum, g_colsum);
    cudaGetSymbolAddress((void**)&colsq, g_colsq);
    cudaGetSymbolAddress((void**)&wqa, g_wqa);
    cudaGetSymbolAddress((void**)&wka, g_wka);

    cudaFuncSetAttribute(gemm_tc<0>, cudaFuncAttributeMaxDynamicSharedMemorySize, GEMM_SMEM_BYTES);
    cudaFuncSetAttribute(gemm_tc<1>, cudaFuncAttributeMaxDynamicSharedMemorySize, GEMM_SMEM_BYTES);

    const int TPB = 256;
    const int ND4_BLK = (ND4 + TPB - 1) / TPB;
    const int E_BLK = (TT*EE + TPB - 1) / TPB;
    const int GCNW_BLK = (NN*32 + TPB - 1) / TPB;     // warp per node
    const int ATTW_BLK = (TNN*32 + TPB - 1) / TPB;    // warp per (t,node)
    const int G1 = (NN + 127) / 128;
    const int G3 = (TNN + 127) / 128;

    // ---- CSR build (once per call) ----
    cudaMemsetAsync(cnt, 0, TNN*sizeof(int), 0);
    cudaMemsetAsync(fill, 0, TNN*sizeof(int), 0);
    count_k<<<E_BLK, TPB>>>(edge_dst, cnt);
    prep_k<<<(NN + TPB - 1)/TPB, TPB>>>(cnt, inv, gscale);
    scan_block_k<<<NB_SCAN, 256>>>(cnt, offs, partial);
    scan_partial_k<<<1, 256>>>(partial);
    scan_add_k<<<NB_SCAN, 256>>>(offs, partial);
    scatter_k<<<E_BLK, TPB>>>(edge_src, edge_dst, offs, fill, ssrc);
    gather_feat_k<<<ND4_BLK, TPB>>>((const float*)d_in[0], node_ind, feat);

    const float* gcn_w1[2]    = {(const float*)d_in[2],  (const float*)d_in[14]};
    const float* gcn_gamma[2] = {(const float*)d_in[3],  (const float*)d_in[15]};
    const float* gcn_beta[2]  = {(const float*)d_in[4],  (const float*)d_in[16]};
    const float* gcn_w2[2]    = {(const float*)d_in[5],  (const float*)d_in[17]};
    const float* gcn_b2[2]    = {(const float*)d_in[6],  (const float*)d_in[18]};
    const float* at_wq[2]     = {(const float*)d_in[7],  (const float*)d_in[19]};
    const float* at_wk[2]     = {(const float*)d_in[8],  (const float*)d_in[20]};
    const float* at_wv[2]     = {(const float*)d_in[9],  (const float*)d_in[21]};
    const float* at_wa[2]     = {(const float*)d_in[10], (const float*)d_in[22]};
    const float* at_wp[2]     = {(const float*)d_in[12], (const float*)d_in[24]};
    const float* at_bp[2]     = {(const float*)d_in[13], (const float*)d_in[25]};

    for (int L = 0; L < 2; L++) {
        // ---- GCN layer ----
        gcn_edge_sorted<<<GCNW_BLK, TPB>>>(feat, e_emb, ssrc, offs, cnt, inv, gscale, t1);
        gemm_tc<0><<<G1, 256, GEMM_SMEM_BYTES>>>(t1, gcn_w1[L], t2, nullptr, NN);
        cudaMemsetAsync(colsum, 0, DD*sizeof(float), 0);
        cudaMemsetAsync(colsq, 0, DD*sizeof(float), 0);
        bn_stats_k<<<1024, 256>>>(t2, colsum, colsq);
        bn_apply_relu_k<<<ND4_BLK, TPB>>>(t2, gcn_gamma[L], gcn_beta[L], colsum, colsq);
        gemm_tc<1><<<G1, 256, GEMM_SMEM_BYTES>>>(t2, gcn_w2[L], feat, gcn_b2[L], NN);

        // ---- Attention layer ----
        gemm_tc<0><<<1, 256, GEMM_SMEM_BYTES>>>(at_wq[L], at_wa[L], wqa, nullptr, 128);
        gemm_tc<0><<<1, 256, GEMM_SMEM_BYTES>>>(at_wk[L], at_wa[L], wka, nullptr, 128);
        attn_edge_sorted<<<ATTW_BLK, TPB>>>(feat, e_emb, ssrc, offs, cnt, inv, key);
        gemm_tc<0><<<G1, 256, GEMM_SMEM_BYTES>>>(feat, wqa, t1, nullptr, NN);
        gemm_tc<0><<<G3, 256, GEMM_SMEM_BYTES>>>(key, wka, ska, nullptr, TNN);
        gemm_tc<0><<<G3, 256, GEMM_SMEM_BYTES>>>(key, at_wv[L], vv, nullptr, TNN);
        attn_combine_k<<<ND4_BLK, TPB>>>(t1, ska, vv, t2);
        gemm_tc<1><<<G1, 256, GEMM_SMEM_BYTES>>>(t2, at_wp[L], feat, at_bp[L], NN);
    }

    cudaMemcpyAsync(d_out, feat, (size_t)ND*sizeof(float), cudaMemcpyDeviceToDevice, 0);
    if (out_size >= ND + TT*DD) {
        cudaMemcpyAsync((float*)d_out + ND, e_emb, TT*DD*sizeof(float),
                        cudaMemcpyDeviceToDevice, 0);
    }
}

// round 11
// speedup vs baseline: 1.3815x; 1.2274x over previous
#include <cuda_runtime.h>
#include <cuda_fp16.h>
#include <cstdint>
#include <math.h>

#define NN 100000
#define DD 128
#define EE 250000
#define TT 3
#define ND (NN*DD)
#define ND4 (ND/4)
#define TNN (TT*NN)
#define NB_SCAN ((TNN + 255) / 256)
#define SCHUNK ((NB_SCAN + 255) / 256)

// -------- scratch --------
__device__ float  g_feat[ND];          // f32 residual stream
__device__ __half g_feat16[ND];        // fp16 shadow of feat
__device__ __half g_t1h[ND];
__device__ __half g_t2h[ND];
__device__ __half g_keyh[3*ND];
__device__ __half g_skah[3*ND];
__device__ __half g_vh[3*ND];
__device__ __half g_qah[ND];
__device__ __half g_t2ch[ND];
__device__ __half g_w16[8][DD*DD];     // transposed fp16 weights: w1,w2,wv,wp ×2 layers
__device__ __half g_wqa16[DD*DD];      // transposed
__device__ __half g_wka16[DD*DD];      // transposed
__device__ int    g_cnt[TNN];
__device__ int    g_offs[TNN];
__device__ int    g_fill[TNN];
__device__ int    g_partial[NB_SCAN];
__device__ int    g_ssrc[TT*EE];
__device__ float  g_inv[TNN];
__device__ float  g_gscale[NN];
__device__ float  g_colsum[DD];
__device__ float  g_colsq[DD];

// -------- setup kernels --------

__global__ void gather_feat_k(const float* __restrict__ n_emb, const int* __restrict__ ind,
                              float* __restrict__ feat, __half* __restrict__ feat16) {
    int idx = blockIdx.x * blockDim.x + threadIdx.x;
    if (idx >= ND4) return;
    int n = idx >> 5;
    float4 v = reinterpret_cast<const float4*>(n_emb)[(long)ind[n] * 32 + (idx & 31)];
    reinterpret_cast<float4*>(feat)[idx] = v;
    __half2* h = reinterpret_cast<__half2*>(feat16) + idx * 2;
    h[0] = __floats2half2_rn(v.x, v.y);
    h[1] = __floats2half2_rn(v.z, v.w);
}

__global__ void convert_wt_k(const float* __restrict__ w, __half* __restrict__ wt) {
    int i = blockIdx.x * blockDim.x + threadIdx.x;
    if (i >= DD*DD) return;
    int n = i >> 7, k = i & 127;
    wt[n * 128 + k] = __float2half(w[k * 128 + n]);   // transpose: wt[n][k]
}

__global__ void count_k(const int* __restrict__ dst, int* __restrict__ cnt) {
    int e = blockIdx.x * blockDim.x + threadIdx.x;
    if (e >= TT*EE) return;
    int t = e / EE;
    atomicAdd(&cnt[t * NN + dst[e]], 1);
}

__global__ void prep_k(const int* __restrict__ cnt, float* __restrict__ inv,
                       float* __restrict__ gscale) {
    int n = blockIdx.x * blockDim.x + threadIdx.x;
    if (n >= NN) return;
    int c0 = cnt[n], c1 = cnt[NN + n], c2 = cnt[2*NN + n];
    inv[n]        = 1.f / (float)max(c0, 1);
    inv[NN + n]   = 1.f / (float)max(c1, 1);
    inv[2*NN + n] = 1.f / (float)max(c2, 1);
    gscale[n] = (float)((c0 > 0) + (c1 > 0) + (c2 > 0));
}

__global__ void scan_block_k(const int* __restrict__ cnt, int* __restrict__ offs,
                             int* __restrict__ partial) {
    __shared__ int sh[256];
    int tid = threadIdx.x;
    int i = blockIdx.x * 256 + tid;
    int v = (i < TNN) ? cnt[i] : 0;
    sh[tid] = v; __syncthreads();
    #pragma unroll
    for (int off = 1; off < 256; off <<= 1) {
        int x = (tid >= off) ? sh[tid - off] : 0;
        __syncthreads();
        sh[tid] += x;
        __syncthreads();
    }
    if (i < TNN) offs[i] = sh[tid] - v;
    if (tid == 255) partial[blockIdx.x] = sh[tid];
}

__global__ void scan_partial_k(int* __restrict__ partial) {
    __shared__ int sh[256];
    int tid = threadIdx.x;
    int base = tid * SCHUNK;
    int loc[SCHUNK];
    int s = 0;
    #pragma unroll
    for (int j = 0; j < SCHUNK; j++) {
        int idx = base + j;
        int v = (idx < NB_SCAN) ? partial[idx] : 0;
        loc[j] = s; s += v;
    }
    sh[tid] = s; __syncthreads();
    #pragma unroll
    for (int off = 1; off < 256; off <<= 1) {
        int x = (tid >= off) ? sh[tid - off] : 0;
        __syncthreads();
        sh[tid] += x;
        __syncthreads();
    }
    int excl = sh[tid] - s;
    #pragma unroll
    for (int j = 0; j < SCHUNK; j++) {
        int idx = base + j;
        if (idx < NB_SCAN) partial[idx] = excl + loc[j];
    }
}

__global__ void scan_add_k(int* __restrict__ offs, const int* __restrict__ partial) {
    int i = blockIdx.x * 256 + threadIdx.x;
    if (i < TNN) offs[i] += partial[blockIdx.x];
}

__global__ void scatter_k(const int* __restrict__ src, const int* __restrict__ dst,
                          const int* __restrict__ offs, int* __restrict__ fill,
                          int* __restrict__ ssrc) {
    int e = blockIdx.x * blockDim.x + threadIdx.x;
    if (e >= TT*EE) return;
    int t = e / EE;
    int td = t * NN + dst[e];
    int pos = offs[td] + atomicAdd(&fill[td], 1);
    ssrc[pos] = src[e];
}

// -------- sorted edge passes (fp16 gather, f32 accumulate, fp16 store) --------

__device__ __forceinline__ void h4_to_f4(uint2 u, float4& f) {
    __half2 h0 = *reinterpret_cast<__half2*>(&u.x);
    __half2 h1 = *reinterpret_cast<__half2*>(&u.y);
    float2 a = __half22float2(h0), b = __half22float2(h1);
    f.x = a.x; f.y = a.y; f.z = b.x; f.w = b.y;
}

__device__ __forceinline__ uint2 f4_to_h4(float4 f) {
    __half2 h0 = __floats2half2_rn(f.x, f.y);
    __half2 h1 = __floats2half2_rn(f.z, f.w);
    uint2 u;
    u.x = *reinterpret_cast<uint32_t*>(&h0);
    u.y = *reinterpret_cast<uint32_t*>(&h1);
    return u;
}

__global__ void gcn_edge_sorted(const __half* __restrict__ feat16, const float* __restrict__ emb,
                                const int* __restrict__ ssrc, const int* __restrict__ offs,
                                const int* __restrict__ cnt, const float* __restrict__ inv,
                                const float* __restrict__ gscale, __half* __restrict__ out) {
    int gw = (blockIdx.x * blockDim.x + threadIdx.x) >> 5;
    int lane = threadIdx.x & 31;
    if (gw >= NN) return;
    const uint2* f16 = reinterpret_cast<const uint2*>(feat16);
    float4 a; h4_to_f4(f16[gw * 32 + lane], a);
    float gs = gscale[gw];
    float4 acc = make_float4(a.x * gs, a.y * gs, a.z * gs, a.w * gs);
    #pragma unroll
    for (int t = 0; t < TT; t++) {
        int td = t * NN + gw;
        int len = cnt[td];
        if (len == 0) continue;
        int beg = offs[td];
        float4 s = make_float4(0.f, 0.f, 0.f, 0.f);
        for (int i = 0; i < len; i++) {
            int sn = ssrc[beg + i];
            float4 f; h4_to_f4(f16[sn * 32 + lane], f);
            s.x += f.x; s.y += f.y; s.z += f.z; s.w += f.w;
        }
        float4 e = reinterpret_cast<const float4*>(emb)[t * 32 + lane];
        float w = inv[td];
        acc.x -= s.x * e.x * w; acc.y -= s.y * e.y * w;
        acc.z -= s.z * e.z * w; acc.w -= s.w * e.w * w;
    }
    reinterpret_cast<uint2*>(out)[gw * 32 + lane] = f4_to_h4(acc);
}

__global__ void attn_edge_sorted(const __half* __restrict__ feat16, const float* __restrict__ emb,
                                 const int* __restrict__ ssrc, const int* __restrict__ offs,
                                 const int* __restrict__ cnt, const float* __restrict__ inv,
                                 __half* __restrict__ key) {
    int gw = (blockIdx.x * blockDim.x + threadIdx.x) >> 5;
    int lane = threadIdx.x & 31;
    if (gw >= TNN) return;
    int t = gw / NN;
    int len = cnt[gw];
    int beg = offs[gw];
    const uint2* f16 = reinterpret_cast<const uint2*>(feat16);
    float4 s = make_float4(0.f, 0.f, 0.f, 0.f);
    for (int i = 0; i < len; i++) {
        int sn = ssrc[beg + i];
        float4 f; h4_to_f4(f16[sn * 32 + lane], f);
        s.x += f.x; s.y += f.y; s.z += f.z; s.w += f.w;
    }
    float4 e = reinterpret_cast<const float4*>(emb)[t * 32 + lane];
    float w = inv[gw];
    reinterpret_cast<uint2*>(key)[(long)gw * 32 + lane] =
        f4_to_h4(make_float4(s.x*e.x*w, s.y*e.y*w, s.z*e.z*w, s.w*e.w*w));
}

// -------- fp16 tensor-core GEMM, cp.async double buffered --------
// C[M,128] = A[M,128] @ Bt^T  where Bt is [n][k] fp16 (pre-transposed).
// EPI 0: store fp16 C. EPI 1: featf += acc + bias (f32) and refresh feat16.

__device__ __forceinline__ void cp_async16(uint32_t saddr, const void* gptr, bool pred) {
    int sz = pred ? 16 : 0;
    asm volatile("cp.async.ca.shared.global [%0], [%1], 16, %2;"
                 :: "r"(saddr), "l"(gptr), "r"(sz));
}

__device__ __forceinline__ void mma_f16(float* c, const uint32_t* a, const uint32_t* b) {
    asm volatile("mma.sync.aligned.m16n8k16.row.col.f32.f16.f16.f32 "
                 "{%0,%1,%2,%3}, {%4,%5,%6,%7}, {%8,%9}, {%0,%1,%2,%3};"
                 : "+f"(c[0]), "+f"(c[1]), "+f"(c[2]), "+f"(c[3])
                 : "r"(a[0]), "r"(a[1]), "r"(a[2]), "r"(a[3]), "r"(b[0]), "r"(b[1]));
}

template<int EPI>
__global__ __launch_bounds__(256) void gemm16(const __half* __restrict__ A,
                                              const __half* __restrict__ Bt,
                                              __half* __restrict__ C16, int M,
                                              const float* __restrict__ bias,
                                              float* __restrict__ featf,
                                              __half* __restrict__ feat16) {
    __shared__ __half As[2][128][40];   // [m][k] chunk, +8 halfs pad
    __shared__ __half Bs[2][128][40];   // [n][k] chunk, +8 halfs pad
    int tid = threadIdx.x;
    int lane = tid & 31, wid = tid >> 5;
    int wm = wid & 3, wn = wid >> 2;
    int g = lane >> 2, q = lane & 3;
    long m0 = (long)blockIdx.x * 128;

    float acc[2][8][4];
    #pragma unroll
    for (int mt = 0; mt < 2; mt++)
        #pragma unroll
        for (int nt = 0; nt < 8; nt++)
            #pragma unroll
            for (int i = 0; i < 4; i++) acc[mt][nt][i] = 0.f;

    // staging coords: 512 16B-vectors per operand chunk, 2 per thread
    int vr[2], vk[2];
    #pragma unroll
    for (int i = 0; i < 2; i++) {
        int v = tid + 256 * i;
        vr[i] = v >> 2;            // row (A) / n (B)
        vk[i] = (v & 3) * 8;       // k offset in halfs
    }

    auto prefetch = [&](int kc, int s) {
        #pragma unroll
        for (int i = 0; i < 2; i++) {
            long row = m0 + vr[i];
            uint32_t sa = (uint32_t)__cvta_generic_to_shared(&As[s][vr[i]][vk[i]]);
            cp_async16(sa, A + row * 128 + kc * 32 + vk[i], row < M);
            uint32_t sb = (uint32_t)__cvta_generic_to_shared(&Bs[s][vr[i]][vk[i]]);
            cp_async16(sb, Bt + vr[i] * 128 + kc * 32 + vk[i], true);
        }
        asm volatile("cp.async.commit_group;");
    };

    prefetch(0, 0);

    for (int kc = 0; kc < 4; kc++) {
        if (kc < 3) {
            prefetch(kc + 1, (kc + 1) & 1);
            asm volatile("cp.async.wait_group 1;");
        } else {
            asm volatile("cp.async.wait_group 0;");
        }
        __syncthreads();
        int s = kc & 1;

        #pragma unroll
        for (int ks = 0; ks < 2; ks++) {
            int kk = ks * 16;
            uint32_t a[2][4], b[8][2];
            #pragma unroll
            for (int mt = 0; mt < 2; mt++) {
                int row = wm * 32 + mt * 16 + g;
                a[mt][0] = *reinterpret_cast<const uint32_t*>(&As[s][row][kk + 2*q]);
                a[mt][1] = *reinterpret_cast<const uint32_t*>(&As[s][row + 8][kk + 2*q]);
                a[mt][2] = *reinterpret_cast<const uint32_t*>(&As[s][row][kk + 2*q + 8]);
                a[mt][3] = *reinterpret_cast<const uint32_t*>(&As[s][row + 8][kk + 2*q + 8]);
            }
            #pragma unroll
            for (int nt = 0; nt < 8; nt++) {
                int col = wn * 64 + nt * 8 + g;
                b[nt][0] = *reinterpret_cast<const uint32_t*>(&Bs[s][col][kk + 2*q]);
                b[nt][1] = *reinterpret_cast<const uint32_t*>(&Bs[s][col][kk + 2*q + 8]);
            }
            #pragma unroll
            for (int mt = 0; mt < 2; mt++)
                #pragma unroll
                for (int nt = 0; nt < 8; nt++)
                    mma_f16(acc[mt][nt], a[mt], b[nt]);
        }
        __syncthreads();
    }

    #pragma unroll
    for (int mt = 0; mt < 2; mt++) {
        #pragma unroll
        for (int h = 0; h < 2; h++) {
            long row = m0 + wm * 32 + mt * 16 + g + h * 8;
            if (row >= M) continue;
            #pragma unroll
            for (int nt = 0; nt < 8; nt++) {
                int col = wn * 64 + nt * 8 + q * 2;
                long base = row * 128 + col;
                float v0 = acc[mt][nt][h * 2], v1 = acc[mt][nt][h * 2 + 1];
                if (EPI == 0) {
                    *reinterpret_cast<__half2*>(&C16[base]) = __floats2half2_rn(v0, v1);
                } else {
                    float2 prev = *reinterpret_cast<const float2*>(&featf[base]);
                    float n0 = prev.x + v0 + bias[col];
                    float n1 = prev.y + v1 + bias[col + 1];
                    *reinterpret_cast<float2*>(&featf[base]) = make_float2(n0, n1);
                    *reinterpret_cast<__half2*>(&feat16[base]) = __floats2half2_rn(n0, n1);
                }
            }
        }
    }
}

// -------- tf32 GEMM (f32 inputs) for the tiny wqa/wka products; stores fp16 TRANSPOSED --------

#define GSTAGE_A (128*36)
#define GSTAGE_B (32*136)
#define GSTAGE   (GSTAGE_A + GSTAGE_B)
#define GEMM_SMEM_BYTES (2*GSTAGE*4)

__device__ __forceinline__ void mma_tf32(float* c, const uint32_t* a, const uint32_t* b) {
    asm volatile("mma.sync.aligned.m16n8k8.row.col.f32.tf32.tf32.f32 "
                 "{%0,%1,%2,%3}, {%4,%5,%6,%7}, {%8,%9}, {%0,%1,%2,%3};"
                 : "+f"(c[0]), "+f"(c[1]), "+f"(c[2]), "+f"(c[3])
                 : "r"(a[0]), "r"(a[1]), "r"(a[2]), "r"(a[3]), "r"(b[0]), "r"(b[1]));
}

__global__ __launch_bounds__(256) void gemm_w_tr(const float* __restrict__ A,
                                                 const float* __restrict__ B,
                                                 __half* __restrict__ C16t, int M) {
    extern __shared__ float smf[];
    int tid = threadIdx.x;
    int lane = tid & 31, wid = tid >> 5;
    int wm = wid & 3, wn = wid >> 2;
    int g = lane >> 2, q = lane & 3;
    long m0 = (long)blockIdx.x * 128;

    float acc[2][8][4];
    #pragma unroll
    for (int mt = 0; mt < 2; mt++)
        #pragma unroll
        for (int nt = 0; nt < 8; nt++)
            #pragma unroll
            for (int i = 0; i < 4; i++) acc[mt][nt][i] = 0.f;

    int ar[4], ac_[4], br[4], bc[4];
    #pragma unroll
    for (int i = 0; i < 4; i++) {
        int idx = (tid + 256 * i) * 4;
        ar[i] = idx >> 5; ac_[i] = idx & 31;
        br[i] = idx >> 7; bc[i] = idx & 127;
    }

    auto prefetch = [&](int kc, int s) {
        float* As = smf + s * GSTAGE;
        float* Bs = As + GSTAGE_A;
        #pragma unroll
        for (int i = 0; i < 4; i++) {
            long row = m0 + ar[i];
            uint32_t sa = (uint32_t)__cvta_generic_to_shared(&As[ar[i]*36 + ac_[i]]);
            cp_async16(sa, A + row * 128 + kc * 32 + ac_[i], row < M);
        }
        #pragma unroll
        for (int i = 0; i < 4; i++) {
            uint32_t sb = (uint32_t)__cvta_generic_to_shared(&Bs[br[i]*136 + bc[i]]);
            cp_async16(sb, B + (kc * 32 + br[i]) * 128 + bc[i], true);
        }
        asm volatile("cp.async.commit_group;");
    };

    prefetch(0, 0);
    for (int kc = 0; kc < 4; kc++) {
        if (kc < 3) {
            prefetch(kc + 1, (kc + 1) & 1);
            asm volatile("cp.async.wait_group 1;");
        } else {
            asm volatile("cp.async.wait_group 0;");
        }
        __syncthreads();
        const uint32_t* As = reinterpret_cast<const uint32_t*>(smf + (kc & 1) * GSTAGE);
        const uint32_t* Bs = As + GSTAGE_A;
        #pragma unroll
        for (int ks = 0; ks < 4; ks++) {
            int kc8 = ks * 8;
            uint32_t a[2][4], b[8][2];
            #pragma unroll
            for (int mt = 0; mt < 2; mt++) {
                int row = wm * 32 + mt * 16 + g;
                a[mt][0] = As[row*36 + kc8 + q];
                a[mt][1] = As[(row+8)*36 + kc8 + q];
                a[mt][2] = As[row*36 + kc8 + q + 4];
                a[mt][3] = As[(row+8)*36 + kc8 + q + 4];
            }
            #pragma unroll
            for (int nt = 0; nt < 8; nt++) {
                int col = wn * 64 + nt * 8 + g;
                b[nt][0] = Bs[(kc8 + q)*136 + col];
                b[nt][1] = Bs[(kc8 + q + 4)*136 + col];
            }
            #pragma unroll
            for (int mt = 0; mt < 2; mt++)
                #pragma unroll
                for (int nt = 0; nt < 8; nt++)
                    mma_tf32(acc[mt][nt], a[mt], b[nt]);
        }
        __syncthreads();
    }

    #pragma unroll
    for (int mt = 0; mt < 2; mt++) {
        #pragma unroll
        for (int h = 0; h < 2; h++) {
            long row = m0 + wm * 32 + mt * 16 + g + h * 8;
            if (row >= M) continue;
            #pragma unroll
            for (int nt = 0; nt < 8; nt++) {
                int col = wn * 64 + nt * 8 + q * 2;
                // transposed fp16 store: C16t[n][k] = C[k=row? no: C16t[col][row]]
                C16t[(long)col * 128 + row]       = __float2half(acc[mt][nt][h*2]);
                C16t[(long)(col + 1) * 128 + row] = __float2half(acc[mt][nt][h*2+1]);
            }
        }
    }
}

// -------- BN / softmax kernels (fp16 data) --------

__global__ void bn_stats_k(const __half* __restrict__ h, float* __restrict__ colsum,
                           float* __restrict__ colsq) {
    __shared__ float ssum[128], ssq[128];
    int tid = threadIdx.x;
    if (tid < 128) { ssum[tid] = 0.f; ssq[tid] = 0.f; }
    __syncthreads();
    int c4 = tid & 31;
    int rstep = gridDim.x * 8;
    const uint2* h4 = reinterpret_cast<const uint2*>(h);
    float4 s = make_float4(0,0,0,0), s2 = make_float4(0,0,0,0);
    for (int r = blockIdx.x * 8 + (tid >> 5); r < NN; r += rstep) {
        float4 x; h4_to_f4(h4[(long)r * 32 + c4], x);
        s.x += x.x; s.y += x.y; s.z += x.z; s.w += x.w;
        s2.x += x.x*x.x; s2.y += x.y*x.y; s2.z += x.z*x.z; s2.w += x.w*x.w;
    }
    atomicAdd(&ssum[c4*4+0], s.x);  atomicAdd(&ssq[c4*4+0], s2.x);
    atomicAdd(&ssum[c4*4+1], s.y);  atomicAdd(&ssq[c4*4+1], s2.y);
    atomicAdd(&ssum[c4*4+2], s.z);  atomicAdd(&ssq[c4*4+2], s2.z);
    atomicAdd(&ssum[c4*4+3], s.w);  atomicAdd(&ssq[c4*4+3], s2.w);
    __syncthreads();
    if (tid < 128) {
        atomicAdd(&colsum[tid], ssum[tid]);
        atomicAdd(&colsq[tid], ssq[tid]);
    }
}

__global__ void bn_apply_relu_k(__half* __restrict__ h, const float* __restrict__ gamma,
                                const float* __restrict__ beta,
                                const float* __restrict__ colsum,
                                const float* __restrict__ colsq) {
    __shared__ float sm_mean[128], sm_scale[128], sm_beta[128];
    int tid = threadIdx.x;
    if (tid < 128) {
        const float invN = 1.f / (float)NN;
        float mean = colsum[tid] * invN;
        float var  = colsq[tid] * invN - mean * mean;
        sm_mean[tid] = mean;
        sm_scale[tid] = rsqrtf(var + 1e-5f) * gamma[tid];
        sm_beta[tid] = beta[tid];
    }
    __syncthreads();
    int idx = blockIdx.x * blockDim.x + tid;
    if (idx >= ND4) return;
    int c = (idx & 31) * 4;
    uint2* h4 = reinterpret_cast<uint2*>(h);
    float4 x; h4_to_f4(h4[idx], x);
    float4 o;
    o.x = fmaxf((x.x - sm_mean[c+0]) * sm_scale[c+0] + sm_beta[c+0], 0.f);
    o.y = fmaxf((x.y - sm_mean[c+1]) * sm_scale[c+1] + sm_beta[c+1], 0.f);
    o.z = fmaxf((x.z - sm_mean[c+2]) * sm_scale[c+2] + sm_beta[c+2], 0.f);
    o.w = fmaxf((x.w - sm_mean[c+3]) * sm_scale[c+3] + sm_beta[c+3], 0.f);
    h4[idx] = f4_to_h4(o);
}

__global__ void attn_combine_k(const __half* __restrict__ qa, const __half* __restrict__ ska,
                               const __half* __restrict__ vv, __half* __restrict__ o) {
    int idx = blockIdx.x * blockDim.x + threadIdx.x;
    if (idx >= ND4) return;
    const uint2* qa4 = reinterpret_cast<const uint2*>(qa);
    const uint2* sk4 = reinterpret_cast<const uint2*>(ska);
    const uint2* vv4 = reinterpret_cast<const uint2*>(vv);
    float4 q, s0, s1, s2, v0, v1, v2;
    h4_to_f4(qa4[idx], q);
    h4_to_f4(sk4[idx], s0); h4_to_f4(sk4[idx + ND4], s1); h4_to_f4(sk4[idx + 2*ND4], s2);
    h4_to_f4(vv4[idx], v0); h4_to_f4(vv4[idx + ND4], v1); h4_to_f4(vv4[idx + 2*ND4], v2);
    float4 r;
    const float* pq = &q.x; const float* p0 = &s0.x; const float* p1 = &s1.x;
    const float* p2 = &s2.x; const float* w0 = &v0.x; const float* w1 = &v1.x;
    const float* w2 = &v2.x; float* pr = &r.x;
    #pragma unroll
    for (int j = 0; j < 4; j++) {
        float l0 = pq[j] - p0[j], l1 = pq[j] - p1[j], l2 = pq[j] - p2[j];
        float m = fmaxf(l0, fmaxf(l1, l2));
        float e0 = __expf(l0 - m), e1 = __expf(l1 - m), e2 = __expf(l2 - m);
        pr[j] = (e0 * w0[j] + e1 * w1[j] + e2 * w2[j]) / (e0 + e1 + e2);
    }
    reinterpret_cast<uint2*>(o)[idx] = f4_to_h4(r);
}

// -------- host --------

extern "C" void kernel_launch(void* const* d_in, const int* in_sizes, int n_in,
                              void* d_out, int out_size) {
    const float* e_emb = (const float*)d_in[1];
    const int* node_ind = (const int*)d_in[26];
    const int* edge_src = (const int*)d_in[27];
    const int* edge_dst = (const int*)d_in[28];

    float *feat, *inv, *gscale, *colsum, *colsq;
    __half *feat16, *t1h, *t2h, *keyh, *skah, *vh, *qah, *t2ch, *w16, *wqa16, *wka16;
    int *cnt, *offs, *fill, *partial, *ssrc;
    cudaGetSymbolAddress((void**)&feat, g_feat);
    cudaGetSymbolAddress((void**)&feat16, g_feat16);
    cudaGetSymbolAddress((void**)&t1h, g_t1h);
    cudaGetSymbolAddress((void**)&t2h, g_t2h);
    cudaGetSymbolAddress((void**)&keyh, g_keyh);
    cudaGetSymbolAddress((void**)&skah, g_skah);
    cudaGetSymbolAddress((void**)&vh, g_vh);
    cudaGetSymbolAddress((void**)&qah, g_qah);
    cudaGetSymbolAddress((void**)&t2ch, g_t2ch);
    cudaGetSymbolAddress((void**)&w16, g_w16);
    cudaGetSymbolAddress((void**)&wqa16, g_wqa16);
    cudaGetSymbolAddress((void**)&wka16, g_wka16);
    cudaGetSymbolAddress((void**)&cnt, g_cnt);
    cudaGetSymbolAddress((void**)&offs, g_offs);
    cudaGetSymbolAddress((void**)&fill, g_fill);
    cudaGetSymbolAddress((void**)&partial, g_partial);
    cudaGetSymbolAddress((void**)&ssrc, g_ssrc);
    cudaGetSymbolAddress((void**)&inv, g_inv);
    cudaGetSymbolAddress((void**)&gscale, g_gscale);
    cudaGetSymbolAddress((void**)&colsum, g_colsum);
    cudaGetSymbolAddress((void**)&colsq, g_colsq);

    cudaFuncSetAttribute(gemm_w_tr, cudaFuncAttributeMaxDynamicSharedMemorySize, GEMM_SMEM_BYTES);

    const int TPB = 256;
    const int ND4_BLK = (ND4 + TPB - 1) / TPB;
    const int E_BLK = (TT*EE + TPB - 1) / TPB;
    const int GCNW_BLK = (NN*32 + TPB - 1) / TPB;
    const int ATTW_BLK = (TNN*32 + TPB - 1) / TPB;
    const int G1 = (NN + 127) / 128;
    const int G3 = (TNN + 127) / 128;
    const int W_BLK = (DD*DD + TPB - 1) / TPB;

    // weight pointers (layer-major): w1, w2, wv, wp
    const float* wsrc[8] = {
        (const float*)d_in[2],  (const float*)d_in[5],  (const float*)d_in[9],  (const float*)d_in[12],
        (const float*)d_in[14], (const float*)d_in[17], (const float*)d_in[21], (const float*)d_in[24]};
    for (int i = 0; i < 8; i++)
        convert_wt_k<<<W_BLK, TPB>>>(wsrc[i], w16 + (size_t)i * DD * DD);

    // ---- CSR build ----
    cudaMemsetAsync(cnt, 0, TNN*sizeof(int), 0);
    cudaMemsetAsync(fill, 0, TNN*sizeof(int), 0);
    count_k<<<E_BLK, TPB>>>(edge_dst, cnt);
    prep_k<<<(NN + TPB - 1)/TPB, TPB>>>(cnt, inv, gscale);
    scan_block_k<<<NB_SCAN, 256>>>(cnt, offs, partial);
    scan_partial_k<<<1, 256>>>(partial);
    scan_add_k<<<NB_SCAN, 256>>>(offs, partial);
    scatter_k<<<E_BLK, TPB>>>(edge_src, edge_dst, offs, fill, ssrc);
    gather_feat_k<<<ND4_BLK, TPB>>>((const float*)d_in[0], node_ind, feat, feat16);

    const float* gcn_gamma[2] = {(const float*)d_in[3],  (const float*)d_in[15]};
    const float* gcn_beta[2]  = {(const float*)d_in[4],  (const float*)d_in[16]};
    const float* gcn_b2[2]    = {(const float*)d_in[6],  (const float*)d_in[18]};
    const float* at_wq[2]     = {(const float*)d_in[7],  (const float*)d_in[19]};
    const float* at_wk[2]     = {(const float*)d_in[8],  (const float*)d_in[20]};
    const float* at_wa[2]     = {(const float*)d_in[10], (const float*)d_in[22]};
    const float* at_bp[2]     = {(const float*)d_in[13], (const float*)d_in[25]};

    for (int L = 0; L < 2; L++) {
        const __half* w1t = w16 + (size_t)(L*4 + 0) * DD * DD;
        const __half* w2t = w16 + (size_t)(L*4 + 1) * DD * DD;
        const __half* wvt = w16 + (size_t)(L*4 + 2) * DD * DD;
        const __half* wpt = w16 + (size_t)(L*4 + 3) * DD * DD;

        // ---- GCN layer ----
        gcn_edge_sorted<<<GCNW_BLK, TPB>>>(feat16, e_emb, ssrc, offs, cnt, inv, gscale, t1h);
        gemm16<0><<<G1, 256>>>(t1h, w1t, t2h, NN, nullptr, nullptr, nullptr);
        cudaMemsetAsync(colsum, 0, DD*sizeof(float), 0);
        cudaMemsetAsync(colsq, 0, DD*sizeof(float), 0);
        bn_stats_k<<<1024, 256>>>(t2h, colsum, colsq);
        bn_apply_relu_k<<<ND4_BLK, TPB>>>(t2h, gcn_gamma[L], gcn_beta[L], colsum, colsq);
        gemm16<1><<<G1, 256>>>(t2h, w2t, nullptr, NN, gcn_b2[L], feat, feat16);

        // ---- Attention layer ----
        gemm_w_tr<<<1, 256, GEMM_SMEM_BYTES>>>(at_wq[L], at_wa[L], wqa16, 128);
        gemm_w_tr<<<1, 256, GEMM_SMEM_BYTES>>>(at_wk[L], at_wa[L], wka16, 128);
        attn_edge_sorted<<<ATTW_BLK, TPB>>>(feat16, e_emb, ssrc, offs, cnt, inv, keyh);
        gemm16<0><<<G1, 256>>>(feat16, wqa16, qah, NN, nullptr, nullptr, nullptr);
        gemm16<0><<<G3, 256>>>(keyh, wka16, skah, TNN, nullptr, nullptr, nullptr);
        gemm16<0><<<G3, 256>>>(keyh, wvt, vh, TNN, nullptr, nullptr, nullptr);
        attn_combine_k<<<ND4_BLK, TPB>>>(qah, skah, vh, t2ch);
        gemm16<1><<<G1, 256>>>(t2ch, wpt, nullptr, NN, at_bp[L], feat, feat16);
    }

    cudaMemcpyAsync(d_out, feat, (size_t)ND*sizeof(float), cudaMemcpyDeviceToDevice, 0);
    if (out_size >= ND + TT*DD) {
        cudaMemcpyAsync((float*)d_out + ND, e_emb, TT*DD*sizeof(float),
                        cudaMemcpyDeviceToDevice, 0);
    }
}

// round 12
// speedup vs baseline: 1.3846x; 1.0022x over previous
#include <cuda_runtime.h>
#include <cuda_fp16.h>
#include <cstdint>
#include <math.h>

#define NN 100000
#define DD 128
#define EE 250000
#define TT 3
#define ND (NN*DD)
#define ND4 (ND/4)
#define TNN (TT*NN)
#define NB_SCAN ((TNN + 255) / 256)
#define SCHUNK ((NB_SCAN + 255) / 256)

// -------- scratch --------
__device__ float  g_feat[ND];
__device__ __half g_feat16[ND];
__device__ __half g_t1h[ND];
__device__ __half g_t2h[ND];
__device__ __half g_keyh[3*ND];
__device__ __half g_skah[3*ND];
__device__ __half g_vh[3*ND];
__device__ __half g_t2ch[ND];
__device__ __half g_w16[8][DD*DD];
__device__ __half g_wqa16[DD*DD];
__device__ __half g_wka16[DD*DD];
__device__ int    g_cnt[TNN];
__device__ int    g_offs[TNN];
__device__ int    g_fill[TNN];
__device__ int    g_partial[NB_SCAN];
__device__ int    g_ssrc[TT*EE];
__device__ float  g_inv[TNN];
__device__ float  g_gscale[NN];
__device__ float  g_colsum[DD];
__device__ float  g_colsq[DD];

// -------- setup kernels --------

__global__ void gather_feat_k(const float* __restrict__ n_emb, const int* __restrict__ ind,
                              float* __restrict__ feat, __half* __restrict__ feat16) {
    int idx = blockIdx.x * blockDim.x + threadIdx.x;
    if (idx >= ND4) return;
    int n = idx >> 5;
    float4 v = reinterpret_cast<const float4*>(n_emb)[(long)ind[n] * 32 + (idx & 31)];
    reinterpret_cast<float4*>(feat)[idx] = v;
    __half2* h = reinterpret_cast<__half2*>(feat16) + idx * 2;
    h[0] = __floats2half2_rn(v.x, v.y);
    h[1] = __floats2half2_rn(v.z, v.w);
}

// all 8 weight transposes in one launch
__global__ void convert_wt8_k(const float* w0, const float* w1, const float* w2, const float* w3,
                              const float* w4, const float* w5, const float* w6, const float* w7,
                              __half* __restrict__ wt) {
    int i = blockIdx.x * blockDim.x + threadIdx.x;
    if (i >= 8*DD*DD) return;
    const float* ws[8] = {w0, w1, w2, w3, w4, w5, w6, w7};
    int m = i >> 14;               // which matrix
    int j = i & (DD*DD - 1);
    int n = j >> 7, k = j & 127;
    wt[(size_t)m * DD * DD + n * 128 + k] = __float2half(ws[m][k * 128 + n]);
}

__global__ void count_k(const int* __restrict__ dst, int* __restrict__ cnt) {
    int e = blockIdx.x * blockDim.x + threadIdx.x;
    if (e >= TT*EE) return;
    int t = e / EE;
    atomicAdd(&cnt[t * NN + dst[e]], 1);
}

__global__ void prep_k(const int* __restrict__ cnt, float* __restrict__ inv,
                       float* __restrict__ gscale) {
    int n = blockIdx.x * blockDim.x + threadIdx.x;
    if (n >= NN) return;
    int c0 = cnt[n], c1 = cnt[NN + n], c2 = cnt[2*NN + n];
    inv[n]        = 1.f / (float)max(c0, 1);
    inv[NN + n]   = 1.f / (float)max(c1, 1);
    inv[2*NN + n] = 1.f / (float)max(c2, 1);
    gscale[n] = (float)((c0 > 0) + (c1 > 0) + (c2 > 0));
}

__global__ void scan_block_k(const int* __restrict__ cnt, int* __restrict__ offs,
                             int* __restrict__ partial) {
    __shared__ int sh[256];
    int tid = threadIdx.x;
    int i = blockIdx.x * 256 + tid;
    int v = (i < TNN) ? cnt[i] : 0;
    sh[tid] = v; __syncthreads();
    #pragma unroll
    for (int off = 1; off < 256; off <<= 1) {
        int x = (tid >= off) ? sh[tid - off] : 0;
        __syncthreads();
        sh[tid] += x;
        __syncthreads();
    }
    if (i < TNN) offs[i] = sh[tid] - v;
    if (tid == 255) partial[blockIdx.x] = sh[tid];
}

__global__ void scan_partial_k(int* __restrict__ partial) {
    __shared__ int sh[256];
    int tid = threadIdx.x;
    int base = tid * SCHUNK;
    int loc[SCHUNK];
    int s = 0;
    #pragma unroll
    for (int j = 0; j < SCHUNK; j++) {
        int idx = base + j;
        int v = (idx < NB_SCAN) ? partial[idx] : 0;
        loc[j] = s; s += v;
    }
    sh[tid] = s; __syncthreads();
    #pragma unroll
    for (int off = 1; off < 256; off <<= 1) {
        int x = (tid >= off) ? sh[tid - off] : 0;
        __syncthreads();
        sh[tid] += x;
        __syncthreads();
    }
    int excl = sh[tid] - s;
    #pragma unroll
    for (int j = 0; j < SCHUNK; j++) {
        int idx = base + j;
        if (idx < NB_SCAN) partial[idx] = excl + loc[j];
    }
}

__global__ void scan_add_k(int* __restrict__ offs, const int* __restrict__ partial) {
    int i = blockIdx.x * 256 + threadIdx.x;
    if (i < TNN) offs[i] += partial[blockIdx.x];
}

__global__ void scatter_k(const int* __restrict__ src, const int* __restrict__ dst,
                          const int* __restrict__ offs, int* __restrict__ fill,
                          int* __restrict__ ssrc) {
    int e = blockIdx.x * blockDim.x + threadIdx.x;
    if (e >= TT*EE) return;
    int t = e / EE;
    int td = t * NN + dst[e];
    int pos = offs[td] + atomicAdd(&fill[td], 1);
    ssrc[pos] = src[e];
}

// -------- fp16 helpers --------

__device__ __forceinline__ void h4_to_f4(uint2 u, float4& f) {
    __half2 h0 = *reinterpret_cast<__half2*>(&u.x);
    __half2 h1 = *reinterpret_cast<__half2*>(&u.y);
    float2 a = __half22float2(h0), b = __half22float2(h1);
    f.x = a.x; f.y = a.y; f.z = b.x; f.w = b.y;
}

__device__ __forceinline__ uint2 f4_to_h4(float4 f) {
    __half2 h0 = __floats2half2_rn(f.x, f.y);
    __half2 h1 = __floats2half2_rn(f.z, f.w);
    uint2 u;
    u.x = *reinterpret_cast<uint32_t*>(&h0);
    u.y = *reinterpret_cast<uint32_t*>(&h1);
    return u;
}

// -------- sorted edge passes --------

__global__ void gcn_edge_sorted(const __half* __restrict__ feat16, const float* __restrict__ emb,
                                const int* __restrict__ ssrc, const int* __restrict__ offs,
                                const int* __restrict__ cnt, const float* __restrict__ inv,
                                const float* __restrict__ gscale, __half* __restrict__ out) {
    int gw = (blockIdx.x * blockDim.x + threadIdx.x) >> 5;
    int lane = threadIdx.x & 31;
    if (gw >= NN) return;
    const uint2* f16 = reinterpret_cast<const uint2*>(feat16);
    float4 a; h4_to_f4(f16[gw * 32 + lane], a);
    float gs = gscale[gw];
    float4 acc = make_float4(a.x * gs, a.y * gs, a.z * gs, a.w * gs);
    #pragma unroll
    for (int t = 0; t < TT; t++) {
        int td = t * NN + gw;
        int len = cnt[td];
        if (len == 0) continue;
        int beg = offs[td];
        float4 s = make_float4(0.f, 0.f, 0.f, 0.f);
        for (int i = 0; i < len; i++) {
            int sn = ssrc[beg + i];
            float4 f; h4_to_f4(f16[sn * 32 + lane], f);
            s.x += f.x; s.y += f.y; s.z += f.z; s.w += f.w;
        }
        float4 e = reinterpret_cast<const float4*>(emb)[t * 32 + lane];
        float w = inv[td];
        acc.x -= s.x * e.x * w; acc.y -= s.y * e.y * w;
        acc.z -= s.z * e.z * w; acc.w -= s.w * e.w * w;
    }
    reinterpret_cast<uint2*>(out)[gw * 32 + lane] = f4_to_h4(acc);
}

__global__ void attn_edge_sorted(const __half* __restrict__ feat16, const float* __restrict__ emb,
                                 const int* __restrict__ ssrc, const int* __restrict__ offs,
                                 const int* __restrict__ cnt, const float* __restrict__ inv,
                                 __half* __restrict__ key) {
    int gw = (blockIdx.x * blockDim.x + threadIdx.x) >> 5;
    int lane = threadIdx.x & 31;
    if (gw >= TNN) return;
    int t = gw / NN;
    int len = cnt[gw];
    int beg = offs[gw];
    const uint2* f16 = reinterpret_cast<const uint2*>(feat16);
    float4 s = make_float4(0.f, 0.f, 0.f, 0.f);
    for (int i = 0; i < len; i++) {
        int sn = ssrc[beg + i];
        float4 f; h4_to_f4(f16[sn * 32 + lane], f);
        s.x += f.x; s.y += f.y; s.z += f.z; s.w += f.w;
    }
    float4 e = reinterpret_cast<const float4*>(emb)[t * 32 + lane];
    float w = inv[gw];
    reinterpret_cast<uint2*>(key)[(long)gw * 32 + lane] =
        f4_to_h4(make_float4(s.x*e.x*w, s.y*e.y*w, s.z*e.z*w, s.w*e.w*w));
}

// -------- fp16 tensor-core GEMM --------
// EPI 0: store fp16 C. EPI 1: featf += acc + bias and refresh feat16.
// EPI 2: softmax-combine (acc = qa) with ska/vv → store fp16 C.

__device__ __forceinline__ void cp_async16(uint32_t saddr, const void* gptr, bool pred) {
    int sz = pred ? 16 : 0;
    asm volatile("cp.async.ca.shared.global [%0], [%1], 16, %2;"
                 :: "r"(saddr), "l"(gptr), "r"(sz));
}

__device__ __forceinline__ void mma_f16(float* c, const uint32_t* a, const uint32_t* b) {
    asm volatile("mma.sync.aligned.m16n8k16.row.col.f32.f16.f16.f32 "
                 "{%0,%1,%2,%3}, {%4,%5,%6,%7}, {%8,%9}, {%0,%1,%2,%3};"
                 : "+f"(c[0]), "+f"(c[1]), "+f"(c[2]), "+f"(c[3])
                 : "r"(a[0]), "r"(a[1]), "r"(a[2]), "r"(a[3]), "r"(b[0]), "r"(b[1]));
}

template<int EPI>
__global__ __launch_bounds__(256) void gemm16(const __half* __restrict__ A,
                                              const __half* __restrict__ Bt,
                                              __half* __restrict__ C16, int M,
                                              const float* __restrict__ bias,
                                              float* __restrict__ featf,
                                              __half* __restrict__ feat16,
                                              const __half* __restrict__ ska,
                                              const __half* __restrict__ vv) {
    __shared__ __half As[2][128][40];
    __shared__ __half Bs[2][128][40];
    int tid = threadIdx.x;
    int lane = tid & 31, wid = tid >> 5;
    int wm = wid & 3, wn = wid >> 2;
    int g = lane >> 2, q = lane & 3;
    long m0 = (long)blockIdx.x * 128;

    float acc[2][8][4];
    #pragma unroll
    for (int mt = 0; mt < 2; mt++)
        #pragma unroll
        for (int nt = 0; nt < 8; nt++)
            #pragma unroll
            for (int i = 0; i < 4; i++) acc[mt][nt][i] = 0.f;

    int vr[2], vk[2];
    #pragma unroll
    for (int i = 0; i < 2; i++) {
        int v = tid + 256 * i;
        vr[i] = v >> 2;
        vk[i] = (v & 3) * 8;
    }

    auto prefetch = [&](int kc, int s) {
        #pragma unroll
        for (int i = 0; i < 2; i++) {
            long row = m0 + vr[i];
            uint32_t sa = (uint32_t)__cvta_generic_to_shared(&As[s][vr[i]][vk[i]]);
            cp_async16(sa, A + row * 128 + kc * 32 + vk[i], row < M);
            uint32_t sb = (uint32_t)__cvta_generic_to_shared(&Bs[s][vr[i]][vk[i]]);
            cp_async16(sb, Bt + vr[i] * 128 + kc * 32 + vk[i], true);
        }
        asm volatile("cp.async.commit_group;");
    };

    prefetch(0, 0);
    for (int kc = 0; kc < 4; kc++) {
        if (kc < 3) {
            prefetch(kc + 1, (kc + 1) & 1);
            asm volatile("cp.async.wait_group 1;");
        } else {
            asm volatile("cp.async.wait_group 0;");
        }
        __syncthreads();
        int s = kc & 1;
        #pragma unroll
        for (int ks = 0; ks < 2; ks++) {
            int kk = ks * 16;
            uint32_t a[2][4], b[8][2];
            #pragma unroll
            for (int mt = 0; mt < 2; mt++) {
                int row = wm * 32 + mt * 16 + g;
                a[mt][0] = *reinterpret_cast<const uint32_t*>(&As[s][row][kk + 2*q]);
                a[mt][1] = *reinterpret_cast<const uint32_t*>(&As[s][row + 8][kk + 2*q]);
                a[mt][2] = *reinterpret_cast<const uint32_t*>(&As[s][row][kk + 2*q + 8]);
                a[mt][3] = *reinterpret_cast<const uint32_t*>(&As[s][row + 8][kk + 2*q + 8]);
            }
            #pragma unroll
            for (int nt = 0; nt < 8; nt++) {
                int col = wn * 64 + nt * 8 + g;
                b[nt][0] = *reinterpret_cast<const uint32_t*>(&Bs[s][col][kk + 2*q]);
                b[nt][1] = *reinterpret_cast<const uint32_t*>(&Bs[s][col][kk + 2*q + 8]);
            }
            #pragma unroll
            for (int mt = 0; mt < 2; mt++)
                #pragma unroll
                for (int nt = 0; nt < 8; nt++)
                    mma_f16(acc[mt][nt], a[mt], b[nt]);
        }
        __syncthreads();
    }

    #pragma unroll
    for (int mt = 0; mt < 2; mt++) {
        #pragma unroll
        for (int h = 0; h < 2; h++) {
            long row = m0 + wm * 32 + mt * 16 + g + h * 8;
            if (row >= M) continue;
            #pragma unroll
            for (int nt = 0; nt < 8; nt++) {
                int col = wn * 64 + nt * 8 + q * 2;
                long base = row * 128 + col;
                float v0 = acc[mt][nt][h * 2], v1 = acc[mt][nt][h * 2 + 1];
                if (EPI == 0) {
                    *reinterpret_cast<__half2*>(&C16[base]) = __floats2half2_rn(v0, v1);
                } else if (EPI == 1) {
                    float2 prev = *reinterpret_cast<const float2*>(&featf[base]);
                    float n0 = prev.x + v0 + bias[col];
                    float n1 = prev.y + v1 + bias[col + 1];
                    *reinterpret_cast<float2*>(&featf[base]) = make_float2(n0, n1);
                    *reinterpret_cast<__half2*>(&feat16[base]) = __floats2half2_rn(n0, n1);
                } else { // EPI == 2: softmax combine, acc = qa
                    float2 s0 = __half22float2(*reinterpret_cast<const __half2*>(ska + base));
                    float2 s1 = __half22float2(*reinterpret_cast<const __half2*>(ska + base + (long)ND));
                    float2 s2 = __half22float2(*reinterpret_cast<const __half2*>(ska + base + 2L*ND));
                    float2 w0 = __half22float2(*reinterpret_cast<const __half2*>(vv + base));
                    float2 w1 = __half22float2(*reinterpret_cast<const __half2*>(vv + base + (long)ND));
                    float2 w2 = __half22float2(*reinterpret_cast<const __half2*>(vv + base + 2L*ND));
                    float o0, o1;
                    {
                        float l0 = v0 - s0.x, l1 = v0 - s1.x, l2 = v0 - s2.x;
                        float mx = fmaxf(l0, fmaxf(l1, l2));
                        float e0 = __expf(l0-mx), e1 = __expf(l1-mx), e2 = __expf(l2-mx);
                        o0 = (e0*w0.x + e1*w1.x + e2*w2.x) / (e0 + e1 + e2);
                    }
                    {
                        float l0 = v1 - s0.y, l1 = v1 - s1.y, l2 = v1 - s2.y;
                        float mx = fmaxf(l0, fmaxf(l1, l2));
                        float e0 = __expf(l0-mx), e1 = __expf(l1-mx), e2 = __expf(l2-mx);
                        o1 = (e0*w0.y + e1*w1.y + e2*w2.y) / (e0 + e1 + e2);
                    }
                    *reinterpret_cast<__half2*>(&C16[base]) = __floats2half2_rn(o0, o1);
                }
            }
        }
    }
}

// Sequential-dual GEMM: C1 = A@B1t^T, C2 = A@B2t^T. A + both Bs staged in smem once;
// the two mainloops run back-to-back reusing the same 64 accumulator registers.
#define SEQ_SMEM_BYTES ((size_t)3 * 128 * 136 * 2)

__global__ __launch_bounds__(256) void gemm_seq2(const __half* __restrict__ A,
                                                 const __half* __restrict__ B1t,
                                                 const __half* __restrict__ B2t,
                                                 __half* __restrict__ C1,
                                                 __half* __restrict__ C2, int M) {
    extern __shared__ __half sh[];
    __half (*As)[136]  = reinterpret_cast<__half(*)[136]>(sh);
    __half (*Bs1)[136] = reinterpret_cast<__half(*)[136]>(sh + 128*136);
    __half (*Bs2)[136] = reinterpret_cast<__half(*)[136]>(sh + 2*128*136);
    int tid = threadIdx.x;
    int lane = tid & 31, wid = tid >> 5;
    int wm = wid & 3, wn = wid >> 2;
    int g = lane >> 2, q = lane & 3;
    long m0 = (long)blockIdx.x * 128;

    // stage A (2048 16B-vectors) + B1 + B2 (2048 each → 8 per thread each)
    #pragma unroll
    for (int i = 0; i < 8; i++) {
        int v = tid + 256 * i;
        int r = v >> 4, kv = (v & 15) * 8;
        long row = m0 + r;
        uint32_t sa = (uint32_t)__cvta_generic_to_shared(&As[r][kv]);
        cp_async16(sa, A + row * 128 + kv, row < M);
        uint32_t s1 = (uint32_t)__cvta_generic_to_shared(&Bs1[r][kv]);
        cp_async16(s1, B1t + r * 128 + kv, true);
        uint32_t s2 = (uint32_t)__cvta_generic_to_shared(&Bs2[r][kv]);
        cp_async16(s2, B2t + r * 128 + kv, true);
    }
    asm volatile("cp.async.commit_group;");
    asm volatile("cp.async.wait_group 0;");
    __syncthreads();

    #pragma unroll
    for (int pass = 0; pass < 2; pass++) {
        __half (*Bs)[136] = pass ? Bs2 : Bs1;
        __half* C = pass ? C2 : C1;
        float acc[2][8][4];
        #pragma unroll
        for (int mt = 0; mt < 2; mt++)
            #pragma unroll
            for (int nt = 0; nt < 8; nt++)
                #pragma unroll
                for (int i = 0; i < 4; i++) acc[mt][nt][i] = 0.f;

        #pragma unroll
        for (int ks = 0; ks < 8; ks++) {
            int kk = ks * 16;
            uint32_t a[2][4], b[8][2];
            #pragma unroll
            for (int mt = 0; mt < 2; mt++) {
                int row = wm * 32 + mt * 16 + g;
                a[mt][0] = *reinterpret_cast<const uint32_t*>(&As[row][kk + 2*q]);
                a[mt][1] = *reinterpret_cast<const uint32_t*>(&As[row + 8][kk + 2*q]);
                a[mt][2] = *reinterpret_cast<const uint32_t*>(&As[row][kk + 2*q + 8]);
                a[mt][3] = *reinterpret_cast<const uint32_t*>(&As[row + 8][kk + 2*q + 8]);
            }
            #pragma unroll
            for (int nt = 0; nt < 8; nt++) {
                int col = wn * 64 + nt * 8 + g;
                b[nt][0] = *reinterpret_cast<const uint32_t*>(&Bs[col][kk + 2*q]);
                b[nt][1] = *reinterpret_cast<const uint32_t*>(&Bs[col][kk + 2*q + 8]);
            }
            #pragma unroll
            for (int mt = 0; mt < 2; mt++)
                #pragma unroll
                for (int nt = 0; nt < 8; nt++)
                    mma_f16(acc[mt][nt], a[mt], b[nt]);
        }

        #pragma unroll
        for (int mt = 0; mt < 2; mt++)
            #pragma unroll
            for (int h = 0; h < 2; h++) {
                long row = m0 + wm * 32 + mt * 16 + g + h * 8;
                if (row >= M) continue;
                #pragma unroll
                for (int nt = 0; nt < 8; nt++) {
                    int col = wn * 64 + nt * 8 + q * 2;
                    *reinterpret_cast<__half2*>(&C[row * 128 + col]) =
                        __floats2half2_rn(acc[mt][nt][h*2], acc[mt][nt][h*2+1]);
                }
            }
    }
}

// -------- tf32 GEMM for tiny wqa/wka products; stores fp16 TRANSPOSED --------

#define GSTAGE_A (128*36)
#define GSTAGE_B (32*136)
#define GSTAGE   (GSTAGE_A + GSTAGE_B)
#define GEMM_SMEM_BYTES (2*GSTAGE*4)

__device__ __forceinline__ void mma_tf32(float* c, const uint32_t* a, const uint32_t* b) {
    asm volatile("mma.sync.aligned.m16n8k8.row.col.f32.tf32.tf32.f32 "
                 "{%0,%1,%2,%3}, {%4,%5,%6,%7}, {%8,%9}, {%0,%1,%2,%3};"
                 : "+f"(c[0]), "+f"(c[1]), "+f"(c[2]), "+f"(c[3])
                 : "r"(a[0]), "r"(a[1]), "r"(a[2]), "r"(a[3]), "r"(b[0]), "r"(b[1]));
}

__global__ __launch_bounds__(256) void gemm_w_tr(const float* __restrict__ A,
                                                 const float* __restrict__ B,
                                                 __half* __restrict__ C16t, int M) {
    extern __shared__ float smf[];
    int tid = threadIdx.x;
    int lane = tid & 31, wid = tid >> 5;
    int wm = wid & 3, wn = wid >> 2;
    int g = lane >> 2, q = lane & 3;
    long m0 = (long)blockIdx.x * 128;

    float acc[2][8][4];
    #pragma unroll
    for (int mt = 0; mt < 2; mt++)
        #pragma unroll
        for (int nt = 0; nt < 8; nt++)
            #pragma unroll
            for (int i = 0; i < 4; i++) acc[mt][nt][i] = 0.f;

    int ar[4], ac_[4], br[4], bc[4];
    #pragma unroll
    for (int i = 0; i < 4; i++) {
        int idx = (tid + 256 * i) * 4;
        ar[i] = idx >> 5; ac_[i] = idx & 31;
        br[i] = idx >> 7; bc[i] = idx & 127;
    }

    auto prefetch = [&](int kc, int s) {
        float* As = smf + s * GSTAGE;
        float* Bs = As + GSTAGE_A;
        #pragma unroll
        for (int i = 0; i < 4; i++) {
            long row = m0 + ar[i];
            uint32_t sa = (uint32_t)__cvta_generic_to_shared(&As[ar[i]*36 + ac_[i]]);
            cp_async16(sa, A + row * 128 + kc * 32 + ac_[i], row < M);
        }
        #pragma unroll
        for (int i = 0; i < 4; i++) {
            uint32_t sb = (uint32_t)__cvta_generic_to_shared(&Bs[br[i]*136 + bc[i]]);
            cp_async16(sb, B + (kc * 32 + br[i]) * 128 + bc[i], true);
        }
        asm volatile("cp.async.commit_group;");
    };

    prefetch(0, 0);
    for (int kc = 0; kc < 4; kc++) {
        if (kc < 3) {
            prefetch(kc + 1, (kc + 1) & 1);
            asm volatile("cp.async.wait_group 1;");
        } else {
            asm volatile("cp.async.wait_group 0;");
        }
        __syncthreads();
        const uint32_t* As = reinterpret_cast<const uint32_t*>(smf + (kc & 1) * GSTAGE);
        const uint32_t* Bs = As + GSTAGE_A;
        #pragma unroll
        for (int ks = 0; ks < 4; ks++) {
            int kc8 = ks * 8;
            uint32_t a[2][4], b[8][2];
            #pragma unroll
            for (int mt = 0; mt < 2; mt++) {
                int row = wm * 32 + mt * 16 + g;
                a[mt][0] = As[row*36 + kc8 + q];
                a[mt][1] = As[(row+8)*36 + kc8 + q];
                a[mt][2] = As[row*36 + kc8 + q + 4];
                a[mt][3] = As[(row+8)*36 + kc8 + q + 4];
            }
            #pragma unroll
            for (int nt = 0; nt < 8; nt++) {
                int col = wn * 64 + nt * 8 + g;
                b[nt][0] = Bs[(kc8 + q)*136 + col];
                b[nt][1] = Bs[(kc8 + q + 4)*136 + col];
            }
            #pragma unroll
            for (int mt = 0; mt < 2; mt++)
                #pragma unroll
                for (int nt = 0; nt < 8; nt++)
                    mma_tf32(acc[mt][nt], a[mt], b[nt]);
        }
        __syncthreads();
    }

    #pragma unroll
    for (int mt = 0; mt < 2; mt++) {
        #pragma unroll
        for (int h = 0; h < 2; h++) {
            long row = m0 + wm * 32 + mt * 16 + g + h * 8;
            if (row >= M) continue;
            #pragma unroll
            for (int nt = 0; nt < 8; nt++) {
                int col = wn * 64 + nt * 8 + q * 2;
                C16t[(long)col * 128 + row]       = __float2half(acc[mt][nt][h*2]);
                C16t[(long)(col + 1) * 128 + row] = __float2half(acc[mt][nt][h*2+1]);
            }
        }
    }
}

// -------- BN kernels --------

__global__ void bn_stats_k(const __half* __restrict__ h, float* __restrict__ colsum,
                           float* __restrict__ colsq) {
    __shared__ float ssum[128], ssq[128];
    int tid = threadIdx.x;
    if (tid < 128) { ssum[tid] = 0.f; ssq[tid] = 0.f; }
    __syncthreads();
    int c4 = tid & 31;
    int rstep = gridDim.x * 8;
    const uint2* h4 = reinterpret_cast<const uint2*>(h);
    float4 s = make_float4(0,0,0,0), s2 = make_float4(0,0,0,0);
    for (int r = blockIdx.x * 8 + (tid >> 5); r < NN; r += rstep) {
        float4 x; h4_to_f4(h4[(long)r * 32 + c4], x);
        s.x += x.x; s.y += x.y; s.z += x.z; s.w += x.w;
        s2.x += x.x*x.x; s2.y += x.y*x.y; s2.z += x.z*x.z; s2.w += x.w*x.w;
    }
    atomicAdd(&ssum[c4*4+0], s.x);  atomicAdd(&ssq[c4*4+0], s2.x);
    atomicAdd(&ssum[c4*4+1], s.y);  atomicAdd(&ssq[c4*4+1], s2.y);
    atomicAdd(&ssum[c4*4+2], s.z);  atomicAdd(&ssq[c4*4+2], s2.z);
    atomicAdd(&ssum[c4*4+3], s.w);  atomicAdd(&ssq[c4*4+3], s2.w);
    __syncthreads();
    if (tid < 128) {
        atomicAdd(&colsum[tid], ssum[tid]);
        atomicAdd(&colsq[tid], ssq[tid]);
    }
}

__global__ void bn_apply_relu_k(__half* __restrict__ h, const float* __restrict__ gamma,
                                const float* __restrict__ beta,
                                const float* __restrict__ colsum,
                                const float* __restrict__ colsq) {
    __shared__ float sm_mean[128], sm_scale[128], sm_beta[128];
    int tid = threadIdx.x;
    if (tid < 128) {
        const float invN = 1.f / (float)NN;
        float mean = colsum[tid] * invN;
        float var  = colsq[tid] * invN - mean * mean;
        sm_mean[tid] = mean;
        sm_scale[tid] = rsqrtf(var + 1e-5f) * gamma[tid];
        sm_beta[tid] = beta[tid];
    }
    __syncthreads();
    int idx = blockIdx.x * blockDim.x + tid;
    if (idx >= ND4) return;
    int c = (idx & 31) * 4;
    uint2* h4 = reinterpret_cast<uint2*>(h);
    float4 x; h4_to_f4(h4[idx], x);
    float4 o;
    o.x = fmaxf((x.x - sm_mean[c+0]) * sm_scale[c+0] + sm_beta[c+0], 0.f);
    o.y = fmaxf((x.y - sm_mean[c+1]) * sm_scale[c+1] + sm_beta[c+1], 0.f);
    o.z = fmaxf((x.z - sm_mean[c+2]) * sm_scale[c+2] + sm_beta[c+2], 0.f);
    o.w = fmaxf((x.w - sm_mean[c+3]) * sm_scale[c+3] + sm_beta[c+3], 0.f);
    h4[idx] = f4_to_h4(o);
}

// -------- host --------

extern "C" void kernel_launch(void* const* d_in, const int* in_sizes, int n_in,
                              void* d_out, int out_size) {
    const float* e_emb = (const float*)d_in[1];
    const int* node_ind = (const int*)d_in[26];
    const int* edge_src = (const int*)d_in[27];
    const int* edge_dst = (const int*)d_in[28];

    float *feat, *inv, *gscale, *colsum, *colsq;
    __half *feat16, *t1h, *t2h, *keyh, *skah, *vh, *t2ch, *w16, *wqa16, *wka16;
    int *cnt, *offs, *fill, *partial, *ssrc;
    cudaGetSymbolAddress((void**)&feat, g_feat);
    cudaGetSymbolAddress((void**)&feat16, g_feat16);
    cudaGetSymbolAddress((void**)&t1h, g_t1h);
    cudaGetSymbolAddress((void**)&t2h, g_t2h);
    cudaGetSymbolAddress((void**)&keyh, g_keyh);
    cudaGetSymbolAddress((void**)&skah, g_skah);
    cudaGetSymbolAddress((void**)&vh, g_vh);
    cudaGetSymbolAddress((void**)&t2ch, g_t2ch);
    cudaGetSymbolAddress((void**)&w16, g_w16);
    cudaGetSymbolAddress((void**)&wqa16, g_wqa16);
    cudaGetSymbolAddress((void**)&wka16, g_wka16);
    cudaGetSymbolAddress((void**)&cnt, g_cnt);
    cudaGetSymbolAddress((void**)&offs, g_offs);
    cudaGetSymbolAddress((void**)&fill, g_fill);
    cudaGetSymbolAddress((void**)&partial, g_partial);
    cudaGetSymbolAddress((void**)&ssrc, g_ssrc);
    cudaGetSymbolAddress((void**)&inv, g_inv);
    cudaGetSymbolAddress((void**)&gscale, g_gscale);
    cudaGetSymbolAddress((void**)&colsum, g_colsum);
    cudaGetSymbolAddress((void**)&colsq, g_colsq);

    cudaFuncSetAttribute(gemm_w_tr, cudaFuncAttributeMaxDynamicSharedMemorySize, GEMM_SMEM_BYTES);
    cudaFuncSetAttribute(gemm_seq2, cudaFuncAttributeMaxDynamicSharedMemorySize, (int)SEQ_SMEM_BYTES);

    const int TPB = 256;
    const int ND4_BLK = (ND4 + TPB - 1) / TPB;
    const int E_BLK = (TT*EE + TPB - 1) / TPB;
    const int GCNW_BLK = (NN*32 + TPB - 1) / TPB;
    const int ATTW_BLK = (TNN*32 + TPB - 1) / TPB;
    const int G1 = (NN + 127) / 128;
    const int G3 = (TNN + 127) / 128;

    convert_wt8_k<<<(8*DD*DD + TPB - 1)/TPB, TPB>>>(
        (const float*)d_in[2],  (const float*)d_in[5],  (const float*)d_in[9],  (const float*)d_in[12],
        (const float*)d_in[14], (const float*)d_in[17], (const float*)d_in[21], (const float*)d_in[24],
        w16);

    // ---- CSR build ----
    cudaMemsetAsync(cnt, 0, TNN*sizeof(int), 0);
    cudaMemsetAsync(fill, 0, TNN*sizeof(int), 0);
    count_k<<<E_BLK, TPB>>>(edge_dst, cnt);
    prep_k<<<(NN + TPB - 1)/TPB, TPB>>>(cnt, inv, gscale);
    scan_block_k<<<NB_SCAN, 256>>>(cnt, offs, partial);
    scan_partial_k<<<1, 256>>>(partial);
    scan_add_k<<<NB_SCAN, 256>>>(offs, partial);
    scatter_k<<<E_BLK, TPB>>>(edge_src, edge_dst, offs, fill, ssrc);
    gather_feat_k<<<ND4_BLK, TPB>>>((const float*)d_in[0], node_ind, feat, feat16);

    const float* gcn_gamma[2] = {(const float*)d_in[3],  (const float*)d_in[15]};
    const float* gcn_beta[2]  = {(const float*)d_in[4],  (const float*)d_in[16]};
    const float* gcn_b2[2]    = {(const float*)d_in[6],  (const float*)d_in[18]};
    const float* at_wq[2]     = {(const float*)d_in[7],  (const float*)d_in[19]};
    const float* at_wk[2]     = {(const float*)d_in[8],  (const float*)d_in[20]};
    const float* at_wa[2]     = {(const float*)d_in[10], (const float*)d_in[22]};
    const float* at_bp[2]     = {(const float*)d_in[13], (const float*)d_in[25]};

    for (int L = 0; L < 2; L++) {
        const __half* w1t = w16 + (size_t)(L*4 + 0) * DD * DD;
        const __half* w2t = w16 + (size_t)(L*4 + 1) * DD * DD;
        const __half* wvt = w16 + (size_t)(L*4 + 2) * DD * DD;
        const __half* wpt = w16 + (size_t)(L*4 + 3) * DD * DD;

        // ---- GCN layer ----
        gcn_edge_sorted<<<GCNW_BLK, TPB>>>(feat16, e_emb, ssrc, offs, cnt, inv, gscale, t1h);
        gemm16<0><<<G1, 256>>>(t1h, w1t, t2h, NN, nullptr, nullptr, nullptr, nullptr, nullptr);
        cudaMemsetAsync(colsum, 0, DD*sizeof(float), 0);
        cudaMemsetAsync(colsq, 0, DD*sizeof(float), 0);
        bn_stats_k<<<1024, 256>>>(t2h, colsum, colsq);
        bn_apply_relu_k<<<ND4_BLK, TPB>>>(t2h, gcn_gamma[L], gcn_beta[L], colsum, colsq);
        gemm16<1><<<G1, 256>>>(t2h, w2t, nullptr, NN, gcn_b2[L], feat, feat16, nullptr, nullptr);

        // ---- Attention layer ----
        gemm_w_tr<<<1, 256, GEMM_SMEM_BYTES>>>(at_wq[L], at_wa[L], wqa16, 128);
        gemm_w_tr<<<1, 256, GEMM_SMEM_BYTES>>>(at_wk[L], at_wa[L], wka16, 128);
        attn_edge_sorted<<<ATTW_BLK, TPB>>>(feat16, e_emb, ssrc, offs, cnt, inv, keyh);
        gemm_seq2<<<G3, 256, SEQ_SMEM_BYTES>>>(keyh, wka16, wvt, skah, vh, TNN);
        // qa GEMM + softmax-combine epilogue → t2ch
        gemm16<2><<<G1, 256>>>(feat16, wqa16, t2ch, NN, nullptr, nullptr, nullptr, skah, vh);
        gemm16<1><<<G1, 256>>>(t2ch, wpt, nullptr, NN, at_bp[L], feat, feat16, nullptr, nullptr);
    }

    cudaMemcpyAsync(d_out, feat, (size_t)ND*sizeof(float), cudaMemcpyDeviceToDevice, 0);
    if (out_size >= ND + TT*DD) {
        cudaMemcpyAsync((float*)d_out + ND, e_emb, TT*DD*sizeof(float),
                        cudaMemcpyDeviceToDevice, 0);
    }
}

// round 13
// speedup vs baseline: 1.4570x; 1.0523x over previous
#include <cuda_runtime.h>
#include <cuda_fp16.h>
#include <cstdint>
#include <math.h>

#define NN 100000
#define DD 128
#define EE 250000
#define TT 3
#define ND (NN*DD)
#define ND4 (ND/4)
#define TNN (TT*NN)
#define NB_SCAN ((TNN + 255) / 256)
#define SCHUNK ((NB_SCAN + 255) / 256)

// -------- scratch --------
__device__ float  g_feat[ND];
__device__ __half g_feat16[ND];
__device__ __half g_t1h[ND];
__device__ __half g_t2h[ND];
__device__ __half g_keyh[3*ND];
__device__ __half g_skah[3*ND];
__device__ __half g_vh[3*ND];
__device__ __half g_t2ch[ND];
__device__ __half g_w16[8][DD*DD];
__device__ __half g_wqa16[2][DD*DD];
__device__ __half g_wka16[2][DD*DD];
__device__ int    g_cnt[TNN];
__device__ int    g_offs[TNN];
__device__ int    g_fill[TNN];
__device__ int    g_partial[NB_SCAN];
__device__ int    g_ssrc[TT*EE];
__device__ float  g_inv[TNN];
__device__ float  g_gscale[NN];
__device__ float  g_colstats[2*DD];     // [0:128) sum, [128:256) sumsq

// -------- setup kernels --------

__global__ void gather_feat_k(const float* __restrict__ n_emb, const int* __restrict__ ind,
                              float* __restrict__ feat, __half* __restrict__ feat16) {
    int idx = blockIdx.x * blockDim.x + threadIdx.x;
    if (idx >= ND4) return;
    int n = idx >> 5;
    float4 v = reinterpret_cast<const float4*>(n_emb)[(long)ind[n] * 32 + (idx & 31)];
    reinterpret_cast<float4*>(feat)[idx] = v;
    __half2* h = reinterpret_cast<__half2*>(feat16) + idx * 2;
    h[0] = __floats2half2_rn(v.x, v.y);
    h[1] = __floats2half2_rn(v.z, v.w);
}

__global__ void convert_wt8_k(const float* w0, const float* w1, const float* w2, const float* w3,
                              const float* w4, const float* w5, const float* w6, const float* w7,
                              __half* __restrict__ wt) {
    int i = blockIdx.x * blockDim.x + threadIdx.x;
    if (i >= 8*DD*DD) return;
    const float* ws[8] = {w0, w1, w2, w3, w4, w5, w6, w7};
    int m = i >> 14;
    int j = i & (DD*DD - 1);
    int n = j >> 7, k = j & 127;
    wt[(size_t)m * DD * DD + n * 128 + k] = __float2half(ws[m][k * 128 + n]);
}

__global__ void count_k(const int* __restrict__ dst, int* __restrict__ cnt) {
    int e = blockIdx.x * blockDim.x + threadIdx.x;
    if (e >= TT*EE) return;
    int t = e / EE;
    atomicAdd(&cnt[t * NN + dst[e]], 1);
}

__global__ void prep_k(const int* __restrict__ cnt, float* __restrict__ inv,
                       float* __restrict__ gscale) {
    int n = blockIdx.x * blockDim.x + threadIdx.x;
    if (n >= NN) return;
    int c0 = cnt[n], c1 = cnt[NN + n], c2 = cnt[2*NN + n];
    inv[n]        = 1.f / (float)max(c0, 1);
    inv[NN + n]   = 1.f / (float)max(c1, 1);
    inv[2*NN + n] = 1.f / (float)max(c2, 1);
    gscale[n] = (float)((c0 > 0) + (c1 > 0) + (c2 > 0));
}

__global__ void scan_block_k(const int* __restrict__ cnt, int* __restrict__ offs,
                             int* __restrict__ partial) {
    __shared__ int sh[256];
    int tid = threadIdx.x;
    int i = blockIdx.x * 256 + tid;
    int v = (i < TNN) ? cnt[i] : 0;
    sh[tid] = v; __syncthreads();
    #pragma unroll
    for (int off = 1; off < 256; off <<= 1) {
        int x = (tid >= off) ? sh[tid - off] : 0;
        __syncthreads();
        sh[tid] += x;
        __syncthreads();
    }
    if (i < TNN) offs[i] = sh[tid] - v;
    if (tid == 255) partial[blockIdx.x] = sh[tid];
}

__global__ void scan_partial_k(int* __restrict__ partial) {
    __shared__ int sh[256];
    int tid = threadIdx.x;
    int base = tid * SCHUNK;
    int loc[SCHUNK];
    int s = 0;
    #pragma unroll
    for (int j = 0; j < SCHUNK; j++) {
        int idx = base + j;
        int v = (idx < NB_SCAN) ? partial[idx] : 0;
        loc[j] = s; s += v;
    }
    sh[tid] = s; __syncthreads();
    #pragma unroll
    for (int off = 1; off < 256; off <<= 1) {
        int x = (tid >= off) ? sh[tid - off] : 0;
        __syncthreads();
        sh[tid] += x;
        __syncthreads();
    }
    int excl = sh[tid] - s;
    #pragma unroll
    for (int j = 0; j < SCHUNK; j++) {
        int idx = base + j;
        if (idx < NB_SCAN) partial[idx] = excl + loc[j];
    }
}

__global__ void scan_add_k(int* __restrict__ offs, const int* __restrict__ partial) {
    int i = blockIdx.x * 256 + threadIdx.x;
    if (i < TNN) offs[i] += partial[blockIdx.x];
}

__global__ void scatter_k(const int* __restrict__ src, const int* __restrict__ dst,
                          const int* __restrict__ offs, int* __restrict__ fill,
                          int* __restrict__ ssrc) {
    int e = blockIdx.x * blockDim.x + threadIdx.x;
    if (e >= TT*EE) return;
    int t = e / EE;
    int td = t * NN + dst[e];
    int pos = offs[td] + atomicAdd(&fill[td], 1);
    ssrc[pos] = src[e];
}

// -------- fp16 helpers --------

__device__ __forceinline__ void h4_to_f4(uint2 u, float4& f) {
    __half2 h0 = *reinterpret_cast<__half2*>(&u.x);
    __half2 h1 = *reinterpret_cast<__half2*>(&u.y);
    float2 a = __half22float2(h0), b = __half22float2(h1);
    f.x = a.x; f.y = a.y; f.z = b.x; f.w = b.y;
}

__device__ __forceinline__ uint2 f4_to_h4(float4 f) {
    __half2 h0 = __floats2half2_rn(f.x, f.y);
    __half2 h1 = __floats2half2_rn(f.z, f.w);
    uint2 u;
    u.x = *reinterpret_cast<uint32_t*>(&h0);
    u.y = *reinterpret_cast<uint32_t*>(&h1);
    return u;
}

// -------- sorted edge passes --------

__global__ void gcn_edge_sorted(const __half* __restrict__ feat16, const float* __restrict__ emb,
                                const int* __restrict__ ssrc, const int* __restrict__ offs,
                                const int* __restrict__ cnt, const float* __restrict__ inv,
                                const float* __restrict__ gscale, __half* __restrict__ out) {
    int gw = (blockIdx.x * blockDim.x + threadIdx.x) >> 5;
    int lane = threadIdx.x & 31;
    if (gw >= NN) return;
    const uint2* f16 = reinterpret_cast<const uint2*>(feat16);
    float4 a; h4_to_f4(f16[gw * 32 + lane], a);
    float gs = gscale[gw];
    float4 acc = make_float4(a.x * gs, a.y * gs, a.z * gs, a.w * gs);
    #pragma unroll
    for (int t = 0; t < TT; t++) {
        int td = t * NN + gw;
        int len = cnt[td];
        if (len == 0) continue;
        int beg = offs[td];
        float4 s = make_float4(0.f, 0.f, 0.f, 0.f);
        for (int i = 0; i < len; i++) {
            int sn = ssrc[beg + i];
            float4 f; h4_to_f4(f16[sn * 32 + lane], f);
            s.x += f.x; s.y += f.y; s.z += f.z; s.w += f.w;
        }
        float4 e = reinterpret_cast<const float4*>(emb)[t * 32 + lane];
        float w = inv[td];
        acc.x -= s.x * e.x * w; acc.y -= s.y * e.y * w;
        acc.z -= s.z * e.z * w; acc.w -= s.w * e.w * w;
    }
    reinterpret_cast<uint2*>(out)[gw * 32 + lane] = f4_to_h4(acc);
}

__global__ void attn_edge_sorted(const __half* __restrict__ feat16, const float* __restrict__ emb,
                                 const int* __restrict__ ssrc, const int* __restrict__ offs,
                                 const int* __restrict__ cnt, const float* __restrict__ inv,
                                 __half* __restrict__ key) {
    int gw = (blockIdx.x * blockDim.x + threadIdx.x) >> 5;
    int lane = threadIdx.x & 31;
    if (gw >= TNN) return;
    int t = gw / NN;
    int len = cnt[gw];
    int beg = offs[gw];
    const uint2* f16 = reinterpret_cast<const uint2*>(feat16);
    float4 s = make_float4(0.f, 0.f, 0.f, 0.f);
    for (int i = 0; i < len; i++) {
        int sn = ssrc[beg + i];
        float4 f; h4_to_f4(f16[sn * 32 + lane], f);
        s.x += f.x; s.y += f.y; s.z += f.z; s.w += f.w;
    }
    float4 e = reinterpret_cast<const float4*>(emb)[t * 32 + lane];
    float w = inv[gw];
    reinterpret_cast<uint2*>(key)[(long)gw * 32 + lane] =
        f4_to_h4(make_float4(s.x*e.x*w, s.y*e.y*w, s.z*e.z*w, s.w*e.w*w));
}

// -------- fp16 GEMM: full-stage (A and B staged whole, one sync, unbroken MMA loop) --------
// EPI 0: store fp16 C. EPI 1: featf += acc + bias; refresh feat16.
// EPI 2: softmax-combine (acc = qa) with ska/vv → fp16 C.
// EPI 3: fout = featf + acc + bias  (final layer, writes d_out directly)

#define G16_SMEM_BYTES ((size_t)2 * 128 * 136 * 2)

__device__ __forceinline__ void cp_async16(uint32_t saddr, const void* gptr, bool pred) {
    int sz = pred ? 16 : 0;
    asm volatile("cp.async.ca.shared.global [%0], [%1], 16, %2;"
                 :: "r"(saddr), "l"(gptr), "r"(sz));
}

__device__ __forceinline__ void mma_f16(float* c, const uint32_t* a, const uint32_t* b) {
    asm volatile("mma.sync.aligned.m16n8k16.row.col.f32.f16.f16.f32 "
                 "{%0,%1,%2,%3}, {%4,%5,%6,%7}, {%8,%9}, {%0,%1,%2,%3};"
                 : "+f"(c[0]), "+f"(c[1]), "+f"(c[2]), "+f"(c[3])
                 : "r"(a[0]), "r"(a[1]), "r"(a[2]), "r"(a[3]), "r"(b[0]), "r"(b[1]));
}

template<int EPI>
__global__ __launch_bounds__(256) void gemm16(const __half* __restrict__ A,
                                              const __half* __restrict__ Bt,
                                              __half* __restrict__ C16, int M,
                                              const float* __restrict__ bias,
                                              float* __restrict__ featf,
                                              __half* __restrict__ feat16,
                                              const __half* __restrict__ ska,
                                              const __half* __restrict__ vv,
                                              float* __restrict__ fout) {
    extern __shared__ __half shh[];
    __half (*As)[136] = reinterpret_cast<__half(*)[136]>(shh);
    __half (*Bs)[136] = reinterpret_cast<__half(*)[136]>(shh + 128*136);
    int tid = threadIdx.x;
    int lane = tid & 31, wid = tid >> 5;
    int wm = wid & 3, wn = wid >> 2;
    int g = lane >> 2, q = lane & 3;
    long m0 = (long)blockIdx.x * 128;

    // stage A + B fully (2048 16B-vectors each, 8 per thread each)
    #pragma unroll
    for (int i = 0; i < 8; i++) {
        int v = tid + 256 * i;
        int r = v >> 4, kv = (v & 15) * 8;
        long row = m0 + r;
        uint32_t sa = (uint32_t)__cvta_generic_to_shared(&As[r][kv]);
        cp_async16(sa, A + row * 128 + kv, row < M);
        uint32_t sb = (uint32_t)__cvta_generic_to_shared(&Bs[r][kv]);
        cp_async16(sb, Bt + r * 128 + kv, true);
    }
    asm volatile("cp.async.commit_group;");
    asm volatile("cp.async.wait_group 0;");
    __syncthreads();

    float acc[2][8][4];
    #pragma unroll
    for (int mt = 0; mt < 2; mt++)
        #pragma unroll
        for (int nt = 0; nt < 8; nt++)
            #pragma unroll
            for (int i = 0; i < 4; i++) acc[mt][nt][i] = 0.f;

    #pragma unroll
    for (int ks = 0; ks < 8; ks++) {
        int kk = ks * 16;
        uint32_t a[2][4], b[8][2];
        #pragma unroll
        for (int mt = 0; mt < 2; mt++) {
            int row = wm * 32 + mt * 16 + g;
            a[mt][0] = *reinterpret_cast<const uint32_t*>(&As[row][kk + 2*q]);
            a[mt][1] = *reinterpret_cast<const uint32_t*>(&As[row + 8][kk + 2*q]);
            a[mt][2] = *reinterpret_cast<const uint32_t*>(&As[row][kk + 2*q + 8]);
            a[mt][3] = *reinterpret_cast<const uint32_t*>(&As[row + 8][kk + 2*q + 8]);
        }
        #pragma unroll
        for (int nt = 0; nt < 8; nt++) {
            int col = wn * 64 + nt * 8 + g;
            b[nt][0] = *reinterpret_cast<const uint32_t*>(&Bs[col][kk + 2*q]);
            b[nt][1] = *reinterpret_cast<const uint32_t*>(&Bs[col][kk + 2*q + 8]);
        }
        #pragma unroll
        for (int mt = 0; mt < 2; mt++)
            #pragma unroll
            for (int nt = 0; nt < 8; nt++)
                mma_f16(acc[mt][nt], a[mt], b[nt]);
    }

    #pragma unroll
    for (int mt = 0; mt < 2; mt++) {
        #pragma unroll
        for (int h = 0; h < 2; h++) {
            long row = m0 + wm * 32 + mt * 16 + g + h * 8;
            if (row >= M) continue;
            #pragma unroll
            for (int nt = 0; nt < 8; nt++) {
                int col = wn * 64 + nt * 8 + q * 2;
                long base = row * 128 + col;
                float v0 = acc[mt][nt][h * 2], v1 = acc[mt][nt][h * 2 + 1];
                if (EPI == 0) {
                    *reinterpret_cast<__half2*>(&C16[base]) = __floats2half2_rn(v0, v1);
                } else if (EPI == 1) {
                    float2 prev = *reinterpret_cast<const float2*>(&featf[base]);
                    float n0 = prev.x + v0 + bias[col];
                    float n1 = prev.y + v1 + bias[col + 1];
                    *reinterpret_cast<float2*>(&featf[base]) = make_float2(n0, n1);
                    *reinterpret_cast<__half2*>(&feat16[base]) = __floats2half2_rn(n0, n1);
                } else if (EPI == 3) {
                    float2 prev = *reinterpret_cast<const float2*>(&featf[base]);
                    *reinterpret_cast<float2*>(&fout[base]) =
                        make_float2(prev.x + v0 + bias[col], prev.y + v1 + bias[col + 1]);
                } else { // EPI == 2
                    float2 s0 = __half22float2(*reinterpret_cast<const __half2*>(ska + base));
                    float2 s1 = __half22float2(*reinterpret_cast<const __half2*>(ska + base + (long)ND));
                    float2 s2 = __half22float2(*reinterpret_cast<const __half2*>(ska + base + 2L*ND));
                    float2 w0 = __half22float2(*reinterpret_cast<const __half2*>(vv + base));
                    float2 w1 = __half22float2(*reinterpret_cast<const __half2*>(vv + base + (long)ND));
                    float2 w2 = __half22float2(*reinterpret_cast<const __half2*>(vv + base + 2L*ND));
                    float o0, o1;
                    {
                        float l0 = v0 - s0.x, l1 = v0 - s1.x, l2 = v0 - s2.x;
                        float mx = fmaxf(l0, fmaxf(l1, l2));
                        float e0 = __expf(l0-mx), e1 = __expf(l1-mx), e2 = __expf(l2-mx);
                        o0 = (e0*w0.x + e1*w1.x + e2*w2.x) / (e0 + e1 + e2);
                    }
                    {
                        float l0 = v1 - s0.y, l1 = v1 - s1.y, l2 = v1 - s2.y;
                        float mx = fmaxf(l0, fmaxf(l1, l2));
                        float e0 = __expf(l0-mx), e1 = __expf(l1-mx), e2 = __expf(l2-mx);
                        o1 = (e0*w0.y + e1*w1.y + e2*w2.y) / (e0 + e1 + e2);
                    }
                    *reinterpret_cast<__half2*>(&C16[base]) = __floats2half2_rn(o0, o1);
                }
            }
        }
    }
}

// Sequential-dual GEMM (unchanged from R12)
#define SEQ_SMEM_BYTES ((size_t)3 * 128 * 136 * 2)

__global__ __launch_bounds__(256) void gemm_seq2(const __half* __restrict__ A,
                                                 const __half* __restrict__ B1t,
                                                 const __half* __restrict__ B2t,
                                                 __half* __restrict__ C1,
                                                 __half* __restrict__ C2, int M) {
    extern __shared__ __half sh[];
    __half (*As)[136]  = reinterpret_cast<__half(*)[136]>(sh);
    __half (*Bs1)[136] = reinterpret_cast<__half(*)[136]>(sh + 128*136);
    __half (*Bs2)[136] = reinterpret_cast<__half(*)[136]>(sh + 2*128*136);
    int tid = threadIdx.x;
    int lane = tid & 31, wid = tid >> 5;
    int wm = wid & 3, wn = wid >> 2;
    int g = lane >> 2, q = lane & 3;
    long m0 = (long)blockIdx.x * 128;

    #pragma unroll
    for (int i = 0; i < 8; i++) {
        int v = tid + 256 * i;
        int r = v >> 4, kv = (v & 15) * 8;
        long row = m0 + r;
        uint32_t sa = (uint32_t)__cvta_generic_to_shared(&As[r][kv]);
        cp_async16(sa, A + row * 128 + kv, row < M);
        uint32_t s1 = (uint32_t)__cvta_generic_to_shared(&Bs1[r][kv]);
        cp_async16(s1, B1t + r * 128 + kv, true);
        uint32_t s2 = (uint32_t)__cvta_generic_to_shared(&Bs2[r][kv]);
        cp_async16(s2, B2t + r * 128 + kv, true);
    }
    asm volatile("cp.async.commit_group;");
    asm volatile("cp.async.wait_group 0;");
    __syncthreads();

    #pragma unroll
    for (int pass = 0; pass < 2; pass++) {
        __half (*Bs)[136] = pass ? Bs2 : Bs1;
        __half* C = pass ? C2 : C1;
        float acc[2][8][4];
        #pragma unroll
        for (int mt = 0; mt < 2; mt++)
            #pragma unroll
            for (int nt = 0; nt < 8; nt++)
                #pragma unroll
                for (int i = 0; i < 4; i++) acc[mt][nt][i] = 0.f;

        #pragma unroll
        for (int ks = 0; ks < 8; ks++) {
            int kk = ks * 16;
            uint32_t a[2][4], b[8][2];
            #pragma unroll
            for (int mt = 0; mt < 2; mt++) {
                int row = wm * 32 + mt * 16 + g;
                a[mt][0] = *reinterpret_cast<const uint32_t*>(&As[row][kk + 2*q]);
                a[mt][1] = *reinterpret_cast<const uint32_t*>(&As[row + 8][kk + 2*q]);
                a[mt][2] = *reinterpret_cast<const uint32_t*>(&As[row][kk + 2*q + 8]);
                a[mt][3] = *reinterpret_cast<const uint32_t*>(&As[row + 8][kk + 2*q + 8]);
            }
            #pragma unroll
            for (int nt = 0; nt < 8; nt++) {
                int col = wn * 64 + nt * 8 + g;
                b[nt][0] = *reinterpret_cast<const uint32_t*>(&Bs[col][kk + 2*q]);
                b[nt][1] = *reinterpret_cast<const uint32_t*>(&Bs[col][kk + 2*q + 8]);
            }
            #pragma unroll
            for (int mt = 0; mt < 2; mt++)
                #pragma unroll
                for (int nt = 0; nt < 8; nt++)
                    mma_f16(acc[mt][nt], a[mt], b[nt]);
        }

        #pragma unroll
        for (int mt = 0; mt < 2; mt++)
            #pragma unroll
            for (int h = 0; h < 2; h++) {
                long row = m0 + wm * 32 + mt * 16 + g + h * 8;
                if (row >= M) continue;
                #pragma unroll
                for (int nt = 0; nt < 8; nt++) {
                    int col = wn * 64 + nt * 8 + q * 2;
                    *reinterpret_cast<__half2*>(&C[row * 128 + col]) =
                        __floats2half2_rn(acc[mt][nt][h*2], acc[mt][nt][h*2+1]);
                }
            }
    }
}

// -------- tf32 GEMM for tiny wqa/wka products (setup phase); stores fp16 TRANSPOSED --------

#define GSTAGE_A (128*36)
#define GSTAGE_B (32*136)
#define GSTAGE   (GSTAGE_A + GSTAGE_B)
#define GEMM_SMEM_BYTES (2*GSTAGE*4)

__device__ __forceinline__ void mma_tf32(float* c, const uint32_t* a, const uint32_t* b) {
    asm volatile("mma.sync.aligned.m16n8k8.row.col.f32.tf32.tf32.f32 "
                 "{%0,%1,%2,%3}, {%4,%5,%6,%7}, {%8,%9}, {%0,%1,%2,%3};"
                 : "+f"(c[0]), "+f"(c[1]), "+f"(c[2]), "+f"(c[3])
                 : "r"(a[0]), "r"(a[1]), "r"(a[2]), "r"(a[3]), "r"(b[0]), "r"(b[1]));
}

__global__ __launch_bounds__(256) void gemm_w_tr(const float* __restrict__ A,
                                                 const float* __restrict__ B,
                                                 __half* __restrict__ C16t, int M) {
    extern __shared__ float smf[];
    int tid = threadIdx.x;
    int lane = tid & 31, wid = tid >> 5;
    int wm = wid & 3, wn = wid >> 2;
    int g = lane >> 2, q = lane & 3;
    long m0 = (long)blockIdx.x * 128;

    float acc[2][8][4];
    #pragma unroll
    for (int mt = 0; mt < 2; mt++)
        #pragma unroll
        for (int nt = 0; nt < 8; nt++)
            #pragma unroll
            for (int i = 0; i < 4; i++) acc[mt][nt][i] = 0.f;

    int ar[4], ac_[4], br[4], bc[4];
    #pragma unroll
    for (int i = 0; i < 4; i++) {
        int idx = (tid + 256 * i) * 4;
        ar[i] = idx >> 5; ac_[i] = idx & 31;
        br[i] = idx >> 7; bc[i] = idx & 127;
    }

    auto prefetch = [&](int kc, int s) {
        float* As = smf + s * GSTAGE;
        float* Bs = As + GSTAGE_A;
        #pragma unroll
        for (int i = 0; i < 4; i++) {
            long row = m0 + ar[i];
            uint32_t sa = (uint32_t)__cvta_generic_to_shared(&As[ar[i]*36 + ac_[i]]);
            cp_async16(sa, A + row * 128 + kc * 32 + ac_[i], row < M);
        }
        #pragma unroll
        for (int i = 0; i < 4; i++) {
            uint32_t sb = (uint32_t)__cvta_generic_to_shared(&Bs[br[i]*136 + bc[i]]);
            cp_async16(sb, B + (kc * 32 + br[i]) * 128 + bc[i], true);
        }
        asm volatile("cp.async.commit_group;");
    };

    prefetch(0, 0);
    for (int kc = 0; kc < 4; kc++) {
        if (kc < 3) {
            prefetch(kc + 1, (kc + 1) & 1);
            asm volatile("cp.async.wait_group 1;");
        } else {
            asm volatile("cp.async.wait_group 0;");
        }
        __syncthreads();
        const uint32_t* As = reinterpret_cast<const uint32_t*>(smf + (kc & 1) * GSTAGE);
        const uint32_t* Bs = As + GSTAGE_A;
        #pragma unroll
        for (int ks = 0; ks < 4; ks++) {
            int kc8 = ks * 8;
            uint32_t a[2][4], b[8][2];
            #pragma unroll
            for (int mt = 0; mt < 2; mt++) {
                int row = wm * 32 + mt * 16 + g;
                a[mt][0] = As[row*36 + kc8 + q];
                a[mt][1] = As[(row+8)*36 + kc8 + q];
                a[mt][2] = As[row*36 + kc8 + q + 4];
                a[mt][3] = As[(row+8)*36 + kc8 + q + 4];
            }
            #pragma unroll
            for (int nt = 0; nt < 8; nt++) {
                int col = wn * 64 + nt * 8 + g;
                b[nt][0] = Bs[(kc8 + q)*136 + col];
                b[nt][1] = Bs[(kc8 + q + 4)*136 + col];
            }
            #pragma unroll
            for (int mt = 0; mt < 2; mt++)
                #pragma unroll
                for (int nt = 0; nt < 8; nt++)
                    mma_tf32(acc[mt][nt], a[mt], b[nt]);
        }
        __syncthreads();
    }

    #pragma unroll
    for (int mt = 0; mt < 2; mt++) {
        #pragma unroll
        for (int h = 0; h < 2; h++) {
            long row = m0 + wm * 32 + mt * 16 + g + h * 8;
            if (row >= M) continue;
            #pragma unroll
            for (int nt = 0; nt < 8; nt++) {
                int col = wn * 64 + nt * 8 + q * 2;
                C16t[(long)col * 128 + row]       = __float2half(acc[mt][nt][h*2]);
                C16t[(long)(col + 1) * 128 + row] = __float2half(acc[mt][nt][h*2+1]);
            }
        }
    }
}

// -------- BN kernels --------

__global__ void bn_stats_k(const __half* __restrict__ h, float* __restrict__ colstats) {
    __shared__ float ssum[128], ssq[128];
    int tid = threadIdx.x;
    if (tid < 128) { ssum[tid] = 0.f; ssq[tid] = 0.f; }
    __syncthreads();
    int c4 = tid & 31;
    int rstep = gridDim.x * 8;
    const uint2* h4 = reinterpret_cast<const uint2*>(h);
    float4 s = make_float4(0,0,0,0), s2 = make_float4(0,0,0,0);
    for (int r = blockIdx.x * 8 + (tid >> 5); r < NN; r += rstep) {
        float4 x; h4_to_f4(h4[(long)r * 32 + c4], x);
        s.x += x.x; s.y += x.y; s.z += x.z; s.w += x.w;
        s2.x += x.x*x.x; s2.y += x.y*x.y; s2.z += x.z*x.z; s2.w += x.w*x.w;
    }
    atomicAdd(&ssum[c4*4+0], s.x);  atomicAdd(&ssq[c4*4+0], s2.x);
    atomicAdd(&ssum[c4*4+1], s.y);  atomicAdd(&ssq[c4*4+1], s2.y);
    atomicAdd(&ssum[c4*4+2], s.z);  atomicAdd(&ssq[c4*4+2], s2.z);
    atomicAdd(&ssum[c4*4+3], s.w);  atomicAdd(&ssq[c4*4+3], s2.w);
    __syncthreads();
    if (tid < 128) {
        atomicAdd(&colstats[tid], ssum[tid]);
        atomicAdd(&colstats[128 + tid], ssq[tid]);
    }
}

__global__ void bn_apply_relu_k(__half* __restrict__ h, const float* __restrict__ gamma,
                                const float* __restrict__ beta,
                                const float* __restrict__ colstats) {
    __shared__ float sm_mean[128], sm_scale[128], sm_beta[128];
    int tid = threadIdx.x;
    if (tid < 128) {
        const float invN = 1.f / (float)NN;
        float mean = colstats[tid] * invN;
        float var  = colstats[128 + tid] * invN - mean * mean;
        sm_mean[tid] = mean;
        sm_scale[tid] = rsqrtf(var + 1e-5f) * gamma[tid];
        sm_beta[tid] = beta[tid];
    }
    __syncthreads();
    int idx = blockIdx.x * blockDim.x + tid;
    if (idx >= ND4) return;
    int c = (idx & 31) * 4;
    uint2* h4 = reinterpret_cast<uint2*>(h);
    float4 x; h4_to_f4(h4[idx], x);
    float4 o;
    o.x = fmaxf((x.x - sm_mean[c+0]) * sm_scale[c+0] + sm_beta[c+0], 0.f);
    o.y = fmaxf((x.y - sm_mean[c+1]) * sm_scale[c+1] + sm_beta[c+1], 0.f);
    o.z = fmaxf((x.z - sm_mean[c+2]) * sm_scale[c+2] + sm_beta[c+2], 0.f);
    o.w = fmaxf((x.w - sm_mean[c+3]) * sm_scale[c+3] + sm_beta[c+3], 0.f);
    h4[idx] = f4_to_h4(o);
}

// -------- host --------

extern "C" void kernel_launch(void* const* d_in, const int* in_sizes, int n_in,
                              void* d_out, int out_size) {
    const float* e_emb = (const float*)d_in[1];
    const int* node_ind = (const int*)d_in[26];
    const int* edge_src = (const int*)d_in[27];
    const int* edge_dst = (const int*)d_in[28];

    float *feat, *inv, *gscale, *colstats;
    __half *feat16, *t1h, *t2h, *keyh, *skah, *vh, *t2ch, *w16, *wqa16, *wka16;
    int *cnt, *offs, *fill, *partial, *ssrc;
    cudaGetSymbolAddress((void**)&feat, g_feat);
    cudaGetSymbolAddress((void**)&feat16, g_feat16);
    cudaGetSymbolAddress((void**)&t1h, g_t1h);
    cudaGetSymbolAddress((void**)&t2h, g_t2h);
    cudaGetSymbolAddress((void**)&keyh, g_keyh);
    cudaGetSymbolAddress((void**)&skah, g_skah);
    cudaGetSymbolAddress((void**)&vh, g_vh);
    cudaGetSymbolAddress((void**)&t2ch, g_t2ch);
    cudaGetSymbolAddress((void**)&w16, g_w16);
    cudaGetSymbolAddress((void**)&wqa16, g_wqa16);
    cudaGetSymbolAddress((void**)&wka16, g_wka16);
    cudaGetSymbolAddress((void**)&cnt, g_cnt);
    cudaGetSymbolAddress((void**)&offs, g_offs);
    cudaGetSymbolAddress((void**)&fill, g_fill);
    cudaGetSymbolAddress((void**)&partial, g_partial);
    cudaGetSymbolAddress((void**)&ssrc, g_ssrc);
    cudaGetSymbolAddress((void**)&inv, g_inv);
    cudaGetSymbolAddress((void**)&gscale, g_gscale);
    cudaGetSymbolAddress((void**)&colstats, g_colstats);

    cudaFuncSetAttribute(gemm_w_tr, cudaFuncAttributeMaxDynamicSharedMemorySize, GEMM_SMEM_BYTES);
    cudaFuncSetAttribute(gemm_seq2, cudaFuncAttributeMaxDynamicSharedMemorySize, (int)SEQ_SMEM_BYTES);
    cudaFuncSetAttribute(gemm16<0>, cudaFuncAttributeMaxDynamicSharedMemorySize, (int)G16_SMEM_BYTES);
    cudaFuncSetAttribute(gemm16<1>, cudaFuncAttributeMaxDynamicSharedMemorySize, (int)G16_SMEM_BYTES);
    cudaFuncSetAttribute(gemm16<2>, cudaFuncAttributeMaxDynamicSharedMemorySize, (int)G16_SMEM_BYTES);
    cudaFuncSetAttribute(gemm16<3>, cudaFuncAttributeMaxDynamicSharedMemorySize, (int)G16_SMEM_BYTES);

    const int TPB = 256;
    const int ND4_BLK = (ND4 + TPB - 1) / TPB;
    const int E_BLK = (TT*EE + TPB - 1) / TPB;
    const int GCNW_BLK = (NN*32 + TPB - 1) / TPB;
    const int ATTW_BLK = (TNN*32 + TPB - 1) / TPB;
    const int G1 = (NN + 127) / 128;
    const int G3 = (TNN + 127) / 128;

    // ---- setup: weights, wqa/wka (hoisted), CSR build ----
    convert_wt8_k<<<(8*DD*DD + TPB - 1)/TPB, TPB>>>(
        (const float*)d_in[2],  (const float*)d_in[5],  (const float*)d_in[9],  (const float*)d_in[12],
        (const float*)d_in[14], (const float*)d_in[17], (const float*)d_in[21], (const float*)d_in[24],
        w16);
    gemm_w_tr<<<1, 256, GEMM_SMEM_BYTES>>>((const float*)d_in[7],  (const float*)d_in[10], wqa16, 128);
    gemm_w_tr<<<1, 256, GEMM_SMEM_BYTES>>>((const float*)d_in[8],  (const float*)d_in[10], wka16, 128);
    gemm_w_tr<<<1, 256, GEMM_SMEM_BYTES>>>((const float*)d_in[19], (const float*)d_in[22], wqa16 + DD*DD, 128);
    gemm_w_tr<<<1, 256, GEMM_SMEM_BYTES>>>((const float*)d_in[20], (const float*)d_in[22], wka16 + DD*DD, 128);

    cudaMemsetAsync(cnt, 0, TNN*sizeof(int), 0);
    cudaMemsetAsync(fill, 0, TNN*sizeof(int), 0);
    count_k<<<E_BLK, TPB>>>(edge_dst, cnt);
    prep_k<<<(NN + TPB - 1)/TPB, TPB>>>(cnt, inv, gscale);
    scan_block_k<<<NB_SCAN, 256>>>(cnt, offs, partial);
    scan_partial_k<<<1, 256>>>(partial);
    scan_add_k<<<NB_SCAN, 256>>>(offs, partial);
    scatter_k<<<E_BLK, TPB>>>(edge_src, edge_dst, offs, fill, ssrc);
    gather_feat_k<<<ND4_BLK, TPB>>>((const float*)d_in[0], node_ind, feat, feat16);

    const float* gcn_gamma[2] = {(const float*)d_in[3],  (const float*)d_in[15]};
    const float* gcn_beta[2]  = {(const float*)d_in[4],  (const float*)d_in[16]};
    const float* gcn_b2[2]    = {(const float*)d_in[6],  (const float*)d_in[18]};
    const float* at_bp[2]     = {(const float*)d_in[13], (const float*)d_in[25]};

    for (int L = 0; L < 2; L++) {
        const __half* w1t = w16 + (size_t)(L*4 + 0) * DD * DD;
        const __half* w2t = w16 + (size_t)(L*4 + 1) * DD * DD;
        const __half* wvt = w16 + (size_t)(L*4 + 2) * DD * DD;
        const __half* wpt = w16 + (size_t)(L*4 + 3) * DD * DD;
        const __half* wqaL = wqa16 + (size_t)L * DD * DD;
        const __half* wkaL = wka16 + (size_t)L * DD * DD;

        // ---- GCN layer ----
        gcn_edge_sorted<<<GCNW_BLK, TPB>>>(feat16, e_emb, ssrc, offs, cnt, inv, gscale, t1h);
        gemm16<0><<<G1, 256, G16_SMEM_BYTES>>>(t1h, w1t, t2h, NN, nullptr, nullptr, nullptr, nullptr, nullptr, nullptr);
        cudaMemsetAsync(colstats, 0, 2*DD*sizeof(float), 0);
        bn_stats_k<<<1024, 256>>>(t2h, colstats);
        bn_apply_relu_k<<<ND4_BLK, TPB>>>(t2h, gcn_gamma[L], gcn_beta[L], colstats);
        gemm16<1><<<G1, 256, G16_SMEM_BYTES>>>(t2h, w2t, nullptr, NN, gcn_b2[L], feat, feat16, nullptr, nullptr, nullptr);

        // ---- Attention layer ----
        attn_edge_sorted<<<ATTW_BLK, TPB>>>(feat16, e_emb, ssrc, offs, cnt, inv, keyh);
        gemm_seq2<<<G3, 256, SEQ_SMEM_BYTES>>>(keyh, wkaL, wvt, skah, vh, TNN);
        gemm16<2><<<G1, 256, G16_SMEM_BYTES>>>(feat16, wqaL, t2ch, NN, nullptr, nullptr, nullptr, skah, vh, nullptr);
        if (L == 0) {
            gemm16<1><<<G1, 256, G16_SMEM_BYTES>>>(t2ch, wpt, nullptr, NN, at_bp[L], feat, feat16, nullptr, nullptr, nullptr);
        } else {
            gemm16<3><<<G1, 256, G16_SMEM_BYTES>>>(t2ch, wpt, nullptr, NN, at_bp[L], feat, nullptr, nullptr, nullptr, (float*)d_out);
        }
    }

    if (out_size >= ND + TT*DD) {
        cudaMemcpyAsync((float*)d_out + ND, e_emb, TT*DD*sizeof(float),
                        cudaMemcpyDeviceToDevice, 0);
    }
}

// round 14
// speedup vs baseline: 1.4735x; 1.0113x over previous
#include <cuda_runtime.h>
#include <cuda_fp16.h>
#include <cstdint>
#include <math.h>

#define NN 100000
#define DD 128
#define EE 250000
#define TT 3
#define ND (NN*DD)
#define ND4 (ND/4)
#define TNN (TT*NN)
#define NB_SCAN ((TNN + 255) / 256)
#define SCHUNK ((NB_SCAN + 255) / 256)

// -------- scratch --------
__device__ float  g_feat[ND];
__device__ __half g_feat16[ND];
__device__ __half g_t1h[ND];
__device__ __half g_t2h[ND];
__device__ __half g_keyh[3*ND];
__device__ __half g_skah[3*ND];
__device__ __half g_vh[3*ND];
__device__ __half g_t2ch[ND];
__device__ __half g_w16[8][DD*DD];
__device__ __half g_wqa16[2][DD*DD];
__device__ __half g_wka16[2][DD*DD];
__device__ int    g_cnt[TNN];
__device__ int    g_offs[TNN];
__device__ int    g_fill[TNN];
__device__ int    g_partial[NB_SCAN];
__device__ int    g_ssrc[TT*EE];
__device__ float  g_inv[TNN];
__device__ float  g_gscale[NN];
__device__ float  g_colstats[2*DD];

// -------- setup kernels --------

__global__ void gather_feat_k(const float* __restrict__ n_emb, const int* __restrict__ ind,
                              float* __restrict__ feat, __half* __restrict__ feat16) {
    int idx = blockIdx.x * blockDim.x + threadIdx.x;
    if (idx >= ND4) return;
    int n = idx >> 5;
    float4 v = reinterpret_cast<const float4*>(n_emb)[(long)ind[n] * 32 + (idx & 31)];
    reinterpret_cast<float4*>(feat)[idx] = v;
    __half2* h = reinterpret_cast<__half2*>(feat16) + idx * 2;
    h[0] = __floats2half2_rn(v.x, v.y);
    h[1] = __floats2half2_rn(v.z, v.w);
}

__global__ void convert_wt8_k(const float* w0, const float* w1, const float* w2, const float* w3,
                              const float* w4, const float* w5, const float* w6, const float* w7,
                              __half* __restrict__ wt) {
    int i = blockIdx.x * blockDim.x + threadIdx.x;
    if (i >= 8*DD*DD) return;
    const float* ws[8] = {w0, w1, w2, w3, w4, w5, w6, w7};
    int m = i >> 14;
    int j = i & (DD*DD - 1);
    int n = j >> 7, k = j & 127;
    wt[(size_t)m * DD * DD + n * 128 + k] = __float2half(ws[m][k * 128 + n]);
}

__global__ void count_k(const int* __restrict__ dst, int* __restrict__ cnt) {
    int e = blockIdx.x * blockDim.x + threadIdx.x;
    if (e >= TT*EE) return;
    int t = e / EE;
    atomicAdd(&cnt[t * NN + dst[e]], 1);
}

__global__ void prep_k(const int* __restrict__ cnt, float* __restrict__ inv,
                       float* __restrict__ gscale) {
    int n = blockIdx.x * blockDim.x + threadIdx.x;
    if (n >= NN) return;
    int c0 = cnt[n], c1 = cnt[NN + n], c2 = cnt[2*NN + n];
    inv[n]        = 1.f / (float)max(c0, 1);
    inv[NN + n]   = 1.f / (float)max(c1, 1);
    inv[2*NN + n] = 1.f / (float)max(c2, 1);
    gscale[n] = (float)((c0 > 0) + (c1 > 0) + (c2 > 0));
}

__global__ void scan_block_k(const int* __restrict__ cnt, int* __restrict__ offs,
                             int* __restrict__ partial) {
    __shared__ int sh[256];
    int tid = threadIdx.x;
    int i = blockIdx.x * 256 + tid;
    int v = (i < TNN) ? cnt[i] : 0;
    sh[tid] = v; __syncthreads();
    #pragma unroll
    for (int off = 1; off < 256; off <<= 1) {
        int x = (tid >= off) ? sh[tid - off] : 0;
        __syncthreads();
        sh[tid] += x;
        __syncthreads();
    }
    if (i < TNN) offs[i] = sh[tid] - v;
    if (tid == 255) partial[blockIdx.x] = sh[tid];
}

__global__ void scan_partial_k(int* __restrict__ partial) {
    __shared__ int sh[256];
    int tid = threadIdx.x;
    int base = tid * SCHUNK;
    int loc[SCHUNK];
    int s = 0;
    #pragma unroll
    for (int j = 0; j < SCHUNK; j++) {
        int idx = base + j;
        int v = (idx < NB_SCAN) ? partial[idx] : 0;
        loc[j] = s; s += v;
    }
    sh[tid] = s; __syncthreads();
    #pragma unroll
    for (int off = 1; off < 256; off <<= 1) {
        int x = (tid >= off) ? sh[tid - off] : 0;
        __syncthreads();
        sh[tid] += x;
        __syncthreads();
    }
    int excl = sh[tid] - s;
    #pragma unroll
    for (int j = 0; j < SCHUNK; j++) {
        int idx = base + j;
        if (idx < NB_SCAN) partial[idx] = excl + loc[j];
    }
}

__global__ void scan_add_k(int* __restrict__ offs, const int* __restrict__ partial) {
    int i = blockIdx.x * 256 + threadIdx.x;
    if (i < TNN) offs[i] += partial[blockIdx.x];
}

__global__ void scatter_k(const int* __restrict__ src, const int* __restrict__ dst,
                          const int* __restrict__ offs, int* __restrict__ fill,
                          int* __restrict__ ssrc) {
    int e = blockIdx.x * blockDim.x + threadIdx.x;
    if (e >= TT*EE) return;
    int t = e / EE;
    int td = t * NN + dst[e];
    int pos = offs[td] + atomicAdd(&fill[td], 1);
    ssrc[pos] = src[e];
}

// -------- fp16 helpers --------

__device__ __forceinline__ void h4_to_f4(uint2 u, float4& f) {
    __half2 h0 = *reinterpret_cast<__half2*>(&u.x);
    __half2 h1 = *reinterpret_cast<__half2*>(&u.y);
    float2 a = __half22float2(h0), b = __half22float2(h1);
    f.x = a.x; f.y = a.y; f.z = b.x; f.w = b.y;
}

__device__ __forceinline__ uint2 f4_to_h4(float4 f) {
    __half2 h0 = __floats2half2_rn(f.x, f.y);
    __half2 h1 = __floats2half2_rn(f.z, f.w);
    uint2 u;
    u.x = *reinterpret_cast<uint32_t*>(&h0);
    u.y = *reinterpret_cast<uint32_t*>(&h1);
    return u;
}

// -------- sorted edge passes --------

__global__ void gcn_edge_sorted(const __half* __restrict__ feat16, const float* __restrict__ emb,
                                const int* __restrict__ ssrc, const int* __restrict__ offs,
                                const int* __restrict__ cnt, const float* __restrict__ inv,
                                const float* __restrict__ gscale, __half* __restrict__ out) {
    int gw = (blockIdx.x * blockDim.x + threadIdx.x) >> 5;
    int lane = threadIdx.x & 31;
    if (gw >= NN) return;
    const uint2* f16 = reinterpret_cast<const uint2*>(feat16);
    float4 a; h4_to_f4(f16[gw * 32 + lane], a);
    float gs = gscale[gw];
    float4 acc = make_float4(a.x * gs, a.y * gs, a.z * gs, a.w * gs);
    #pragma unroll
    for (int t = 0; t < TT; t++) {
        int td = t * NN + gw;
        int len = cnt[td];
        if (len == 0) continue;
        int beg = offs[td];
        float4 s = make_float4(0.f, 0.f, 0.f, 0.f);
        for (int i = 0; i < len; i++) {
            int sn = ssrc[beg + i];
            float4 f; h4_to_f4(f16[sn * 32 + lane], f);
            s.x += f.x; s.y += f.y; s.z += f.z; s.w += f.w;
        }
        float4 e = reinterpret_cast<const float4*>(emb)[t * 32 + lane];
        float w = inv[td];
        acc.x -= s.x * e.x * w; acc.y -= s.y * e.y * w;
        acc.z -= s.z * e.z * w; acc.w -= s.w * e.w * w;
    }
    reinterpret_cast<uint2*>(out)[gw * 32 + lane] = f4_to_h4(acc);
}

__global__ void attn_edge_sorted(const __half* __restrict__ feat16, const float* __restrict__ emb,
                                 const int* __restrict__ ssrc, const int* __restrict__ offs,
                                 const int* __restrict__ cnt, const float* __restrict__ inv,
                                 __half* __restrict__ key) {
    int gw = (blockIdx.x * blockDim.x + threadIdx.x) >> 5;
    int lane = threadIdx.x & 31;
    if (gw >= TNN) return;
    int t = gw / NN;
    int len = cnt[gw];
    int beg = offs[gw];
    const uint2* f16 = reinterpret_cast<const uint2*>(feat16);
    float4 s = make_float4(0.f, 0.f, 0.f, 0.f);
    for (int i = 0; i < len; i++) {
        int sn = ssrc[beg + i];
        float4 f; h4_to_f4(f16[sn * 32 + lane], f);
        s.x += f.x; s.y += f.y; s.z += f.z; s.w += f.w;
    }
    float4 e = reinterpret_cast<const float4*>(emb)[t * 32 + lane];
    float w = inv[gw];
    reinterpret_cast<uint2*>(key)[(long)gw * 32 + lane] =
        f4_to_h4(make_float4(s.x*e.x*w, s.y*e.y*w, s.z*e.z*w, s.w*e.w*w));
}

// -------- fp16 GEMM (full-stage) --------
// EPI 0: store. EPI 1: featf += acc + bias; refresh feat16. EPI 2: softmax-combine.
// EPI 3: fout = featf + acc + bias.
// STATS 1: accumulate column sum/sumsq of C into colstats (gemm1).
// ABN 1: A-staging applies BN(colstats,gamma,beta)+ReLU (gemm2).

#define G16_SMEM_BYTES ((size_t)2 * 128 * 136 * 2)

__device__ __forceinline__ void cp_async16(uint32_t saddr, const void* gptr, bool pred) {
    int sz = pred ? 16 : 0;
    asm volatile("cp.async.ca.shared.global [%0], [%1], 16, %2;"
                 :: "r"(saddr), "l"(gptr), "r"(sz));
}

__device__ __forceinline__ void mma_f16(float* c, const uint32_t* a, const uint32_t* b) {
    asm volatile("mma.sync.aligned.m16n8k16.row.col.f32.f16.f16.f32 "
                 "{%0,%1,%2,%3}, {%4,%5,%6,%7}, {%8,%9}, {%0,%1,%2,%3};"
                 : "+f"(c[0]), "+f"(c[1]), "+f"(c[2]), "+f"(c[3])
                 : "r"(a[0]), "r"(a[1]), "r"(a[2]), "r"(a[3]), "r"(b[0]), "r"(b[1]));
}

template<int EPI, int STATS, int ABN>
__global__ __launch_bounds__(256, 2) void gemm16(const __half* __restrict__ A,
                                                 const __half* __restrict__ Bt,
                                                 __half* __restrict__ C16, int M,
                                                 const float* __restrict__ bias,
                                                 float* __restrict__ featf,
                                                 __half* __restrict__ feat16,
                                                 const __half* __restrict__ ska,
                                                 const __half* __restrict__ vv,
                                                 float* __restrict__ fout,
                                                 const float* __restrict__ gamma,
                                                 const float* __restrict__ beta,
                                                 float* __restrict__ colstats) {
    extern __shared__ __half shh[];
    __half (*As)[136] = reinterpret_cast<__half(*)[136]>(shh);
    __half (*Bs)[136] = reinterpret_cast<__half(*)[136]>(shh + 128*136);
    __shared__ float bnm[128], bns[128], bnb[128];
    int tid = threadIdx.x;
    int lane = tid & 31, wid = tid >> 5;
    int wm = wid & 3, wn = wid >> 2;
    int g = lane >> 2, q = lane & 3;
    long m0 = (long)blockIdx.x * 128;

    if (ABN && tid < 128) {
        const float invN = 1.f / (float)NN;
        float mean = colstats[tid] * invN;
        float var  = colstats[128 + tid] * invN - mean * mean;
        bnm[tid] = mean;
        bns[tid] = rsqrtf(var + 1e-5f) * gamma[tid];
        bnb[tid] = beta[tid];
    }

    // B staging: cp.async always
    #pragma unroll
    for (int i = 0; i < 8; i++) {
        int v = tid + 256 * i;
        int r = v >> 4, kv = (v & 15) * 8;
        uint32_t sb = (uint32_t)__cvta_generic_to_shared(&Bs[r][kv]);
        cp_async16(sb, Bt + r * 128 + kv, true);
    }
    if (!ABN) {
        #pragma unroll
        for (int i = 0; i < 8; i++) {
            int v = tid + 256 * i;
            int r = v >> 4, kv = (v & 15) * 8;
            long row = m0 + r;
            uint32_t sa = (uint32_t)__cvta_generic_to_shared(&As[r][kv]);
            cp_async16(sa, A + row * 128 + kv, row < M);
        }
        asm volatile("cp.async.commit_group;");
        asm volatile("cp.async.wait_group 0;");
        __syncthreads();
    } else {
        asm volatile("cp.async.commit_group;");
        // A staging via LDG + BN transform + STS (two 4-vector batches)
        #pragma unroll
        for (int batch = 0; batch < 2; batch++) {
            uint4 av[4];
            #pragma unroll
            for (int i = 0; i < 4; i++) {
                int v = tid + 256 * (batch * 4 + i);
                int r = v >> 4, kv = (v & 15) * 8;
                long row = m0 + r;
                av[i] = (row < M) ? *reinterpret_cast<const uint4*>(A + row * 128 + kv)
                                  : make_uint4(0u, 0u, 0u, 0u);
            }
            if (batch == 0) __syncthreads();   // bn params ready; A smem untouched so safe
            #pragma unroll
            for (int i = 0; i < 4; i++) {
                int v = tid + 256 * (batch * 4 + i);
                int r = v >> 4, kv = (v & 15) * 8;
                uint32_t* u = &av[i].x;
                uint4 ov;
                uint32_t* o = &ov.x;
                #pragma unroll
                for (int j = 0; j < 4; j++) {
                    __half2 hv = *reinterpret_cast<__half2*>(&u[j]);
                    float2 f = __half22float2(hv);
                    int c0 = kv + 2*j;
                    f.x = fmaxf((f.x - bnm[c0])   * bns[c0]   + bnb[c0],   0.f);
                    f.y = fmaxf((f.y - bnm[c0+1]) * bns[c0+1] + bnb[c0+1], 0.f);
                    __half2 hr = __floats2half2_rn(f.x, f.y);
                    o[j] = *reinterpret_cast<uint32_t*>(&hr);
                }
                *reinterpret_cast<uint4*>(&As[r][kv]) = ov;
            }
        }
        asm volatile("cp.async.wait_group 0;");
        __syncthreads();
    }

    float acc[2][8][4];
    #pragma unroll
    for (int mt = 0; mt < 2; mt++)
        #pragma unroll
        for (int nt = 0; nt < 8; nt++)
            #pragma unroll
            for (int i = 0; i < 4; i++) acc[mt][nt][i] = 0.f;

    #pragma unroll
    for (int ks = 0; ks < 8; ks++) {
        int kk = ks * 16;
        uint32_t a[2][4], b[8][2];
        #pragma unroll
        for (int mt = 0; mt < 2; mt++) {
            int row = wm * 32 + mt * 16 + g;
            a[mt][0] = *reinterpret_cast<const uint32_t*>(&As[row][kk + 2*q]);
            a[mt][1] = *reinterpret_cast<const uint32_t*>(&As[row + 8][kk + 2*q]);
            a[mt][2] = *reinterpret_cast<const uint32_t*>(&As[row][kk + 2*q + 8]);
            a[mt][3] = *reinterpret_cast<const uint32_t*>(&As[row + 8][kk + 2*q + 8]);
        }
        #pragma unroll
        for (int nt = 0; nt < 8; nt++) {
            int col = wn * 64 + nt * 8 + g;
            b[nt][0] = *reinterpret_cast<const uint32_t*>(&Bs[col][kk + 2*q]);
            b[nt][1] = *reinterpret_cast<const uint32_t*>(&Bs[col][kk + 2*q + 8]);
        }
        #pragma unroll
        for (int mt = 0; mt < 2; mt++)
            #pragma unroll
            for (int nt = 0; nt < 8; nt++)
                mma_f16(acc[mt][nt], a[mt], b[nt]);
    }

    #pragma unroll
    for (int mt = 0; mt < 2; mt++) {
        #pragma unroll
        for (int h = 0; h < 2; h++) {
            long row = m0 + wm * 32 + mt * 16 + g + h * 8;
            if (row >= M) continue;
            #pragma unroll
            for (int nt = 0; nt < 8; nt++) {
                int col = wn * 64 + nt * 8 + q * 2;
                long base = row * 128 + col;
                float v0 = acc[mt][nt][h * 2], v1 = acc[mt][nt][h * 2 + 1];
                if (EPI == 0) {
                    *reinterpret_cast<__half2*>(&C16[base]) = __floats2half2_rn(v0, v1);
                } else if (EPI == 1) {
                    float2 prev = *reinterpret_cast<const float2*>(&featf[base]);
                    float n0 = prev.x + v0 + bias[col];
                    float n1 = prev.y + v1 + bias[col + 1];
                    *reinterpret_cast<float2*>(&featf[base]) = make_float2(n0, n1);
                    *reinterpret_cast<__half2*>(&feat16[base]) = __floats2half2_rn(n0, n1);
                } else if (EPI == 3) {
                    float2 prev = *reinterpret_cast<const float2*>(&featf[base]);
                    *reinterpret_cast<float2*>(&fout[base]) =
                        make_float2(prev.x + v0 + bias[col], prev.y + v1 + bias[col + 1]);
                } else { // EPI == 2
                    float2 s0 = __half22float2(*reinterpret_cast<const __half2*>(ska + base));
                    float2 s1 = __half22float2(*reinterpret_cast<const __half2*>(ska + base + (long)ND));
                    float2 s2 = __half22float2(*reinterpret_cast<const __half2*>(ska + base + 2L*ND));
                    float2 w0 = __half22float2(*reinterpret_cast<const __half2*>(vv + base));
                    float2 w1 = __half22float2(*reinterpret_cast<const __half2*>(vv + base + (long)ND));
                    float2 w2 = __half22float2(*reinterpret_cast<const __half2*>(vv + base + 2L*ND));
                    float o0, o1;
                    {
                        float l0 = v0 - s0.x, l1 = v0 - s1.x, l2 = v0 - s2.x;
                        float mx = fmaxf(l0, fmaxf(l1, l2));
                        float e0 = __expf(l0-mx), e1 = __expf(l1-mx), e2 = __expf(l2-mx);
                        o0 = (e0*w0.x + e1*w1.x + e2*w2.x) / (e0 + e1 + e2);
                    }
                    {
                        float l0 = v1 - s0.y, l1 = v1 - s1.y, l2 = v1 - s2.y;
                        float mx = fmaxf(l0, fmaxf(l1, l2));
                        float e0 = __expf(l0-mx), e1 = __expf(l1-mx), e2 = __expf(l2-mx);
                        o1 = (e0*w0.y + e1*w1.y + e2*w2.y) / (e0 + e1 + e2);
                    }
                    *reinterpret_cast<__half2*>(&C16[base]) = __floats2half2_rn(o0, o1);
                }
            }
        }
    }

    if (STATS) {
        // column stats from accumulators (OOB rows are zero → contribute 0)
        #pragma unroll
        for (int nt = 0; nt < 8; nt++) {
            float s0 = 0.f, q0 = 0.f, s1 = 0.f, q1 = 0.f;
            #pragma unroll
            for (int mt = 0; mt < 2; mt++)
                #pragma unroll
                for (int h = 0; h < 2; h++) {
                    float v0 = acc[mt][nt][h*2], v1 = acc[mt][nt][h*2+1];
                    s0 += v0; q0 += v0*v0; s1 += v1; q1 += v1*v1;
                }
            #pragma unroll
            for (int off = 4; off < 32; off <<= 1) {
                s0 += __shfl_xor_sync(0xffffffffu, s0, off);
                q0 += __shfl_xor_sync(0xffffffffu, q0, off);
                s1 += __shfl_xor_sync(0xffffffffu, s1, off);
                q1 += __shfl_xor_sync(0xffffffffu, q1, off);
            }
            if (g == 0) {
                int col = wn * 64 + nt * 8 + q * 2;
                atomicAdd(&colstats[col], s0);
                atomicAdd(&colstats[128 + col], q0);
                atomicAdd(&colstats[col + 1], s1);
                atomicAdd(&colstats[128 + col + 1], q1);
            }
        }
    }
}

// Sequential-dual GEMM (unchanged)
#define SEQ_SMEM_BYTES ((size_t)3 * 128 * 136 * 2)

__global__ __launch_bounds__(256, 2) void gemm_seq2(const __half* __restrict__ A,
                                                    const __half* __restrict__ B1t,
                                                    const __half* __restrict__ B2t,
                                                    __half* __restrict__ C1,
                                                    __half* __restrict__ C2, int M) {
    extern __shared__ __half sh[];
    __half (*As)[136]  = reinterpret_cast<__half(*)[136]>(sh);
    __half (*Bs1)[136] = reinterpret_cast<__half(*)[136]>(sh + 128*136);
    __half (*Bs2)[136] = reinterpret_cast<__half(*)[136]>(sh + 2*128*136);
    int tid = threadIdx.x;
    int lane = tid & 31, wid = tid >> 5;
    int wm = wid & 3, wn = wid >> 2;
    int g = lane >> 2, q = lane & 3;
    long m0 = (long)blockIdx.x * 128;

    #pragma unroll
    for (int i = 0; i < 8; i++) {
        int v = tid + 256 * i;
        int r = v >> 4, kv = (v & 15) * 8;
        long row = m0 + r;
        uint32_t sa = (uint32_t)__cvta_generic_to_shared(&As[r][kv]);
        cp_async16(sa, A + row * 128 + kv, row < M);
        uint32_t s1 = (uint32_t)__cvta_generic_to_shared(&Bs1[r][kv]);
        cp_async16(s1, B1t + r * 128 + kv, true);
        uint32_t s2 = (uint32_t)__cvta_generic_to_shared(&Bs2[r][kv]);
        cp_async16(s2, B2t + r * 128 + kv, true);
    }
    asm volatile("cp.async.commit_group;");
    asm volatile("cp.async.wait_group 0;");
    __syncthreads();

    #pragma unroll
    for (int pass = 0; pass < 2; pass++) {
        __half (*Bs)[136] = pass ? Bs2 : Bs1;
        __half* C = pass ? C2 : C1;
        float acc[2][8][4];
        #pragma unroll
        for (int mt = 0; mt < 2; mt++)
            #pragma unroll
            for (int nt = 0; nt < 8; nt++)
                #pragma unroll
                for (int i = 0; i < 4; i++) acc[mt][nt][i] = 0.f;

        #pragma unroll
        for (int ks = 0; ks < 8; ks++) {
            int kk = ks * 16;
            uint32_t a[2][4], b[8][2];
            #pragma unroll
            for (int mt = 0; mt < 2; mt++) {
                int row = wm * 32 + mt * 16 + g;
                a[mt][0] = *reinterpret_cast<const uint32_t*>(&As[row][kk + 2*q]);
                a[mt][1] = *reinterpret_cast<const uint32_t*>(&As[row + 8][kk + 2*q]);
                a[mt][2] = *reinterpret_cast<const uint32_t*>(&As[row][kk + 2*q + 8]);
                a[mt][3] = *reinterpret_cast<const uint32_t*>(&As[row + 8][kk + 2*q + 8]);
            }
            #pragma unroll
            for (int nt = 0; nt < 8; nt++) {
                int col = wn * 64 + nt * 8 + g;
                b[nt][0] = *reinterpret_cast<const uint32_t*>(&Bs[col][kk + 2*q]);
                b[nt][1] = *reinterpret_cast<const uint32_t*>(&Bs[col][kk + 2*q + 8]);
            }
            #pragma unroll
            for (int mt = 0; mt < 2; mt++)
                #pragma unroll
                for (int nt = 0; nt < 8; nt++)
                    mma_f16(acc[mt][nt], a[mt], b[nt]);
        }

        #pragma unroll
        for (int mt = 0; mt < 2; mt++)
            #pragma unroll
            for (int h = 0; h < 2; h++) {
                long row = m0 + wm * 32 + mt * 16 + g + h * 8;
                if (row >= M) continue;
                #pragma unroll
                for (int nt = 0; nt < 8; nt++) {
                    int col = wn * 64 + nt * 8 + q * 2;
                    *reinterpret_cast<__half2*>(&C[row * 128 + col]) =
                        __floats2half2_rn(acc[mt][nt][h*2], acc[mt][nt][h*2+1]);
                }
            }
    }
}

// -------- merged tf32 mini-GEMMs (4 weight products in one launch) --------

#define GSTAGE_A (128*36)
#define GSTAGE_B (32*136)
#define GSTAGE   (GSTAGE_A + GSTAGE_B)
#define GEMM_SMEM_BYTES (2*GSTAGE*4)

struct W4Args {
    const float* A[4];
    const float* B[4];
    __half* C[4];
};

__device__ __forceinline__ void mma_tf32(float* c, const uint32_t* a, const uint32_t* b) {
    asm volatile("mma.sync.aligned.m16n8k8.row.col.f32.tf32.tf32.f32 "
                 "{%0,%1,%2,%3}, {%4,%5,%6,%7}, {%8,%9}, {%0,%1,%2,%3};"
                 : "+f"(c[0]), "+f"(c[1]), "+f"(c[2]), "+f"(c[3])
                 : "r"(a[0]), "r"(a[1]), "r"(a[2]), "r"(a[3]), "r"(b[0]), "r"(b[1]));
}

__global__ __launch_bounds__(256) void gemm_w_tr4(W4Args args) {
    const float* A = args.A[blockIdx.x];
    const float* B = args.B[blockIdx.x];
    __half* C16t = args.C[blockIdx.x];
    extern __shared__ float smf[];
    int tid = threadIdx.x;
    int lane = tid & 31, wid = tid >> 5;
    int wm = wid & 3, wn = wid >> 2;
    int g = lane >> 2, q = lane & 3;

    float acc[2][8][4];
    #pragma unroll
    for (int mt = 0; mt < 2; mt++)
        #pragma unroll
        for (int nt = 0; nt < 8; nt++)
            #pragma unroll
            for (int i = 0; i < 4; i++) acc[mt][nt][i] = 0.f;

    int ar[4], ac_[4], br[4], bc[4];
    #pragma unroll
    for (int i = 0; i < 4; i++) {
        int idx = (tid + 256 * i) * 4;
        ar[i] = idx >> 5; ac_[i] = idx & 31;
        br[i] = idx >> 7; bc[i] = idx & 127;
    }

    auto prefetch = [&](int kc, int s) {
        float* As = smf + s * GSTAGE;
        float* Bs = As + GSTAGE_A;
        #pragma unroll
        for (int i = 0; i < 4; i++) {
            uint32_t sa = (uint32_t)__cvta_generic_to_shared(&As[ar[i]*36 + ac_[i]]);
            cp_async16(sa, A + ar[i] * 128 + kc * 32 + ac_[i], true);
        }
        #pragma unroll
        for (int i = 0; i < 4; i++) {
            uint32_t sb = (uint32_t)__cvta_generic_to_shared(&Bs[br[i]*136 + bc[i]]);
            cp_async16(sb, B + (kc * 32 + br[i]) * 128 + bc[i], true);
        }
        asm volatile("cp.async.commit_group;");
    };

    prefetch(0, 0);
    for (int kc = 0; kc < 4; kc++) {
        if (kc < 3) {
            prefetch(kc + 1, (kc + 1) & 1);
            asm volatile("cp.async.wait_group 1;");
        } else {
            asm volatile("cp.async.wait_group 0;");
        }
        __syncthreads();
        const uint32_t* As = reinterpret_cast<const uint32_t*>(smf + (kc & 1) * GSTAGE);
        const uint32_t* Bs = As + GSTAGE_A;
        #pragma unroll
        for (int ks = 0; ks < 4; ks++) {
            int kc8 = ks * 8;
            uint32_t a[2][4], b[8][2];
            #pragma unroll
            for (int mt = 0; mt < 2; mt++) {
                int row = wm * 32 + mt * 16 + g;
                a[mt][0] = As[row*36 + kc8 + q];
                a[mt][1] = As[(row+8)*36 + kc8 + q];
                a[mt][2] = As[row*36 + kc8 + q + 4];
                a[mt][3] = As[(row+8)*36 + kc8 + q + 4];
            }
            #pragma unroll
            for (int nt = 0; nt < 8; nt++) {
                int col = wn * 64 + nt * 8 + g;
                b[nt][0] = Bs[(kc8 + q)*136 + col];
                b[nt][1] = Bs[(kc8 + q + 4)*136 + col];
            }
            #pragma unroll
            for (int mt = 0; mt < 2; mt++)
                #pragma unroll
                for (int nt = 0; nt < 8; nt++)
                    mma_tf32(acc[mt][nt], a[mt], b[nt]);
        }
        __syncthreads();
    }

    #pragma unroll
    for (int mt = 0; mt < 2; mt++) {
        #pragma unroll
        for (int h = 0; h < 2; h++) {
            int row = wm * 32 + mt * 16 + g + h * 8;
            #pragma unroll
            for (int nt = 0; nt < 8; nt++) {
                int col = wn * 64 + nt * 8 + q * 2;
                C16t[(long)col * 128 + row]       = __float2half(acc[mt][nt][h*2]);
                C16t[(long)(col + 1) * 128 + row] = __float2half(acc[mt][nt][h*2+1]);
            }
        }
    }
}

// -------- host --------

extern "C" void kernel_launch(void* const* d_in, const int* in_sizes, int n_in,
                              void* d_out, int out_size) {
    const float* e_emb = (const float*)d_in[1];
    const int* node_ind = (const int*)d_in[26];
    const int* edge_src = (const int*)d_in[27];
    const int* edge_dst = (const int*)d_in[28];

    float *feat, *inv, *gscale, *colstats;
    __half *feat16, *t1h, *t2h, *keyh, *skah, *vh, *t2ch, *w16, *wqa16, *wka16;
    int *cnt, *offs, *fill, *partial, *ssrc;
    cudaGetSymbolAddress((void**)&feat, g_feat);
    cudaGetSymbolAddress((void**)&feat16, g_feat16);
    cudaGetSymbolAddress((void**)&t1h, g_t1h);
    cudaGetSymbolAddress((void**)&t2h, g_t2h);
    cudaGetSymbolAddress((void**)&keyh, g_keyh);
    cudaGetSymbolAddress((void**)&skah, g_skah);
    cudaGetSymbolAddress((void**)&vh, g_vh);
    cudaGetSymbolAddress((void**)&t2ch, g_t2ch);
    cudaGetSymbolAddress((void**)&w16, g_w16);
    cudaGetSymbolAddress((void**)&wqa16, g_wqa16);
    cudaGetSymbolAddress((void**)&wka16, g_wka16);
    cudaGetSymbolAddress((void**)&cnt, g_cnt);
    cudaGetSymbolAddress((void**)&offs, g_offs);
    cudaGetSymbolAddress((void**)&fill, g_fill);
    cudaGetSymbolAddress((void**)&partial, g_partial);
    cudaGetSymbolAddress((void**)&ssrc, g_ssrc);
    cudaGetSymbolAddress((void**)&inv, g_inv);
    cudaGetSymbolAddress((void**)&gscale, g_gscale);
    cudaGetSymbolAddress((void**)&colstats, g_colstats);

    cudaFuncSetAttribute(gemm_w_tr4, cudaFuncAttributeMaxDynamicSharedMemorySize, GEMM_SMEM_BYTES);
    cudaFuncSetAttribute(gemm_seq2, cudaFuncAttributeMaxDynamicSharedMemorySize, (int)SEQ_SMEM_BYTES);
    cudaFuncSetAttribute((const void*)gemm16<0,1,0>, cudaFuncAttributeMaxDynamicSharedMemorySize, (int)G16_SMEM_BYTES);
    cudaFuncSetAttribute((const void*)gemm16<1,0,1>, cudaFuncAttributeMaxDynamicSharedMemorySize, (int)G16_SMEM_BYTES);
    cudaFuncSetAttribute((const void*)gemm16<1,0,0>, cudaFuncAttributeMaxDynamicSharedMemorySize, (int)G16_SMEM_BYTES);
    cudaFuncSetAttribute((const void*)gemm16<2,0,0>, cudaFuncAttributeMaxDynamicSharedMemorySize, (int)G16_SMEM_BYTES);
    cudaFuncSetAttribute((const void*)gemm16<3,0,0>, cudaFuncAttributeMaxDynamicSharedMemorySize, (int)G16_SMEM_BYTES);

    const int TPB = 256;
    const int ND4_BLK = (ND4 + TPB - 1) / TPB;
    const int E_BLK = (TT*EE + TPB - 1) / TPB;
    const int GCNW_BLK = (NN*32 + TPB - 1) / TPB;
    const int ATTW_BLK = (TNN*32 + TPB - 1) / TPB;
    const int G1 = (NN + 127) / 128;
    const int G3 = (TNN + 127) / 128;

    convert_wt8_k<<<(8*DD*DD + TPB - 1)/TPB, TPB>>>(
        (const float*)d_in[2],  (const float*)d_in[5],  (const float*)d_in[9],  (const float*)d_in[12],
        (const float*)d_in[14], (const float*)d_in[17], (const float*)d_in[21], (const float*)d_in[24],
        w16);

    W4Args wargs;
    wargs.A[0] = (const float*)d_in[7];  wargs.B[0] = (const float*)d_in[10]; wargs.C[0] = wqa16;
    wargs.A[1] = (const float*)d_in[8];  wargs.B[1] = (const float*)d_in[10]; wargs.C[1] = wka16;
    wargs.A[2] = (const float*)d_in[19]; wargs.B[2] = (const float*)d_in[22]; wargs.C[2] = wqa16 + DD*DD;
    wargs.A[3] = (const float*)d_in[20]; wargs.B[3] = (const float*)d_in[22]; wargs.C[3] = wka16 + DD*DD;
    gemm_w_tr4<<<4, 256, GEMM_SMEM_BYTES>>>(wargs);

    cudaMemsetAsync(cnt, 0, TNN*sizeof(int), 0);
    cudaMemsetAsync(fill, 0, TNN*sizeof(int), 0);
    count_k<<<E_BLK, TPB>>>(edge_dst, cnt);
    prep_k<<<(NN + TPB - 1)/TPB, TPB>>>(cnt, inv, gscale);
    scan_block_k<<<NB_SCAN, 256>>>(cnt, offs, partial);
    scan_partial_k<<<1, 256>>>(partial);
    scan_add_k<<<NB_SCAN, 256>>>(offs, partial);
    scatter_k<<<E_BLK, TPB>>>(edge_src, edge_dst, offs, fill, ssrc);
    gather_feat_k<<<ND4_BLK, TPB>>>((const float*)d_in[0], node_ind, feat, feat16);

    const float* gcn_gamma[2] = {(const float*)d_in[3],  (const float*)d_in[15]};
    const float* gcn_beta[2]  = {(const float*)d_in[4],  (const float*)d_in[16]};
    const float* gcn_b2[2]    = {(const float*)d_in[6],  (const float*)d_in[18]};
    const float* at_bp[2]     = {(const float*)d_in[13], (const float*)d_in[25]};

    for (int L = 0; L < 2; L++) {
        const __half* w1t = w16 + (size_t)(L*4 + 0) * DD * DD;
        const __half* w2t = w16 + (size_t)(L*4 + 1) * DD * DD;
        const __half* wvt = w16 + (size_t)(L*4 + 2) * DD * DD;
        const __half* wpt = w16 + (size_t)(L*4 + 3) * DD * DD;
        const __half* wqaL = wqa16 + (size_t)L * DD * DD;
        const __half* wkaL = wka16 + (size_t)L * DD * DD;

        // ---- GCN layer ----
        cudaMemsetAsync(colstats, 0, 2*DD*sizeof(float), 0);
        gcn_edge_sorted<<<GCNW_BLK, TPB>>>(feat16, e_emb, ssrc, offs, cnt, inv, gscale, t1h);
        gemm16<0,1,0><<<G1, 256, G16_SMEM_BYTES>>>(t1h, w1t, t2h, NN, nullptr, nullptr, nullptr,
                                                   nullptr, nullptr, nullptr, nullptr, nullptr, colstats);
        gemm16<1,0,1><<<G1, 256, G16_SMEM_BYTES>>>(t2h, w2t, nullptr, NN, gcn_b2[L], feat, feat16,
                                                   nullptr, nullptr, nullptr, gcn_gamma[L], gcn_beta[L], colstats);

        // ---- Attention layer ----
        attn_edge_sorted<<<ATTW_BLK, TPB>>>(feat16, e_emb, ssrc, offs, cnt, inv, keyh);
        gemm_seq2<<<G3, 256, SEQ_SMEM_BYTES>>>(keyh, wkaL, wvt, skah, vh, TNN);
        gemm16<2,0,0><<<G1, 256, G16_SMEM_BYTES>>>(feat16, wqaL, t2ch, NN, nullptr, nullptr, nullptr,
                                                   skah, vh, nullptr, nullptr, nullptr, nullptr);
        if (L == 0) {
            gemm16<1,0,0><<<G1, 256, G16_SMEM_BYTES>>>(t2ch, wpt, nullptr, NN, at_bp[L], feat, feat16,
                                                       nullptr, nullptr, nullptr, nullptr, nullptr, nullptr);
        } else {
            gemm16<3,0,0><<<G1, 256, G16_SMEM_BYTES>>>(t2ch, wpt, nullptr, NN, at_bp[L], feat, nullptr,
                                                       nullptr, nullptr, (float*)d_out, nullptr, nullptr, nullptr);
        }
    }

    if (out_size >= ND + TT*DD) {
        cudaMemcpyAsync((float*)d_out + ND, e_emb, TT*DD*sizeof(float),
                        cudaMemcpyDeviceToDevice, 0);
    }
}

// round 15
// speedup vs baseline: 1.5013x; 1.0189x over previous
#include <cuda_runtime.h>
#include <cuda_fp16.h>
#include <cstdint>
#include <math.h>

#define NN 100000
#define DD 128
#define EE 250000
#define TT 3
#define ND (NN*DD)
#define ND4 (ND/4)
#define TNN (TT*NN)
#define NB_SCAN ((TNN + 255) / 256)
#define SCHUNK ((NB_SCAN + 255) / 256)

// -------- scratch --------
__device__ float  g_feat[ND];
__device__ __half g_feat16[ND];
__device__ __half g_t1h[ND];
__device__ __half g_t2h[ND];
__device__ __half g_keyh[3*ND];
__device__ __half g_skah[3*ND];
__device__ __half g_vh[3*ND];
__device__ __half g_w16[8][DD*DD];
__device__ __half g_wqa16[2][DD*DD];
__device__ __half g_wka16[2][DD*DD];
__device__ int    g_cnt[TNN];
__device__ int    g_offs[TNN];
__device__ int    g_fill[TNN];
__device__ int    g_partial[NB_SCAN];
__device__ int    g_ssrc[TT*EE];
__device__ float  g_inv[TNN];
__device__ float  g_gscale[NN];
__device__ float  g_colstats[2*DD];

// -------- setup kernels --------

__global__ void gather_feat_k(const float* __restrict__ n_emb, const int* __restrict__ ind,
                              float* __restrict__ feat, __half* __restrict__ feat16) {
    int idx = blockIdx.x * blockDim.x + threadIdx.x;
    if (idx >= ND4) return;
    int n = idx >> 5;
    float4 v = reinterpret_cast<const float4*>(n_emb)[(long)ind[n] * 32 + (idx & 31)];
    reinterpret_cast<float4*>(feat)[idx] = v;
    __half2* h = reinterpret_cast<__half2*>(feat16) + idx * 2;
    h[0] = __floats2half2_rn(v.x, v.y);
    h[1] = __floats2half2_rn(v.z, v.w);
}

__global__ void convert_wt8_k(const float* w0, const float* w1, const float* w2, const float* w3,
                              const float* w4, const float* w5, const float* w6, const float* w7,
                              __half* __restrict__ wt) {
    int i = blockIdx.x * blockDim.x + threadIdx.x;
    if (i >= 8*DD*DD) return;
    const float* ws[8] = {w0, w1, w2, w3, w4, w5, w6, w7};
    int m = i >> 14;
    int j = i & (DD*DD - 1);
    int n = j >> 7, k = j & 127;
    wt[(size_t)m * DD * DD + n * 128 + k] = __float2half(ws[m][k * 128 + n]);
}

__global__ void count_k(const int* __restrict__ dst, int* __restrict__ cnt) {
    int e = blockIdx.x * blockDim.x + threadIdx.x;
    if (e >= TT*EE) return;
    int t = e / EE;
    atomicAdd(&cnt[t * NN + dst[e]], 1);
}

__global__ void prep_k(const int* __restrict__ cnt, float* __restrict__ inv,
                       float* __restrict__ gscale) {
    int n = blockIdx.x * blockDim.x + threadIdx.x;
    if (n >= NN) return;
    int c0 = cnt[n], c1 = cnt[NN + n], c2 = cnt[2*NN + n];
    inv[n]        = 1.f / (float)max(c0, 1);
    inv[NN + n]   = 1.f / (float)max(c1, 1);
    inv[2*NN + n] = 1.f / (float)max(c2, 1);
    gscale[n] = (float)((c0 > 0) + (c1 > 0) + (c2 > 0));
}

__global__ void scan_block_k(const int* __restrict__ cnt, int* __restrict__ offs,
                             int* __restrict__ partial) {
    __shared__ int sh[256];
    int tid = threadIdx.x;
    int i = blockIdx.x * 256 + tid;
    int v = (i < TNN) ? cnt[i] : 0;
    sh[tid] = v; __syncthreads();
    #pragma unroll
    for (int off = 1; off < 256; off <<= 1) {
        int x = (tid >= off) ? sh[tid - off] : 0;
        __syncthreads();
        sh[tid] += x;
        __syncthreads();
    }
    if (i < TNN) offs[i] = sh[tid] - v;
    if (tid == 255) partial[blockIdx.x] = sh[tid];
}

__global__ void scan_partial_k(int* __restrict__ partial) {
    __shared__ int sh[256];
    int tid = threadIdx.x;
    int base = tid * SCHUNK;
    int loc[SCHUNK];
    int s = 0;
    #pragma unroll
    for (int j = 0; j < SCHUNK; j++) {
        int idx = base + j;
        int v = (idx < NB_SCAN) ? partial[idx] : 0;
        loc[j] = s; s += v;
    }
    sh[tid] = s; __syncthreads();
    #pragma unroll
    for (int off = 1; off < 256; off <<= 1) {
        int x = (tid >= off) ? sh[tid - off] : 0;
        __syncthreads();
        sh[tid] += x;
        __syncthreads();
    }
    int excl = sh[tid] - s;
    #pragma unroll
    for (int j = 0; j < SCHUNK; j++) {
        int idx = base + j;
        if (idx < NB_SCAN) partial[idx] = excl + loc[j];
    }
}

__global__ void scan_add_k(int* __restrict__ offs, const int* __restrict__ partial) {
    int i = blockIdx.x * 256 + threadIdx.x;
    if (i < TNN) offs[i] += partial[blockIdx.x];
}

__global__ void scatter_k(const int* __restrict__ src, const int* __restrict__ dst,
                          const int* __restrict__ offs, int* __restrict__ fill,
                          int* __restrict__ ssrc) {
    int e = blockIdx.x * blockDim.x + threadIdx.x;
    if (e >= TT*EE) return;
    int t = e / EE;
    int td = t * NN + dst[e];
    int pos = offs[td] + atomicAdd(&fill[td], 1);
    ssrc[pos] = src[e];
}

// -------- fp16 helpers --------

__device__ __forceinline__ void h4_to_f4(uint2 u, float4& f) {
    __half2 h0 = *reinterpret_cast<__half2*>(&u.x);
    __half2 h1 = *reinterpret_cast<__half2*>(&u.y);
    float2 a = __half22float2(h0), b = __half22float2(h1);
    f.x = a.x; f.y = a.y; f.z = b.x; f.w = b.y;
}

__device__ __forceinline__ uint2 f4_to_h4(float4 f) {
    __half2 h0 = __floats2half2_rn(f.x, f.y);
    __half2 h1 = __floats2half2_rn(f.z, f.w);
    uint2 u;
    u.x = *reinterpret_cast<uint32_t*>(&h0);
    u.y = *reinterpret_cast<uint32_t*>(&h1);
    return u;
}

// -------- sorted edge passes --------

__global__ void gcn_edge_sorted(const __half* __restrict__ feat16, const float* __restrict__ emb,
                                const int* __restrict__ ssrc, const int* __restrict__ offs,
                                const int* __restrict__ cnt, const float* __restrict__ inv,
                                const float* __restrict__ gscale, __half* __restrict__ out) {
    int gw = (blockIdx.x * blockDim.x + threadIdx.x) >> 5;
    int lane = threadIdx.x & 31;
    if (gw >= NN) return;
    const uint2* f16 = reinterpret_cast<const uint2*>(feat16);
    float4 a; h4_to_f4(f16[gw * 32 + lane], a);
    float gs = gscale[gw];
    float4 acc = make_float4(a.x * gs, a.y * gs, a.z * gs, a.w * gs);
    #pragma unroll
    for (int t = 0; t < TT; t++) {
        int td = t * NN + gw;
        int len = cnt[td];
        if (len == 0) continue;
        int beg = offs[td];
        float4 s = make_float4(0.f, 0.f, 0.f, 0.f);
        for (int i = 0; i < len; i++) {
            int sn = ssrc[beg + i];
            float4 f; h4_to_f4(f16[sn * 32 + lane], f);
            s.x += f.x; s.y += f.y; s.z += f.z; s.w += f.w;
        }
        float4 e = reinterpret_cast<const float4*>(emb)[t * 32 + lane];
        float w = inv[td];
        acc.x -= s.x * e.x * w; acc.y -= s.y * e.y * w;
        acc.z -= s.z * e.z * w; acc.w -= s.w * e.w * w;
    }
    reinterpret_cast<uint2*>(out)[gw * 32 + lane] = f4_to_h4(acc);
}

__global__ void attn_edge_sorted(const __half* __restrict__ feat16, const float* __restrict__ emb,
                                 const int* __restrict__ ssrc, const int* __restrict__ offs,
                                 const int* __restrict__ cnt, const float* __restrict__ inv,
                                 __half* __restrict__ key) {
    int gw = (blockIdx.x * blockDim.x + threadIdx.x) >> 5;
    int lane = threadIdx.x & 31;
    if (gw >= TNN) return;
    int t = gw / NN;
    int len = cnt[gw];
    int beg = offs[gw];
    const uint2* f16 = reinterpret_cast<const uint2*>(feat16);
    float4 s = make_float4(0.f, 0.f, 0.f, 0.f);
    for (int i = 0; i < len; i++) {
        int sn = ssrc[beg + i];
        float4 f; h4_to_f4(f16[sn * 32 + lane], f);
        s.x += f.x; s.y += f.y; s.z += f.z; s.w += f.w;
    }
    float4 e = reinterpret_cast<const float4*>(emb)[t * 32 + lane];
    float w = inv[gw];
    reinterpret_cast<uint2*>(key)[(long)gw * 32 + lane] =
        f4_to_h4(make_float4(s.x*e.x*w, s.y*e.y*w, s.z*e.z*w, s.w*e.w*w));
}

// -------- common GEMM bits --------

#define G16_SMEM_BYTES ((size_t)2 * 128 * 136 * 2)

__device__ __forceinline__ void cp_async16(uint32_t saddr, const void* gptr, bool pred) {
    int sz = pred ? 16 : 0;
    asm volatile("cp.async.ca.shared.global [%0], [%1], 16, %2;"
                 :: "r"(saddr), "l"(gptr), "r"(sz));
}

__device__ __forceinline__ void mma_f16(float* c, const uint32_t* a, const uint32_t* b) {
    asm volatile("mma.sync.aligned.m16n8k16.row.col.f32.f16.f16.f32 "
                 "{%0,%1,%2,%3}, {%4,%5,%6,%7}, {%8,%9}, {%0,%1,%2,%3};"
                 : "+f"(c[0]), "+f"(c[1]), "+f"(c[2]), "+f"(c[3])
                 : "r"(a[0]), "r"(a[1]), "r"(a[2]), "r"(a[3]), "r"(b[0]), "r"(b[1]));
}

// -------- fp16 GEMM (full-stage): GCN path --------
// EPI 0: store. EPI 1: featf += acc + bias; refresh feat16.
// STATS 1: col stats into colstats. ABN 1: BN+ReLU on A-staging.

template<int EPI, int STATS, int ABN>
__global__ __launch_bounds__(256, 2) void gemm16(const __half* __restrict__ A,
                                                 const __half* __restrict__ Bt,
                                                 __half* __restrict__ C16, int M,
                                                 const float* __restrict__ bias,
                                                 float* __restrict__ featf,
                                                 __half* __restrict__ feat16,
                                                 const float* __restrict__ gamma,
                                                 const float* __restrict__ beta,
                                                 float* __restrict__ colstats) {
    extern __shared__ __half shh[];
    __half (*As)[136] = reinterpret_cast<__half(*)[136]>(shh);
    __half (*Bs)[136] = reinterpret_cast<__half(*)[136]>(shh + 128*136);
    __shared__ float bnm[128], bns[128], bnb[128];
    int tid = threadIdx.x;
    int lane = tid & 31, wid = tid >> 5;
    int wm = wid & 3, wn = wid >> 2;
    int g = lane >> 2, q = lane & 3;
    long m0 = (long)blockIdx.x * 128;

    if (ABN && tid < 128) {
        const float invN = 1.f / (float)NN;
        float mean = colstats[tid] * invN;
        float var  = colstats[128 + tid] * invN - mean * mean;
        bnm[tid] = mean;
        bns[tid] = rsqrtf(var + 1e-5f) * gamma[tid];
        bnb[tid] = beta[tid];
    }

    #pragma unroll
    for (int i = 0; i < 8; i++) {
        int v = tid + 256 * i;
        int r = v >> 4, kv = (v & 15) * 8;
        uint32_t sb = (uint32_t)__cvta_generic_to_shared(&Bs[r][kv]);
        cp_async16(sb, Bt + r * 128 + kv, true);
    }
    if (!ABN) {
        #pragma unroll
        for (int i = 0; i < 8; i++) {
            int v = tid + 256 * i;
            int r = v >> 4, kv = (v & 15) * 8;
            long row = m0 + r;
            uint32_t sa = (uint32_t)__cvta_generic_to_shared(&As[r][kv]);
            cp_async16(sa, A + row * 128 + kv, row < M);
        }
        asm volatile("cp.async.commit_group;");
        asm volatile("cp.async.wait_group 0;");
        __syncthreads();
    } else {
        asm volatile("cp.async.commit_group;");
        #pragma unroll
        for (int batch = 0; batch < 2; batch++) {
            uint4 av[4];
            #pragma unroll
            for (int i = 0; i < 4; i++) {
                int v = tid + 256 * (batch * 4 + i);
                int r = v >> 4, kv = (v & 15) * 8;
                long row = m0 + r;
                av[i] = (row < M) ? *reinterpret_cast<const uint4*>(A + row * 128 + kv)
                                  : make_uint4(0u, 0u, 0u, 0u);
            }
            if (batch == 0) __syncthreads();
            #pragma unroll
            for (int i = 0; i < 4; i++) {
                int v = tid + 256 * (batch * 4 + i);
                int r = v >> 4, kv = (v & 15) * 8;
                uint32_t* u = &av[i].x;
                uint4 ov;
                uint32_t* o = &ov.x;
                #pragma unroll
                for (int j = 0; j < 4; j++) {
                    __half2 hv = *reinterpret_cast<__half2*>(&u[j]);
                    float2 f = __half22float2(hv);
                    int c0 = kv + 2*j;
                    f.x = fmaxf((f.x - bnm[c0])   * bns[c0]   + bnb[c0],   0.f);
                    f.y = fmaxf((f.y - bnm[c0+1]) * bns[c0+1] + bnb[c0+1], 0.f);
                    __half2 hr = __floats2half2_rn(f.x, f.y);
                    o[j] = *reinterpret_cast<uint32_t*>(&hr);
                }
                *reinterpret_cast<uint4*>(&As[r][kv]) = ov;
            }
        }
        asm volatile("cp.async.wait_group 0;");
        __syncthreads();
    }

    float acc[2][8][4];
    #pragma unroll
    for (int mt = 0; mt < 2; mt++)
        #pragma unroll
        for (int nt = 0; nt < 8; nt++)
            #pragma unroll
            for (int i = 0; i < 4; i++) acc[mt][nt][i] = 0.f;

    #pragma unroll
    for (int ks = 0; ks < 8; ks++) {
        int kk = ks * 16;
        uint32_t a[2][4], b[8][2];
        #pragma unroll
        for (int mt = 0; mt < 2; mt++) {
            int row = wm * 32 + mt * 16 + g;
            a[mt][0] = *reinterpret_cast<const uint32_t*>(&As[row][kk + 2*q]);
            a[mt][1] = *reinterpret_cast<const uint32_t*>(&As[row + 8][kk + 2*q]);
            a[mt][2] = *reinterpret_cast<const uint32_t*>(&As[row][kk + 2*q + 8]);
            a[mt][3] = *reinterpret_cast<const uint32_t*>(&As[row + 8][kk + 2*q + 8]);
        }
        #pragma unroll
        for (int nt = 0; nt < 8; nt++) {
            int col = wn * 64 + nt * 8 + g;
            b[nt][0] = *reinterpret_cast<const uint32_t*>(&Bs[col][kk + 2*q]);
            b[nt][1] = *reinterpret_cast<const uint32_t*>(&Bs[col][kk + 2*q + 8]);
        }
        #pragma unroll
        for (int mt = 0; mt < 2; mt++)
            #pragma unroll
            for (int nt = 0; nt < 8; nt++)
                mma_f16(acc[mt][nt], a[mt], b[nt]);
    }

    #pragma unroll
    for (int mt = 0; mt < 2; mt++) {
        #pragma unroll
        for (int h = 0; h < 2; h++) {
            long row = m0 + wm * 32 + mt * 16 + g + h * 8;
            if (row >= M) continue;
            #pragma unroll
            for (int nt = 0; nt < 8; nt++) {
                int col = wn * 64 + nt * 8 + q * 2;
                long base = row * 128 + col;
                float v0 = acc[mt][nt][h * 2], v1 = acc[mt][nt][h * 2 + 1];
                if (EPI == 0) {
                    *reinterpret_cast<__half2*>(&C16[base]) = __floats2half2_rn(v0, v1);
                } else {
                    float2 prev = *reinterpret_cast<const float2*>(&featf[base]);
                    float n0 = prev.x + v0 + bias[col];
                    float n1 = prev.y + v1 + bias[col + 1];
                    *reinterpret_cast<float2*>(&featf[base]) = make_float2(n0, n1);
                    *reinterpret_cast<__half2*>(&feat16[base]) = __floats2half2_rn(n0, n1);
                }
            }
        }
    }

    if (STATS) {
        #pragma unroll
        for (int nt = 0; nt < 8; nt++) {
            float s0 = 0.f, q0 = 0.f, s1 = 0.f, q1 = 0.f;
            #pragma unroll
            for (int mt = 0; mt < 2; mt++)
                #pragma unroll
                for (int h = 0; h < 2; h++) {
                    float v0 = acc[mt][nt][h*2], v1 = acc[mt][nt][h*2+1];
                    s0 += v0; q0 += v0*v0; s1 += v1; q1 += v1*v1;
                }
            #pragma unroll
            for (int off = 4; off < 32; off <<= 1) {
                s0 += __shfl_xor_sync(0xffffffffu, s0, off);
                q0 += __shfl_xor_sync(0xffffffffu, q0, off);
                s1 += __shfl_xor_sync(0xffffffffu, s1, off);
                q1 += __shfl_xor_sync(0xffffffffu, q1, off);
            }
            if (g == 0) {
                int col = wn * 64 + nt * 8 + q * 2;
                atomicAdd(&colstats[col], s0);
                atomicAdd(&colstats[128 + col], q0);
                atomicAdd(&colstats[col + 1], s1);
                atomicAdd(&colstats[128 + col + 1], q1);
            }
        }
    }
}

// -------- fused attention output: qa-GEMM → softmax-combine (into smem) → wp-GEMM --------
// FIN 0: featf += acc2 + bias; refresh feat16.   FIN 1: fout = featf + acc2 + bias.

template<int FIN>
__global__ __launch_bounds__(256, 2) void gemm_attn_out(
    const __half* __restrict__ A,        // feat16
    const __half* __restrict__ Bq,       // wqa^T
    const __half* __restrict__ Bp,       // wp^T
    int M,
    const float* __restrict__ bias,
    float* __restrict__ featf,
    __half* __restrict__ feat16,
    const __half* __restrict__ ska,
    const __half* __restrict__ vv,
    float* __restrict__ fout) {
    extern __shared__ __half shh[];
    __half (*As)[136] = reinterpret_cast<__half(*)[136]>(shh);
    __half (*Bs)[136] = reinterpret_cast<__half(*)[136]>(shh + 128*136);
    int tid = threadIdx.x;
    int lane = tid & 31, wid = tid >> 5;
    int wm = wid & 3, wn = wid >> 2;
    int g = lane >> 2, q = lane & 3;
    long m0 = (long)blockIdx.x * 128;

    // stage A=feat16 rows, Bs=wqa
    #pragma unroll
    for (int i = 0; i < 8; i++) {
        int v = tid + 256 * i;
        int r = v >> 4, kv = (v & 15) * 8;
        long row = m0 + r;
        uint32_t sa = (uint32_t)__cvta_generic_to_shared(&As[r][kv]);
        cp_async16(sa, A + row * 128 + kv, row < M);
        uint32_t sb = (uint32_t)__cvta_generic_to_shared(&Bs[r][kv]);
        cp_async16(sb, Bq + r * 128 + kv, true);
    }
    asm volatile("cp.async.commit_group;");
    asm volatile("cp.async.wait_group 0;");
    __syncthreads();

    float acc[2][8][4];
    #pragma unroll
    for (int mt = 0; mt < 2; mt++)
        #pragma unroll
        for (int nt = 0; nt < 8; nt++)
            #pragma unroll
            for (int i = 0; i < 4; i++) acc[mt][nt][i] = 0.f;

    // mainloop 1: qa = feat16 @ wqa^T
    #pragma unroll
    for (int ks = 0; ks < 8; ks++) {
        int kk = ks * 16;
        uint32_t a[2][4], b[8][2];
        #pragma unroll
        for (int mt = 0; mt < 2; mt++) {
            int row = wm * 32 + mt * 16 + g;
            a[mt][0] = *reinterpret_cast<const uint32_t*>(&As[row][kk + 2*q]);
            a[mt][1] = *reinterpret_cast<const uint32_t*>(&As[row + 8][kk + 2*q]);
            a[mt][2] = *reinterpret_cast<const uint32_t*>(&As[row][kk + 2*q + 8]);
            a[mt][3] = *reinterpret_cast<const uint32_t*>(&As[row + 8][kk + 2*q + 8]);
        }
        #pragma unroll
        for (int nt = 0; nt < 8; nt++) {
            int col = wn * 64 + nt * 8 + g;
            b[nt][0] = *reinterpret_cast<const uint32_t*>(&Bs[col][kk + 2*q]);
            b[nt][1] = *reinterpret_cast<const uint32_t*>(&Bs[col][kk + 2*q + 8]);
        }
        #pragma unroll
        for (int mt = 0; mt < 2; mt++)
            #pragma unroll
            for (int nt = 0; nt < 8; nt++)
                mma_f16(acc[mt][nt], a[mt], b[nt]);
    }
    __syncthreads();   // all smem reads of phase 1 done

    // kick wp staging into Bs (overlaps with combine math below)
    #pragma unroll
    for (int i = 0; i < 8; i++) {
        int v = tid + 256 * i;
        int r = v >> 4, kv = (v & 15) * 8;
        uint32_t sb = (uint32_t)__cvta_generic_to_shared(&Bs[r][kv]);
        cp_async16(sb, Bp + r * 128 + kv, true);
    }
    asm volatile("cp.async.commit_group;");

    // softmax-combine: acc(qa) + ska/vv → fp16 into As (A-layout for mainloop 2)
    #pragma unroll
    for (int mt = 0; mt < 2; mt++) {
        #pragma unroll
        for (int h = 0; h < 2; h++) {
            int rloc = wm * 32 + mt * 16 + g + h * 8;
            long row = m0 + rloc;
            bool ok = row < M;
            #pragma unroll
            for (int nt = 0; nt < 8; nt++) {
                int col = wn * 64 + nt * 8 + q * 2;
                long base = row * 128 + col;
                float o0 = 0.f, o1 = 0.f;
                if (ok) {
                    float v0 = acc[mt][nt][h * 2], v1 = acc[mt][nt][h * 2 + 1];
                    float2 s0 = __half22float2(*reinterpret_cast<const __half2*>(ska + base));
                    float2 s1 = __half22float2(*reinterpret_cast<const __half2*>(ska + base + (long)ND));
                    float2 s2 = __half22float2(*reinterpret_cast<const __half2*>(ska + base + 2L*ND));
                    float2 w0 = __half22float2(*reinterpret_cast<const __half2*>(vv + base));
                    float2 w1 = __half22float2(*reinterpret_cast<const __half2*>(vv + base + (long)ND));
                    float2 w2 = __half22float2(*reinterpret_cast<const __half2*>(vv + base + 2L*ND));
                    {
                        float l0 = v0 - s0.x, l1 = v0 - s1.x, l2 = v0 - s2.x;
                        float mx = fmaxf(l0, fmaxf(l1, l2));
                        float e0 = __expf(l0-mx), e1 = __expf(l1-mx), e2 = __expf(l2-mx);
                        o0 = (e0*w0.x + e1*w1.x + e2*w2.x) / (e0 + e1 + e2);
                    }
                    {
                        float l0 = v1 - s0.y, l1 = v1 - s1.y, l2 = v1 - s2.y;
                        float mx = fmaxf(l0, fmaxf(l1, l2));
                        float e0 = __expf(l0-mx), e1 = __expf(l1-mx), e2 = __expf(l2-mx);
                        o1 = (e0*w0.y + e1*w1.y + e2*w2.y) / (e0 + e1 + e2);
                    }
                }
                *reinterpret_cast<__half2*>(&As[rloc][col]) = __floats2half2_rn(o0, o1);
            }
        }
    }
    asm volatile("cp.async.wait_group 0;");
    __syncthreads();

    // mainloop 2: out = combined @ wp^T
    #pragma unroll
    for (int mt = 0; mt < 2; mt++)
        #pragma unroll
        for (int nt = 0; nt < 8; nt++)
            #pragma unroll
            for (int i = 0; i < 4; i++) acc[mt][nt][i] = 0.f;

    #pragma unroll
    for (int ks = 0; ks < 8; ks++) {
        int kk = ks * 16;
        uint32_t a[2][4], b[8][2];
        #pragma unroll
        for (int mt = 0; mt < 2; mt++) {
            int row = wm * 32 + mt * 16 + g;
            a[mt][0] = *reinterpret_cast<const uint32_t*>(&As[row][kk + 2*q]);
            a[mt][1] = *reinterpret_cast<const uint32_t*>(&As[row + 8][kk + 2*q]);
            a[mt][2] = *reinterpret_cast<const uint32_t*>(&As[row][kk + 2*q + 8]);
            a[mt][3] = *reinterpret_cast<const uint32_t*>(&As[row + 8][kk + 2*q + 8]);
        }
        #pragma unroll
        for (int nt = 0; nt < 8; nt++) {
            int col = wn * 64 + nt * 8 + g;
            b[nt][0] = *reinterpret_cast<const uint32_t*>(&Bs[col][kk + 2*q]);
            b[nt][1] = *reinterpret_cast<const uint32_t*>(&Bs[col][kk + 2*q + 8]);
        }
        #pragma unroll
        for (int mt = 0; mt < 2; mt++)
            #pragma unroll
            for (int nt = 0; nt < 8; nt++)
                mma_f16(acc[mt][nt], a[mt], b[nt]);
    }

    #pragma unroll
    for (int mt = 0; mt < 2; mt++) {
        #pragma unroll
        for (int h = 0; h < 2; h++) {
            long row = m0 + wm * 32 + mt * 16 + g + h * 8;
            if (row >= M) continue;
            #pragma unroll
            for (int nt = 0; nt < 8; nt++) {
                int col = wn * 64 + nt * 8 + q * 2;
                long base = row * 128 + col;
                float v0 = acc[mt][nt][h * 2], v1 = acc[mt][nt][h * 2 + 1];
                float2 prev = *reinterpret_cast<const float2*>(&featf[base]);
                float n0 = prev.x + v0 + bias[col];
                float n1 = prev.y + v1 + bias[col + 1];
                if (FIN == 0) {
                    *reinterpret_cast<float2*>(&featf[base]) = make_float2(n0, n1);
                    *reinterpret_cast<__half2*>(&feat16[base]) = __floats2half2_rn(n0, n1);
                } else {
                    *reinterpret_cast<float2*>(&fout[base]) = make_float2(n0, n1);
                }
            }
        }
    }
}

// Sequential-dual GEMM (unchanged)
#define SEQ_SMEM_BYTES ((size_t)3 * 128 * 136 * 2)

__global__ __launch_bounds__(256, 2) void gemm_seq2(const __half* __restrict__ A,
                                                    const __half* __restrict__ B1t,
                                                    const __half* __restrict__ B2t,
                                                    __half* __restrict__ C1,
                                                    __half* __restrict__ C2, int M) {
    extern __shared__ __half sh[];
    __half (*As)[136]  = reinterpret_cast<__half(*)[136]>(sh);
    __half (*Bs1)[136] = reinterpret_cast<__half(*)[136]>(sh + 128*136);
    __half (*Bs2)[136] = reinterpret_cast<__half(*)[136]>(sh + 2*128*136);
    int tid = threadIdx.x;
    int lane = tid & 31, wid = tid >> 5;
    int wm = wid & 3, wn = wid >> 2;
    int g = lane >> 2, q = lane & 3;
    long m0 = (long)blockIdx.x * 128;

    #pragma unroll
    for (int i = 0; i < 8; i++) {
        int v = tid + 256 * i;
        int r = v >> 4, kv = (v & 15) * 8;
        long row = m0 + r;
        uint32_t sa = (uint32_t)__cvta_generic_to_shared(&As[r][kv]);
        cp_async16(sa, A + row * 128 + kv, row < M);
        uint32_t s1 = (uint32_t)__cvta_generic_to_shared(&Bs1[r][kv]);
        cp_async16(s1, B1t + r * 128 + kv, true);
        uint32_t s2 = (uint32_t)__cvta_generic_to_shared(&Bs2[r][kv]);
        cp_async16(s2, B2t + r * 128 + kv, true);
    }
    asm volatile("cp.async.commit_group;");
    asm volatile("cp.async.wait_group 0;");
    __syncthreads();

    #pragma unroll
    for (int pass = 0; pass < 2; pass++) {
        __half (*Bs)[136] = pass ? Bs2 : Bs1;
        __half* C = pass ? C2 : C1;
        float acc[2][8][4];
        #pragma unroll
        for (int mt = 0; mt < 2; mt++)
            #pragma unroll
            for (int nt = 0; nt < 8; nt++)
                #pragma unroll
                for (int i = 0; i < 4; i++) acc[mt][nt][i] = 0.f;

        #pragma unroll
        for (int ks = 0; ks < 8; ks++) {
            int kk = ks * 16;
            uint32_t a[2][4], b[8][2];
            #pragma unroll
            for (int mt = 0; mt < 2; mt++) {
                int row = wm * 32 + mt * 16 + g;
                a[mt][0] = *reinterpret_cast<const uint32_t*>(&As[row][kk + 2*q]);
                a[mt][1] = *reinterpret_cast<const uint32_t*>(&As[row + 8][kk + 2*q]);
                a[mt][2] = *reinterpret_cast<const uint32_t*>(&As[row][kk + 2*q + 8]);
                a[mt][3] = *reinterpret_cast<const uint32_t*>(&As[row + 8][kk + 2*q + 8]);
            }
            #pragma unroll
            for (int nt = 0; nt < 8; nt++) {
                int col = wn * 64 + nt * 8 + g;
                b[nt][0] = *reinterpret_cast<const uint32_t*>(&Bs[col][kk + 2*q]);
                b[nt][1] = *reinterpret_cast<const uint32_t*>(&Bs[col][kk + 2*q + 8]);
            }
            #pragma unroll
            for (int mt = 0; mt < 2; mt++)
                #pragma unroll
                for (int nt = 0; nt < 8; nt++)
                    mma_f16(acc[mt][nt], a[mt], b[nt]);
        }

        #pragma unroll
        for (int mt = 0; mt < 2; mt++)
            #pragma unroll
            for (int h = 0; h < 2; h++) {
                long row = m0 + wm * 32 + mt * 16 + g + h * 8;
                if (row >= M) continue;
                #pragma unroll
                for (int nt = 0; nt < 8; nt++) {
                    int col = wn * 64 + nt * 8 + q * 2;
                    *reinterpret_cast<__half2*>(&C[row * 128 + col]) =
                        __floats2half2_rn(acc[mt][nt][h*2], acc[mt][nt][h*2+1]);
                }
            }
    }
}

// -------- merged tf32 mini-GEMMs --------

#define GSTAGE_A (128*36)
#define GSTAGE_B (32*136)
#define GSTAGE   (GSTAGE_A + GSTAGE_B)
#define GEMM_SMEM_BYTES (2*GSTAGE*4)

struct W4Args {
    const float* A[4];
    const float* B[4];
    __half* C[4];
};

__device__ __forceinline__ void mma_tf32(float* c, const uint32_t* a, const uint32_t* b) {
    asm volatile("mma.sync.aligned.m16n8k8.row.col.f32.tf32.tf32.f32 "
                 "{%0,%1,%2,%3}, {%4,%5,%6,%7}, {%8,%9}, {%0,%1,%2,%3};"
                 : "+f"(c[0]), "+f"(c[1]), "+f"(c[2]), "+f"(c[3])
                 : "r"(a[0]), "r"(a[1]), "r"(a[2]), "r"(a[3]), "r"(b[0]), "r"(b[1]));
}

__global__ __launch_bounds__(256) void gemm_w_tr4(W4Args args) {
    const float* A = args.A[blockIdx.x];
    const float* B = args.B[blockIdx.x];
    __half* C16t = args.C[blockIdx.x];
    extern __shared__ float smf[];
    int tid = threadIdx.x;
    int lane = tid & 31, wid = tid >> 5;
    int wm = wid & 3, wn = wid >> 2;
    int g = lane >> 2, q = lane & 3;

    float acc[2][8][4];
    #pragma unroll
    for (int mt = 0; mt < 2; mt++)
        #pragma unroll
        for (int nt = 0; nt < 8; nt++)
            #pragma unroll
            for (int i = 0; i < 4; i++) acc[mt][nt][i] = 0.f;

    int ar[4], ac_[4], br[4], bc[4];
    #pragma unroll
    for (int i = 0; i < 4; i++) {
        int idx = (tid + 256 * i) * 4;
        ar[i] = idx >> 5; ac_[i] = idx & 31;
        br[i] = idx >> 7; bc[i] = idx & 127;
    }

    auto prefetch = [&](int kc, int s) {
        float* As = smf + s * GSTAGE;
        float* Bs = As + GSTAGE_A;
        #pragma unroll
        for (int i = 0; i < 4; i++) {
            uint32_t sa = (uint32_t)__cvta_generic_to_shared(&As[ar[i]*36 + ac_[i]]);
            cp_async16(sa, A + ar[i] * 128 + kc * 32 + ac_[i], true);
        }
        #pragma unroll
        for (int i = 0; i < 4; i++) {
            uint32_t sb = (uint32_t)__cvta_generic_to_shared(&Bs[br[i]*136 + bc[i]]);
            cp_async16(sb, B + (kc * 32 + br[i]) * 128 + bc[i], true);
        }
        asm volatile("cp.async.commit_group;");
    };

    prefetch(0, 0);
    for (int kc = 0; kc < 4; kc++) {
        if (kc < 3) {
            prefetch(kc + 1, (kc + 1) & 1);
            asm volatile("cp.async.wait_group 1;");
        } else {
            asm volatile("cp.async.wait_group 0;");
        }
        __syncthreads();
        const uint32_t* As = reinterpret_cast<const uint32_t*>(smf + (kc & 1) * GSTAGE);
        const uint32_t* Bs = As + GSTAGE_A;
        #pragma unroll
        for (int ks = 0; ks < 4; ks++) {
            int kc8 = ks * 8;
            uint32_t a[2][4], b[8][2];
            #pragma unroll
            for (int mt = 0; mt < 2; mt++) {
                int row = wm * 32 + mt * 16 + g;
                a[mt][0] = As[row*36 + kc8 + q];
                a[mt][1] = As[(row+8)*36 + kc8 + q];
                a[mt][2] = As[row*36 + kc8 + q + 4];
                a[mt][3] = As[(row+8)*36 + kc8 + q + 4];
            }
            #pragma unroll
            for (int nt = 0; nt < 8; nt++) {
                int col = wn * 64 + nt * 8 + g;
                b[nt][0] = Bs[(kc8 + q)*136 + col];
                b[nt][1] = Bs[(kc8 + q + 4)*136 + col];
            }
            #pragma unroll
            for (int mt = 0; mt < 2; mt++)
                #pragma unroll
                for (int nt = 0; nt < 8; nt++)
                    mma_tf32(acc[mt][nt], a[mt], b[nt]);
        }
        __syncthreads();
    }

    #pragma unroll
    for (int mt = 0; mt < 2; mt++) {
        #pragma unroll
        for (int h = 0; h < 2; h++) {
            int row = wm * 32 + mt * 16 + g + h * 8;
            #pragma unroll
            for (int nt = 0; nt < 8; nt++) {
                int col = wn * 64 + nt * 8 + q * 2;
                C16t[(long)col * 128 + row]       = __float2half(acc[mt][nt][h*2]);
                C16t[(long)(col + 1) * 128 + row] = __float2half(acc[mt][nt][h*2+1]);
            }
        }
    }
}

// -------- host --------

extern "C" void kernel_launch(void* const* d_in, const int* in_sizes, int n_in,
                              void* d_out, int out_size) {
    const float* e_emb = (const float*)d_in[1];
    const int* node_ind = (const int*)d_in[26];
    const int* edge_src = (const int*)d_in[27];
    const int* edge_dst = (const int*)d_in[28];

    float *feat, *inv, *gscale, *colstats;
    __half *feat16, *t1h, *t2h, *keyh, *skah, *vh, *w16, *wqa16, *wka16;
    int *cnt, *offs, *fill, *partial, *ssrc;
    cudaGetSymbolAddress((void**)&feat, g_feat);
    cudaGetSymbolAddress((void**)&feat16, g_feat16);
    cudaGetSymbolAddress((void**)&t1h, g_t1h);
    cudaGetSymbolAddress((void**)&t2h, g_t2h);
    cudaGetSymbolAddress((void**)&keyh, g_keyh);
    cudaGetSymbolAddress((void**)&skah, g_skah);
    cudaGetSymbolAddress((void**)&vh, g_vh);
    cudaGetSymbolAddress((void**)&w16, g_w16);
    cudaGetSymbolAddress((void**)&wqa16, g_wqa16);
    cudaGetSymbolAddress((void**)&wka16, g_wka16);
    cudaGetSymbolAddress((void**)&cnt, g_cnt);
    cudaGetSymbolAddress((void**)&offs, g_offs);
    cudaGetSymbolAddress((void**)&fill, g_fill);
    cudaGetSymbolAddress((void**)&partial, g_partial);
    cudaGetSymbolAddress((void**)&ssrc, g_ssrc);
    cudaGetSymbolAddress((void**)&inv, g_inv);
    cudaGetSymbolAddress((void**)&gscale, g_gscale);
    cudaGetSymbolAddress((void**)&colstats, g_colstats);

    cudaFuncSetAttribute(gemm_w_tr4, cudaFuncAttributeMaxDynamicSharedMemorySize, GEMM_SMEM_BYTES);
    cudaFuncSetAttribute(gemm_seq2, cudaFuncAttributeMaxDynamicSharedMemorySize, (int)SEQ_SMEM_BYTES);
    cudaFuncSetAttribute((const void*)gemm16<0,1,0>, cudaFuncAttributeMaxDynamicSharedMemorySize, (int)G16_SMEM_BYTES);
    cudaFuncSetAttribute((const void*)gemm16<1,0,1>, cudaFuncAttributeMaxDynamicSharedMemorySize, (int)G16_SMEM_BYTES);
    cudaFuncSetAttribute((const void*)gemm_attn_out<0>, cudaFuncAttributeMaxDynamicSharedMemorySize, (int)G16_SMEM_BYTES);
    cudaFuncSetAttribute((const void*)gemm_attn_out<1>, cudaFuncAttributeMaxDynamicSharedMemorySize, (int)G16_SMEM_BYTES);

    const int TPB = 256;
    const int ND4_BLK = (ND4 + TPB - 1) / TPB;
    const int E_BLK = (TT*EE + TPB - 1) / TPB;
    const int GCNW_BLK = (NN*32 + TPB - 1) / TPB;
    const int ATTW_BLK = (TNN*32 + TPB - 1) / TPB;
    const int G1 = (NN + 127) / 128;
    const int G3 = (TNN + 127) / 128;

    convert_wt8_k<<<(8*DD*DD + TPB - 1)/TPB, TPB>>>(
        (const float*)d_in[2],  (const float*)d_in[5],  (const float*)d_in[9],  (const float*)d_in[12],
        (const float*)d_in[14], (const float*)d_in[17], (const float*)d_in[21], (const float*)d_in[24],
        w16);

    W4Args wargs;
    wargs.A[0] = (const float*)d_in[7];  wargs.B[0] = (const float*)d_in[10]; wargs.C[0] = wqa16;
    wargs.A[1] = (const float*)d_in[8];  wargs.B[1] = (const float*)d_in[10]; wargs.C[1] = wka16;
    wargs.A[2] = (const float*)d_in[19]; wargs.B[2] = (const float*)d_in[22]; wargs.C[2] = wqa16 + DD*DD;
    wargs.A[3] = (const float*)d_in[20]; wargs.B[3] = (const float*)d_in[22]; wargs.C[3] = wka16 + DD*DD;
    gemm_w_tr4<<<4, 256, GEMM_SMEM_BYTES>>>(wargs);

    cudaMemsetAsync(cnt, 0, TNN*sizeof(int), 0);
    cudaMemsetAsync(fill, 0, TNN*sizeof(int), 0);
    count_k<<<E_BLK, TPB>>>(edge_dst, cnt);
    prep_k<<<(NN + TPB - 1)/TPB, TPB>>>(cnt, inv, gscale);
    scan_block_k<<<NB_SCAN, 256>>>(cnt, offs, partial);
    scan_partial_k<<<1, 256>>>(partial);
    scan_add_k<<<NB_SCAN, 256>>>(offs, partial);
    scatter_k<<<E_BLK, TPB>>>(edge_src, edge_dst, offs, fill, ssrc);
    gather_feat_k<<<ND4_BLK, TPB>>>((const float*)d_in[0], node_ind, feat, feat16);

    const float* gcn_gamma[2] = {(const float*)d_in[3],  (const float*)d_in[15]};
    const float* gcn_beta[2]  = {(const float*)d_in[4],  (const float*)d_in[16]};
    const float* gcn_b2[2]    = {(const float*)d_in[6],  (const float*)d_in[18]};
    const float* at_bp[2]     = {(const float*)d_in[13], (const float*)d_in[25]};

    for (int L = 0; L < 2; L++) {
        const __half* w1t = w16 + (size_t)(L*4 + 0) * DD * DD;
        const __half* w2t = w16 + (size_t)(L*4 + 1) * DD * DD;
        const __half* wvt = w16 + (size_t)(L*4 + 2) * DD * DD;
        const __half* wpt = w16 + (size_t)(L*4 + 3) * DD * DD;
        const __half* wqaL = wqa16 + (size_t)L * DD * DD;
        const __half* wkaL = wka16 + (size_t)L * DD * DD;

        // ---- GCN layer ----
        cudaMemsetAsync(colstats, 0, 2*DD*sizeof(float), 0);
        gcn_edge_sorted<<<GCNW_BLK, TPB>>>(feat16, e_emb, ssrc, offs, cnt, inv, gscale, t1h);
        gemm16<0,1,0><<<G1, 256, G16_SMEM_BYTES>>>(t1h, w1t, t2h, NN, nullptr, nullptr, nullptr,
                                                   nullptr, nullptr, colstats);
        gemm16<1,0,1><<<G1, 256, G16_SMEM_BYTES>>>(t2h, w2t, nullptr, NN, gcn_b2[L], feat, feat16,
                                                   gcn_gamma[L], gcn_beta[L], colstats);

        // ---- Attention layer ----
        attn_edge_sorted<<<ATTW_BLK, TPB>>>(feat16, e_emb, ssrc, offs, cnt, inv, keyh);
        gemm_seq2<<<G3, 256, SEQ_SMEM_BYTES>>>(keyh, wkaL, wvt, skah, vh, TNN);
        if (L == 0) {
            gemm_attn_out<0><<<G1, 256, G16_SMEM_BYTES>>>(feat16, wqaL, wpt, NN, at_bp[L],
                                                          feat, feat16, skah, vh, nullptr);
        } else {
            gemm_attn_out<1><<<G1, 256, G16_SMEM_BYTES>>>(feat16, wqaL, wpt, NN, at_bp[L],
                                                          feat, nullptr, skah, vh, (float*)d_out);
        }
    }

    if (out_size >= ND + TT*DD) {
        cudaMemcpyAsync((float*)d_out + ND, e_emb, TT*DD*sizeof(float),
                        cudaMemcpyDeviceToDevice, 0);
    }
}